// round 5
// baseline (speedup 1.0000x reference)
#include <cuda_runtime.h>
#include <cuda_bf16.h>
#include <math.h>
#include <stdint.h>

#define B_ 4
#define T_ 1024
#define C_ 1024
#define H_ 16
#define HS_ 64
#define L_ 12
#define V_ 50304
#define M_ 4096  // B*T

static const size_t NLOGITS = (size_t)M_ * V_;

// ---------------- scratch (device globals; no allocs allowed) ----------------
__device__ float g_x[(size_t)M_ * C_];
__device__ float g_qkv[(size_t)M_ * 3 * C_];
__device__ float g_wei[(size_t)B_ * H_ * T_ * T_];
__device__ float g_loss_acc;

__device__ __nv_bfloat16 g_h_hi[(size_t)M_ * C_];
__device__ __nv_bfloat16 g_h_lo[(size_t)M_ * C_];
__device__ __nv_bfloat16 g_att_hi[(size_t)M_ * C_];
__device__ __nv_bfloat16 g_att_lo[(size_t)M_ * C_];
__device__ __nv_bfloat16 g_mlp_hi[(size_t)M_ * 4 * C_];
__device__ __nv_bfloat16 g_mlp_lo[(size_t)M_ * 4 * C_];
__device__ __nv_bfloat16 g_wT_hi[(size_t)V_ * C_];
__device__ __nv_bfloat16 g_wT_lo[(size_t)V_ * C_];

// ---------------- helpers ----------------
__device__ __forceinline__ uint32_t smem_u32(const void* p) {
    uint32_t a;
    asm("{ .reg .u64 t; cvta.to.shared.u64 t, %1; cvt.u32.u64 %0, t; }" : "=r"(a) : "l"(p));
    return a;
}
#define CP16(dst, src) asm volatile("cp.async.cg.shared.global [%0], [%1], 16;" :: "r"(dst), "l"(src) : "memory")
#define CP_COMMIT() asm volatile("cp.async.commit_group;" ::: "memory")
#define CP_WAIT(n)  asm volatile("cp.async.wait_group %0;" :: "n"(n) : "memory")

__device__ __forceinline__ void split_bf16(float x, __nv_bfloat16& h, __nv_bfloat16& l) {
    h = __float2bfloat16_rn(x);
    l = __float2bfloat16_rn(x - __bfloat162float(h));
}

__device__ __forceinline__ void mma_bf16(float* c, const uint32_t* a, const uint32_t* b) {
    asm volatile(
        "mma.sync.aligned.m16n8k16.row.col.f32.bf16.bf16.f32 "
        "{%0,%1,%2,%3}, {%4,%5,%6,%7}, {%8,%9}, {%0,%1,%2,%3};"
        : "+f"(c[0]), "+f"(c[1]), "+f"(c[2]), "+f"(c[3])
        : "r"(a[0]), "r"(a[1]), "r"(a[2]), "r"(a[3]), "r"(b[0]), "r"(b[1]));
}

__device__ __forceinline__ void ldm_x4(uint32_t* r, uint32_t addr) {
    asm volatile("ldmatrix.sync.aligned.m8n8.x4.shared.b16 {%0,%1,%2,%3}, [%4];"
        : "=r"(r[0]), "=r"(r[1]), "=r"(r[2]), "=r"(r[3]) : "r"(addr));
}

// ---------------- weight convert + transpose: W[K][N] -> wT_hi/lo[N][K] ----------------
__global__ void __launch_bounds__(256) convw_kernel(
    const float* __restrict__ W, __nv_bfloat16* __restrict__ hiT,
    __nv_bfloat16* __restrict__ loT, int K, int N)
{
    __shared__ float tile[32][33];
    int nt = blockIdx.x * 32, kt = blockIdx.y * 32;
    int tx = threadIdx.x & 31, ty = threadIdx.x >> 5;  // 32 x 8
    #pragma unroll
    for (int j = 0; j < 4; j++) {
        int kk = ty + j * 8;
        tile[kk][tx] = W[(size_t)(kt + kk) * N + nt + tx];
    }
    __syncthreads();
    #pragma unroll
    for (int j = 0; j < 4; j++) {
        int nn = ty + j * 8;
        float v = tile[tx][nn];
        __nv_bfloat16 h, l;
        split_bf16(v, h, l);
        size_t off = (size_t)(nt + nn) * K + kt + tx;
        hiT[off] = h;
        loT[off] = l;
    }
}

// ---------------- bf16-split GEMM via mma.sync + ldmatrix ----------------
// C = A(MxK) @ B(KxN); A hi/lo [M][K] bf16; B hi/lo transposed [N][K].
// 3 passes (Ahi*Bhi + Ahi*Blo + Alo*Bhi), fp32 accum.
// BM=128 BN=64 BK=32, 256 thr (8 warps 2x4), 3-stage cp.async, 2 CTAs/SM.
#define GSTAGE 30720            // A: 2*10240, B: 2*5120
#define GSMEM  (3 * GSTAGE)     // 92160
__global__ void __launch_bounds__(256, 2) gemm_mma_kernel(
    const __nv_bfloat16* __restrict__ Ahi, const __nv_bfloat16* __restrict__ Alo,
    const __nv_bfloat16* __restrict__ Bhi, const __nv_bfloat16* __restrict__ Blo,
    const float* __restrict__ bias, const float* __restrict__ res,
    float* __restrict__ Cout, __nv_bfloat16* __restrict__ Ohi, __nv_bfloat16* __restrict__ Olo,
    int M, int N, int K, int relu)
{
    extern __shared__ char sm[];
    const uint32_t sbase = smem_u32(sm);
    const int tid = threadIdx.x;
    const int lane = tid & 31, wid = tid >> 5;
    const int wm = wid >> 2, wn = wid & 3;          // 2 x 4 warps
    const int g = lane >> 2, tig = lane & 3;
    const int bm = blockIdx.y << 7, bn = blockIdx.x << 6;

    // ldmatrix lane-relative offsets (80B row stride)
    const uint32_t aoff = (uint32_t)((wm * 64 + (lane & 15)) * 80 + (lane >> 4) * 16);
    const uint32_t boff = (uint32_t)((wn * 16 + (lane & 7) + ((lane >> 4) << 3)) * 80 + ((lane >> 3) & 1) * 16);

    float acc[4][2][4];
    #pragma unroll
    for (int a = 0; a < 4; a++)
        #pragma unroll
        for (int b = 0; b < 2; b++)
            #pragma unroll
            for (int c = 0; c < 4; c++) acc[a][b][c] = 0.f;

    const int nIter = K >> 5;

    auto stage = [&](int it) {
        const uint32_t s0 = sbase + (uint32_t)(it % 3) * GSTAGE;
        const int k0 = it << 5;
        // A: 128 rows x 64B (hi+lo)
        #pragma unroll
        for (int j = 0; j < 2; j++) {
            int c = tid + j * 256;           // 0..511
            int row = c >> 2, q = c & 3;
            uint32_t d = (uint32_t)(row * 80 + q * 16);
            size_t ga = (size_t)(bm + row) * K + k0 + q * 8;
            CP16(s0 + d,         Ahi + ga);
            CP16(s0 + 10240 + d, Alo + ga);
        }
        // B: 64 rows x 64B (hi+lo)
        {
            int row = tid >> 2, q = tid & 3;
            uint32_t d = (uint32_t)(row * 80 + q * 16);
            size_t gb = (size_t)(bn + row) * K + k0 + q * 8;
            CP16(s0 + 20480 + d, Bhi + gb);
            CP16(s0 + 25600 + d, Blo + gb);
        }
    };

    stage(0); CP_COMMIT();
    if (nIter > 1) { stage(1); CP_COMMIT(); }

    for (int i = 0; i < nIter; i++) {
        if (i + 1 < nIter) { CP_WAIT(1); } else { CP_WAIT(0); }
        __syncthreads();
        if (i + 2 < nIter) { stage(i + 2); CP_COMMIT(); }

        const uint32_t s0 = sbase + (uint32_t)(i % 3) * GSTAGE;
        #pragma unroll
        for (int ks = 0; ks < 2; ks++) {
            const uint32_t kofs = (uint32_t)(ks * 32);
            uint32_t ah[4][4], al[4][4], bh[2][2], bl[2][2];
            #pragma unroll
            for (int mf = 0; mf < 4; mf++) {
                uint32_t ad = s0 + aoff + (uint32_t)(mf * 16 * 80) + kofs;
                ldm_x4(ah[mf], ad);
                ldm_x4(al[mf], ad + 10240);
            }
            {
                uint32_t bd = s0 + 20480 + boff + kofs;
                uint32_t r[4];
                ldm_x4(r, bd);
                bh[0][0] = r[0]; bh[0][1] = r[1];
                bh[1][0] = r[2]; bh[1][1] = r[3];
                ldm_x4(r, bd + 5120);
                bl[0][0] = r[0]; bl[0][1] = r[1];
                bl[1][0] = r[2]; bl[1][1] = r[3];
            }
            // pass-major: 8 independent accumulators between reuses
            #pragma unroll
            for (int mf = 0; mf < 4; mf++)
                #pragma unroll
                for (int nf = 0; nf < 2; nf++)
                    mma_bf16(acc[mf][nf], ah[mf], bh[nf]);
            #pragma unroll
            for (int mf = 0; mf < 4; mf++)
                #pragma unroll
                for (int nf = 0; nf < 2; nf++)
                    mma_bf16(acc[mf][nf], ah[mf], bl[nf]);
            #pragma unroll
            for (int mf = 0; mf < 4; mf++)
                #pragma unroll
                for (int nf = 0; nf < 2; nf++)
                    mma_bf16(acc[mf][nf], al[mf], bh[nf]);
        }
    }

    // epilogue
    #pragma unroll
    for (int nf = 0; nf < 2; nf++) {
        int col = bn + wn * 16 + nf * 8 + 2 * tig;
        float2 bz = make_float2(0.f, 0.f);
        if (bias) bz = *(const float2*)(bias + col);
        #pragma unroll
        for (int mf = 0; mf < 4; mf++) {
            int row0 = bm + wm * 64 + mf * 16 + g;
            int row1 = row0 + 8;
            float c0 = acc[mf][nf][0] + bz.x;
            float c1 = acc[mf][nf][1] + bz.y;
            float c2 = acc[mf][nf][2] + bz.x;
            float c3 = acc[mf][nf][3] + bz.y;
            if (res) {
                float2 r0 = *(const float2*)(res + (size_t)row0 * N + col);
                float2 r1 = *(const float2*)(res + (size_t)row1 * N + col);
                c0 += r0.x; c1 += r0.y; c2 += r1.x; c3 += r1.y;
            }
            if (relu) {
                c0 = fmaxf(c0, 0.f); c1 = fmaxf(c1, 0.f);
                c2 = fmaxf(c2, 0.f); c3 = fmaxf(c3, 0.f);
            }
            if (Cout) {
                *(float2*)(Cout + (size_t)row0 * N + col) = make_float2(c0, c1);
                *(float2*)(Cout + (size_t)row1 * N + col) = make_float2(c2, c3);
            }
            if (Ohi) {
                __nv_bfloat16 h0, l0, h1, l1, h2, l2, h3, l3;
                split_bf16(c0, h0, l0); split_bf16(c1, h1, l1);
                split_bf16(c2, h2, l2); split_bf16(c3, h3, l3);
                *(__nv_bfloat162*)(Ohi + (size_t)row0 * N + col) = __halves2bfloat162(h0, h1);
                *(__nv_bfloat162*)(Olo + (size_t)row0 * N + col) = __halves2bfloat162(l0, l1);
                *(__nv_bfloat162*)(Ohi + (size_t)row1 * N + col) = __halves2bfloat162(h2, h3);
                *(__nv_bfloat162*)(Olo + (size_t)row1 * N + col) = __halves2bfloat162(l2, l3);
            }
        }
    }
}

// ---------------- embedding ----------------
__global__ void __launch_bounds__(256) embed_kernel(
    const int* __restrict__ idx, const float* __restrict__ tok,
    const float* __restrict__ pos, float* __restrict__ x)
{
    int row = blockIdx.x;
    int t = row & (T_ - 1);
    int token = idx[row];
    int c = threadIdx.x * 4;
    float4 a = *(const float4*)(tok + (size_t)token * C_ + c);
    float4 p = *(const float4*)(pos + (size_t)t * C_ + c);
    *(float4*)(x + (size_t)row * C_ + c) = make_float4(a.x + p.x, a.y + p.y, a.z + p.z, a.w + p.w);
}

// ---------------- layernorm -> bf16 hi/lo ----------------
__global__ void __launch_bounds__(256) ln_kernel(
    const float* __restrict__ x, const float* __restrict__ g,
    const float* __restrict__ b, __nv_bfloat16* __restrict__ yhi,
    __nv_bfloat16* __restrict__ ylo)
{
    __shared__ float red[256];
    int row = blockIdx.x;
    int t = threadIdx.x;
    const float* xr = x + (size_t)row * C_;
    float4 v = *(const float4*)(xr + t * 4);
    red[t] = v.x + v.y + v.z + v.w;
    __syncthreads();
    for (int o = 128; o > 0; o >>= 1) { if (t < o) red[t] += red[t + o]; __syncthreads(); }
    float mean = red[0] * (1.f / C_);
    __syncthreads();
    float dx = v.x - mean, dy = v.y - mean, dz = v.z - mean, dw = v.w - mean;
    red[t] = dx * dx + dy * dy + dz * dz + dw * dw;
    __syncthreads();
    for (int o = 128; o > 0; o >>= 1) { if (t < o) red[t] += red[t + o]; __syncthreads(); }
    float inv = rsqrtf(red[0] * (1.f / C_) + 1e-5f);
    float4 gv = *(const float4*)(g + t * 4);
    float4 bv = *(const float4*)(b + t * 4);
    float o0 = dx * inv * gv.x + bv.x;
    float o1 = dy * inv * gv.y + bv.y;
    float o2 = dz * inv * gv.z + bv.z;
    float o3 = dw * inv * gv.w + bv.w;
    __nv_bfloat16 h0, l0, h1, l1, h2, l2, h3, l3;
    split_bf16(o0, h0, l0); split_bf16(o1, h1, l1);
    split_bf16(o2, h2, l2); split_bf16(o3, h3, l3);
    size_t off = (size_t)row * C_ + t * 4;
    *(__nv_bfloat162*)(yhi + off)     = __halves2bfloat162(h0, h1);
    *(__nv_bfloat162*)(yhi + off + 2) = __halves2bfloat162(h2, h3);
    *(__nv_bfloat162*)(ylo + off)     = __halves2bfloat162(l0, l1);
    *(__nv_bfloat162*)(ylo + off + 2) = __halves2bfloat162(l2, l3);
}

// ---------------- attention scores (q,k from packed qkv[M][3C]) ----------------
__global__ void __launch_bounds__(256) attn_scores_kernel(
    const float* __restrict__ qkv, float* __restrict__ wei)
{
    int kt = blockIdx.x << 6;
    int qt = blockIdx.y << 6;
    if (kt > qt) return;
    int bh = blockIdx.z;
    int b = bh >> 4, h = bh & 15;
    __shared__ float Qs[64][68];
    __shared__ float Ks[64][68];
    int tid = threadIdx.x;
    const int RS = 3 * C_;
    const float* qbase = qkv + (size_t)(b * T_ + qt) * RS + h * HS_;
    const float* kbase = qkv + (size_t)(b * T_ + kt) * RS + C_ + h * HS_;
    #pragma unroll
    for (int l = tid; l < 1024; l += 256) {
        int r = l >> 4, c4 = l & 15;
        float4 v = *(const float4*)(qbase + (size_t)r * RS + c4 * 4);
        Qs[c4 * 4 + 0][r] = v.x; Qs[c4 * 4 + 1][r] = v.y;
        Qs[c4 * 4 + 2][r] = v.z; Qs[c4 * 4 + 3][r] = v.w;
        float4 w = *(const float4*)(kbase + (size_t)r * RS + c4 * 4);
        Ks[c4 * 4 + 0][r] = w.x; Ks[c4 * 4 + 1][r] = w.y;
        Ks[c4 * 4 + 2][r] = w.z; Ks[c4 * 4 + 3][r] = w.w;
    }
    __syncthreads();
    int tx = tid & 15, ty = tid >> 4;
    float acc[4][4];
    #pragma unroll
    for (int i = 0; i < 4; i++)
        #pragma unroll
        for (int j = 0; j < 4; j++) acc[i][j] = 0.f;
    #pragma unroll 8
    for (int d = 0; d < 64; d++) {
        float a[4], bb[4];
        *(float4*)a  = *(const float4*)(&Qs[d][ty * 4]);
        *(float4*)bb = *(const float4*)(&Ks[d][tx * 4]);
        #pragma unroll
        for (int i = 0; i < 4; i++)
            #pragma unroll
            for (int j = 0; j < 4; j++)
                acc[i][j] = fmaf(a[i], bb[j], acc[i][j]);
    }
    #pragma unroll
    for (int i = 0; i < 4; i++) {
        size_t roff = ((size_t)bh * T_ + qt + ty * 4 + i) * T_ + kt + tx * 4;
        *(float4*)(wei + roff) = *(float4*)(acc[i]);
    }
}

// ---------------- masked softmax ----------------
__global__ void __launch_bounds__(256) softmax_kernel(float* __restrict__ wei)
{
    __shared__ float red[256];
    int row = blockIdx.x;
    int q = row & (T_ - 1);
    float* w = wei + (size_t)row * T_;
    int kend = ((q >> 6) + 1) << 6;
    int t = threadIdx.x;
    int k0 = t * 4;
    float vals[4];
    float mx = -INFINITY;
    #pragma unroll
    for (int j = 0; j < 4; j++) {
        int kk = k0 + j;
        float v = (kk <= q) ? w[kk] * 0.125f : -INFINITY;
        vals[j] = v;
        mx = fmaxf(mx, v);
    }
    red[t] = mx; __syncthreads();
    for (int o = 128; o > 0; o >>= 1) { if (t < o) red[t] = fmaxf(red[t], red[t + o]); __syncthreads(); }
    float Mx = red[0]; __syncthreads();
    float s = 0.f;
    #pragma unroll
    for (int j = 0; j < 4; j++) {
        int kk = k0 + j;
        float e = (kk <= q) ? __expf(vals[j] - Mx) : 0.f;
        vals[j] = e;
        s += e;
    }
    red[t] = s; __syncthreads();
    for (int o = 128; o > 0; o >>= 1) { if (t < o) red[t] += red[t + o]; __syncthreads(); }
    float invS = 1.f / red[0];
    #pragma unroll
    for (int j = 0; j < 4; j++) {
        int kk = k0 + j;
        if (kk < kend) w[kk] = vals[j] * invS;
    }
}

// ---------------- att = wei @ V -> bf16 hi/lo ----------------
__global__ void __launch_bounds__(256) attn_av_kernel(
    const float* __restrict__ wei, const float* __restrict__ qkv,
    __nv_bfloat16* __restrict__ atthi, __nv_bfloat16* __restrict__ attlo)
{
    int qt = blockIdx.x << 6;
    int bh = blockIdx.y;
    int b = bh >> 4, h = bh & 15;
    __shared__ float Ws[64][68];
    __shared__ float Vs[64][68];
    int tid = threadIdx.x;
    int tx = tid & 15, ty = tid >> 4;
    const int RS = 3 * C_;
    float acc[4][4];
    #pragma unroll
    for (int i = 0; i < 4; i++)
        #pragma unroll
        for (int j = 0; j < 4; j++) acc[i][j] = 0.f;

    for (int kt = 0; kt <= qt; kt += 64) {
        const float* wbase = wei + ((size_t)bh * T_ + qt) * T_ + kt;
        const float* vbase = qkv + (size_t)(b * T_ + kt) * RS + 2 * C_ + h * HS_;
        #pragma unroll
        for (int l = tid; l < 1024; l += 256) {
            int r = l >> 4, c4 = l & 15;
            *(float4*)(&Ws[r][c4 * 4]) = *(const float4*)(wbase + (size_t)r * T_ + c4 * 4);
            *(float4*)(&Vs[r][c4 * 4]) = *(const float4*)(vbase + (size_t)r * RS + c4 * 4);
        }
        __syncthreads();
        #pragma unroll 8
        for (int kk = 0; kk < 64; kk++) {
            float bb[4];
            *(float4*)bb = *(const float4*)(&Vs[kk][tx * 4]);
            float a0 = Ws[ty * 4 + 0][kk];
            float a1 = Ws[ty * 4 + 1][kk];
            float a2 = Ws[ty * 4 + 2][kk];
            float a3 = Ws[ty * 4 + 3][kk];
            #pragma unroll
            for (int j = 0; j < 4; j++) {
                acc[0][j] = fmaf(a0, bb[j], acc[0][j]);
                acc[1][j] = fmaf(a1, bb[j], acc[1][j]);
                acc[2][j] = fmaf(a2, bb[j], acc[2][j]);
                acc[3][j] = fmaf(a3, bb[j], acc[3][j]);
            }
        }
        __syncthreads();
    }
    #pragma unroll
    for (int i = 0; i < 4; i++) {
        size_t roff = ((size_t)(b * T_ + qt + ty * 4 + i)) * C_ + h * HS_ + tx * 4;
        __nv_bfloat16 h0, l0, h1, l1, h2, l2, h3, l3;
        split_bf16(acc[i][0], h0, l0); split_bf16(acc[i][1], h1, l1);
        split_bf16(acc[i][2], h2, l2); split_bf16(acc[i][3], h3, l3);
        *(__nv_bfloat162*)(atthi + roff)     = __halves2bfloat162(h0, h1);
        *(__nv_bfloat162*)(atthi + roff + 2) = __halves2bfloat162(h2, h3);
        *(__nv_bfloat162*)(attlo + roff)     = __halves2bfloat162(l0, l1);
        *(__nv_bfloat162*)(attlo + roff + 2) = __halves2bfloat162(l2, l3);
    }
}

// ---------------- loss ----------------
__global__ void zero_acc_kernel(float* acc) { *acc = 0.f; }

__global__ void __launch_bounds__(256) loss_kernel(
    const float* __restrict__ logits, const int* __restrict__ targets, float* __restrict__ acc)
{
    __shared__ float red[256];
    int row = blockIdx.x;
    const float* lr = logits + (size_t)row * V_;
    int t = threadIdx.x;
    float mx = -INFINITY;
    for (int c = t; c < V_; c += 256) mx = fmaxf(mx, lr[c]);
    red[t] = mx; __syncthreads();
    for (int o = 128; o > 0; o >>= 1) { if (t < o) red[t] = fmaxf(red[t], red[t + o]); __syncthreads(); }
    float Mx = red[0]; __syncthreads();
    float s = 0.f;
    for (int c = t; c < V_; c += 256) s += __expf(lr[c] - Mx);
    red[t] = s; __syncthreads();
    for (int o = 128; o > 0; o >>= 1) { if (t < o) red[t] += red[t + o]; __syncthreads(); }
    if (t == 0) {
        float lse = logf(red[0]) + Mx;
        int tgt = targets[row];
        atomicAdd(acc, (lse - lr[tgt]) * (1.f / M_));
    }
}

__global__ void write_loss_kernel(const float* acc, float* out) { out[0] = *acc; }

// ---------------- launch ----------------
extern "C" void kernel_launch(void* const* d_in, const int* in_sizes, int n_in,
                              void* d_out, int out_size)
{
    const int*   idx   = (const int*)d_in[0];
    const int*   tgt   = (const int*)d_in[1];
    const float* tok   = (const float*)d_in[2];
    const float* pos   = (const float*)d_in[3];
    const float* ln1g  = (const float*)d_in[4];
    const float* ln1b  = (const float*)d_in[5];
    const float* Wq    = (const float*)d_in[6];
    const float* Wk    = (const float*)d_in[7];
    const float* Wv    = (const float*)d_in[8];
    const float* Wo    = (const float*)d_in[9];
    const float* bo    = (const float*)d_in[10];
    const float* ln2g  = (const float*)d_in[11];
    const float* ln2b  = (const float*)d_in[12];
    const float* W1    = (const float*)d_in[13];
    const float* b1    = (const float*)d_in[14];
    const float* W2    = (const float*)d_in[15];
    const float* b2    = (const float*)d_in[16];
    const float* lnfg  = (const float*)d_in[17];
    const float* lnfb  = (const float*)d_in[18];
    const float* Wlm   = (const float*)d_in[19];
    const float* blm   = (const float*)d_in[20];

    float *xb, *qkvb, *wb, *accp;
    __nv_bfloat16 *hh, *hl, *ah, *al, *mh, *ml, *wth, *wtl;
    cudaGetSymbolAddress((void**)&xb, g_x);
    cudaGetSymbolAddress((void**)&qkvb, g_qkv);
    cudaGetSymbolAddress((void**)&wb, g_wei);
    cudaGetSymbolAddress((void**)&accp, g_loss_acc);
    cudaGetSymbolAddress((void**)&hh, g_h_hi);
    cudaGetSymbolAddress((void**)&hl, g_h_lo);
    cudaGetSymbolAddress((void**)&ah, g_att_hi);
    cudaGetSymbolAddress((void**)&al, g_att_lo);
    cudaGetSymbolAddress((void**)&mh, g_mlp_hi);
    cudaGetSymbolAddress((void**)&ml, g_mlp_lo);
    cudaGetSymbolAddress((void**)&wth, g_wT_hi);
    cudaGetSymbolAddress((void**)&wtl, g_wT_lo);

    cudaFuncSetAttribute(gemm_mma_kernel, cudaFuncAttributeMaxDynamicSharedMemorySize, GSMEM);

    embed_kernel<<<M_, 256>>>(idx, tok, pos, xb);

    dim3 gC(C_ / 64, M_ / 128);
    dim3 gQKV(3 * C_ / 64, M_ / 128);
    dim3 gF(4 * C_ / 64, M_ / 128);
    dim3 gScore(T_ / 64, T_ / 64, B_ * H_);
    dim3 gAV(T_ / 64, B_ * H_);
    dim3 cvC(C_ / 32, C_ / 32);
    dim3 cv1(4 * C_ / 32, C_ / 32);
    dim3 cv2(C_ / 32, 4 * C_ / 32);
    dim3 cvLM(V_ / 32, C_ / 32);

    for (int l = 0; l < L_; l++) {
        ln_kernel<<<M_, 256>>>(xb, ln1g + (size_t)l * C_, ln1b + (size_t)l * C_, hh, hl);

        convw_kernel<<<cvC, 256>>>(Wq + (size_t)l * C_ * C_, wth,                    wtl,                    C_, C_);
        convw_kernel<<<cvC, 256>>>(Wk + (size_t)l * C_ * C_, wth + (size_t)C_ * C_,  wtl + (size_t)C_ * C_,  C_, C_);
        convw_kernel<<<cvC, 256>>>(Wv + (size_t)l * C_ * C_, wth + (size_t)2 * C_ * C_, wtl + (size_t)2 * C_ * C_, C_, C_);
        gemm_mma_kernel<<<gQKV, 256, GSMEM>>>(hh, hl, wth, wtl, nullptr, nullptr, qkvb, nullptr, nullptr, M_, 3 * C_, C_, 0);

        attn_scores_kernel<<<gScore, 256>>>(qkvb, wb);
        softmax_kernel<<<B_ * H_ * T_, 256>>>(wb);
        attn_av_kernel<<<gAV, 256>>>(wb, qkvb, ah, al);

        convw_kernel<<<cvC, 256>>>(Wo + (size_t)l * C_ * C_, wth, wtl, C_, C_);
        gemm_mma_kernel<<<gC, 256, GSMEM>>>(ah, al, wth, wtl, bo + (size_t)l * C_, xb, xb, nullptr, nullptr, M_, C_, C_, 0);

        ln_kernel<<<M_, 256>>>(xb, ln2g + (size_t)l * C_, ln2b + (size_t)l * C_, hh, hl);

        convw_kernel<<<cv1, 256>>>(W1 + (size_t)l * C_ * 4 * C_, wth, wtl, C_, 4 * C_);
        gemm_mma_kernel<<<gF, 256, GSMEM>>>(hh, hl, wth, wtl, b1 + (size_t)l * 4 * C_, nullptr, nullptr, mh, ml, M_, 4 * C_, C_, 1);
        convw_kernel<<<cv2, 256>>>(W2 + (size_t)l * 4 * C_ * C_, wth, wtl, 4 * C_, C_);
        gemm_mma_kernel<<<gC, 256, GSMEM>>>(mh, ml, wth, wtl, b2 + (size_t)l * C_, xb, xb, nullptr, nullptr, M_, C_, 4 * C_, 0);
    }

    ln_kernel<<<M_, 256>>>(xb, lnfg, lnfb, hh, hl);

    float* out = (float*)d_out;
    convw_kernel<<<cvLM, 256>>>(Wlm, wth, wtl, C_, V_);
    dim3 gLM(V_ / 64, M_ / 128);
    gemm_mma_kernel<<<gLM, 256, GSMEM>>>(hh, hl, wth, wtl, blm, nullptr, out, nullptr, nullptr, M_, V_, C_, 0);

    if ((size_t)out_size > NLOGITS) {
        zero_acc_kernel<<<1, 1>>>(accp);
        loss_kernel<<<M_, 256>>>(out, tgt, accp);
        write_loss_kernel<<<1, 1>>>(accp, out + NLOGITS);
    }
}

// round 6
// speedup vs baseline: 1.2710x; 1.2710x over previous
#include <cuda_runtime.h>
#include <cuda_fp16.h>
#include <math.h>
#include <stdint.h>

#define B_ 4
#define T_ 1024
#define C_ 1024
#define H_ 16
#define HS_ 64
#define L_ 12
#define V_ 50304
#define M_ 4096  // B*T

static const size_t NLOGITS = (size_t)M_ * V_;

// ---------------- scratch (device globals; no allocs allowed) ----------------
__device__ float g_x[(size_t)M_ * C_];
__device__ float g_qkv[(size_t)M_ * 3 * C_];
__device__ float g_wei[(size_t)B_ * H_ * T_ * T_];
__device__ float g_loss_acc;

__device__ __half g_h_hi[(size_t)M_ * C_];
__device__ __half g_h_lo[(size_t)M_ * C_];
__device__ __half g_att_hi[(size_t)M_ * C_];
__device__ __half g_att_lo[(size_t)M_ * C_];
__device__ __half g_mlp_hi[(size_t)M_ * 4 * C_];
__device__ __half g_mlp_lo[(size_t)M_ * 4 * C_];
__device__ __half g_wT[(size_t)V_ * C_];

// ---------------- helpers ----------------
__device__ __forceinline__ uint32_t smem_u32(const void* p) {
    uint32_t a;
    asm("{ .reg .u64 t; cvta.to.shared.u64 t, %1; cvt.u32.u64 %0, t; }" : "=r"(a) : "l"(p));
    return a;
}
#define CP16(dst, src) asm volatile("cp.async.cg.shared.global [%0], [%1], 16;" :: "r"(dst), "l"(src) : "memory")
#define CP_COMMIT() asm volatile("cp.async.commit_group;" ::: "memory")
#define CP_WAIT(n)  asm volatile("cp.async.wait_group %0;" :: "n"(n) : "memory")

__device__ __forceinline__ void split_f16(float x, __half& h, __half& l) {
    h = __float2half_rn(x);
    l = __float2half_rn(x - __half2float(h));
}

__device__ __forceinline__ void mma_f16(float* c, const uint32_t* a, const uint32_t* b) {
    asm volatile(
        "mma.sync.aligned.m16n8k16.row.col.f32.f16.f16.f32 "
        "{%0,%1,%2,%3}, {%4,%5,%6,%7}, {%8,%9}, {%0,%1,%2,%3};"
        : "+f"(c[0]), "+f"(c[1]), "+f"(c[2]), "+f"(c[3])
        : "r"(a[0]), "r"(a[1]), "r"(a[2]), "r"(a[3]), "r"(b[0]), "r"(b[1]));
}

__device__ __forceinline__ void ldm_x4(uint32_t* r, uint32_t addr) {
    asm volatile("ldmatrix.sync.aligned.m8n8.x4.shared.b16 {%0,%1,%2,%3}, [%4];"
        : "=r"(r[0]), "=r"(r[1]), "=r"(r[2]), "=r"(r[3]) : "r"(addr));
}

// ---------------- weight convert + transpose: W[K][N] -> wT[N][K] fp16 ----------------
__global__ void __launch_bounds__(256) convw_kernel(
    const float* __restrict__ W, __half* __restrict__ wT, int K, int N)
{
    __shared__ float tile[32][33];
    int nt = blockIdx.x * 32, kt = blockIdx.y * 32;
    int tx = threadIdx.x & 31, ty = threadIdx.x >> 5;  // 32 x 8
    #pragma unroll
    for (int j = 0; j < 4; j++) {
        int kk = ty + j * 8;
        tile[kk][tx] = W[(size_t)(kt + kk) * N + nt + tx];
    }
    __syncthreads();
    #pragma unroll
    for (int j = 0; j < 4; j++) {
        int nn = ty + j * 8;
        wT[(size_t)(nt + nn) * K + kt + tx] = __float2half_rn(tile[tx][nn]);
    }
}

// ---------------- fp16 2-pass GEMM via mma.sync + ldmatrix ----------------
// C = A(MxK) @ B(KxN); A exact as fp16 hi+lo [M][K]; B fp16 transposed [N][K].
// C = Ahi*B + Alo*B  (fp32 accum). Alo==nullptr -> 1-pass.
// BM=128 BN=128 BK=32, 256 thr (8 warps 2x4), 3-stage cp.async, 1 sync/iter.
#define GSTAGE 30720            // Ahi 10240 + Alo 10240 + B 10240
#define GSMEM  (3 * GSTAGE)     // 92160
__global__ void __launch_bounds__(256) gemm_mma_kernel(
    const __half* __restrict__ Ahi, const __half* __restrict__ Alo,
    const __half* __restrict__ Bw,
    const float* __restrict__ bias, const float* __restrict__ res,
    float* __restrict__ Cout, __half* __restrict__ Ohi, __half* __restrict__ Olo,
    int M, int N, int K, int relu)
{
    extern __shared__ char sm[];
    const uint32_t sbase = smem_u32(sm);
    const int tid = threadIdx.x;
    const int lane = tid & 31, wid = tid >> 5;
    const int wm = wid >> 2, wn = wid & 3;
    const int g = lane >> 2, tig = lane & 3;
    const int bm = blockIdx.y << 7, bn = blockIdx.x << 7;
    const bool twopass = (Alo != nullptr);

    // ldmatrix lane-relative offsets (80B row stride)
    const uint32_t aoff = (uint32_t)((wm * 64 + (lane & 15)) * 80 + (lane >> 4) * 16);
    const uint32_t boff = (uint32_t)((wn * 32 + (lane & 7) + ((lane >> 4) << 3)) * 80 + ((lane >> 3) & 1) * 16);

    float acc[4][4][4];
    #pragma unroll
    for (int a = 0; a < 4; a++)
        #pragma unroll
        for (int b = 0; b < 4; b++)
            #pragma unroll
            for (int c = 0; c < 4; c++) acc[a][b][c] = 0.f;

    const int nIter = K >> 5;

    auto stage = [&](int it) {
        const uint32_t s0 = sbase + (uint32_t)(it % 3) * GSTAGE;
        const int k0 = it << 5;
        #pragma unroll
        for (int j = 0; j < 2; j++) {
            int c = tid + j * 256;           // 0..511 chunk id
            int row = c >> 2, q = c & 3;
            uint32_t d = (uint32_t)(row * 80 + q * 16);
            size_t ga = (size_t)(bm + row) * K + k0 + q * 8;
            size_t gb = (size_t)(bn + row) * K + k0 + q * 8;
            CP16(s0 + d, Ahi + ga);
            if (twopass) CP16(s0 + 10240 + d, Alo + ga);
            CP16(s0 + 20480 + d, Bw + gb);
        }
    };

    stage(0); CP_COMMIT();
    if (nIter > 1) { stage(1); CP_COMMIT(); }

    for (int i = 0; i < nIter; i++) {
        if (i + 1 < nIter) { CP_WAIT(1); } else { CP_WAIT(0); }
        __syncthreads();
        if (i + 2 < nIter) { stage(i + 2); CP_COMMIT(); }

        const uint32_t s0 = sbase + (uint32_t)(i % 3) * GSTAGE;
        #pragma unroll
        for (int ks = 0; ks < 2; ks++) {
            const uint32_t kofs = (uint32_t)(ks * 32);
            uint32_t ah[4][4], al[4][4], bh[4][2];
            #pragma unroll
            for (int mf = 0; mf < 4; mf++) {
                uint32_t ad = s0 + aoff + (uint32_t)(mf * 16 * 80) + kofs;
                ldm_x4(ah[mf], ad);
                if (twopass) ldm_x4(al[mf], ad + 10240);
            }
            #pragma unroll
            for (int p = 0; p < 2; p++) {
                uint32_t bd = s0 + 20480 + boff + (uint32_t)(p * 16 * 80) + kofs;
                uint32_t r[4];
                ldm_x4(r, bd);
                bh[2 * p][0] = r[0]; bh[2 * p][1] = r[1];
                bh[2 * p + 1][0] = r[2]; bh[2 * p + 1][1] = r[3];
            }
            #pragma unroll
            for (int mf = 0; mf < 4; mf++)
                #pragma unroll
                for (int nf = 0; nf < 4; nf++)
                    mma_f16(acc[mf][nf], ah[mf], bh[nf]);
            if (twopass) {
                #pragma unroll
                for (int mf = 0; mf < 4; mf++)
                    #pragma unroll
                    for (int nf = 0; nf < 4; nf++)
                        mma_f16(acc[mf][nf], al[mf], bh[nf]);
            }
        }
    }

    // epilogue
    #pragma unroll
    for (int nf = 0; nf < 4; nf++) {
        int col = bn + wn * 32 + nf * 8 + 2 * tig;
        float2 bz = make_float2(0.f, 0.f);
        if (bias) bz = *(const float2*)(bias + col);
        #pragma unroll
        for (int mf = 0; mf < 4; mf++) {
            int row0 = bm + wm * 64 + mf * 16 + g;
            int row1 = row0 + 8;
            float c0 = acc[mf][nf][0] + bz.x;
            float c1 = acc[mf][nf][1] + bz.y;
            float c2 = acc[mf][nf][2] + bz.x;
            float c3 = acc[mf][nf][3] + bz.y;
            if (res) {
                float2 r0 = *(const float2*)(res + (size_t)row0 * N + col);
                float2 r1 = *(const float2*)(res + (size_t)row1 * N + col);
                c0 += r0.x; c1 += r0.y; c2 += r1.x; c3 += r1.y;
            }
            if (relu) {
                c0 = fmaxf(c0, 0.f); c1 = fmaxf(c1, 0.f);
                c2 = fmaxf(c2, 0.f); c3 = fmaxf(c3, 0.f);
            }
            if (Cout) {
                *(float2*)(Cout + (size_t)row0 * N + col) = make_float2(c0, c1);
                *(float2*)(Cout + (size_t)row1 * N + col) = make_float2(c2, c3);
            }
            if (Ohi) {
                __half h0, l0, h1, l1, h2, l2, h3, l3;
                split_f16(c0, h0, l0); split_f16(c1, h1, l1);
                split_f16(c2, h2, l2); split_f16(c3, h3, l3);
                *(__half2*)(Ohi + (size_t)row0 * N + col) = __halves2half2(h0, h1);
                *(__half2*)(Olo + (size_t)row0 * N + col) = __halves2half2(l0, l1);
                *(__half2*)(Ohi + (size_t)row1 * N + col) = __halves2half2(h2, h3);
                *(__half2*)(Olo + (size_t)row1 * N + col) = __halves2half2(l2, l3);
            }
        }
    }
}

// ---------------- embedding ----------------
__global__ void __launch_bounds__(256) embed_kernel(
    const int* __restrict__ idx, const float* __restrict__ tok,
    const float* __restrict__ pos, float* __restrict__ x)
{
    int row = blockIdx.x;
    int t = row & (T_ - 1);
    int token = idx[row];
    int c = threadIdx.x * 4;
    float4 a = *(const float4*)(tok + (size_t)token * C_ + c);
    float4 p = *(const float4*)(pos + (size_t)t * C_ + c);
    *(float4*)(x + (size_t)row * C_ + c) = make_float4(a.x + p.x, a.y + p.y, a.z + p.z, a.w + p.w);
}

// ---------------- layernorm -> fp16 hi/lo ----------------
__global__ void __launch_bounds__(256) ln_kernel(
    const float* __restrict__ x, const float* __restrict__ g,
    const float* __restrict__ b, __half* __restrict__ yhi, __half* __restrict__ ylo)
{
    __shared__ float red[256];
    int row = blockIdx.x;
    int t = threadIdx.x;
    const float* xr = x + (size_t)row * C_;
    float4 v = *(const float4*)(xr + t * 4);
    red[t] = v.x + v.y + v.z + v.w;
    __syncthreads();
    for (int o = 128; o > 0; o >>= 1) { if (t < o) red[t] += red[t + o]; __syncthreads(); }
    float mean = red[0] * (1.f / C_);
    __syncthreads();
    float dx = v.x - mean, dy = v.y - mean, dz = v.z - mean, dw = v.w - mean;
    red[t] = dx * dx + dy * dy + dz * dz + dw * dw;
    __syncthreads();
    for (int o = 128; o > 0; o >>= 1) { if (t < o) red[t] += red[t + o]; __syncthreads(); }
    float inv = rsqrtf(red[0] * (1.f / C_) + 1e-5f);
    float4 gv = *(const float4*)(g + t * 4);
    float4 bv = *(const float4*)(b + t * 4);
    float o0 = dx * inv * gv.x + bv.x;
    float o1 = dy * inv * gv.y + bv.y;
    float o2 = dz * inv * gv.z + bv.z;
    float o3 = dw * inv * gv.w + bv.w;
    __half h0, l0, h1, l1, h2, l2, h3, l3;
    split_f16(o0, h0, l0); split_f16(o1, h1, l1);
    split_f16(o2, h2, l2); split_f16(o3, h3, l3);
    size_t off = (size_t)row * C_ + t * 4;
    *(__half2*)(yhi + off)     = __halves2half2(h0, h1);
    *(__half2*)(yhi + off + 2) = __halves2half2(h2, h3);
    *(__half2*)(ylo + off)     = __halves2half2(l0, l1);
    *(__half2*)(ylo + off + 2) = __halves2half2(l2, l3);
}

// ---------------- attention scores (q,k from packed qkv[M][3C]) ----------------
__global__ void __launch_bounds__(256) attn_scores_kernel(
    const float* __restrict__ qkv, float* __restrict__ wei)
{
    int kt = blockIdx.x << 6;
    int qt = blockIdx.y << 6;
    if (kt > qt) return;
    int bh = blockIdx.z;
    int b = bh >> 4, h = bh & 15;
    __shared__ float Qs[64][68];
    __shared__ float Ks[64][68];
    int tid = threadIdx.x;
    const int RS = 3 * C_;
    const float* qbase = qkv + (size_t)(b * T_ + qt) * RS + h * HS_;
    const float* kbase = qkv + (size_t)(b * T_ + kt) * RS + C_ + h * HS_;
    #pragma unroll
    for (int l = tid; l < 1024; l += 256) {
        int r = l >> 4, c4 = l & 15;
        float4 v = *(const float4*)(qbase + (size_t)r * RS + c4 * 4);
        Qs[c4 * 4 + 0][r] = v.x; Qs[c4 * 4 + 1][r] = v.y;
        Qs[c4 * 4 + 2][r] = v.z; Qs[c4 * 4 + 3][r] = v.w;
        float4 w = *(const float4*)(kbase + (size_t)r * RS + c4 * 4);
        Ks[c4 * 4 + 0][r] = w.x; Ks[c4 * 4 + 1][r] = w.y;
        Ks[c4 * 4 + 2][r] = w.z; Ks[c4 * 4 + 3][r] = w.w;
    }
    __syncthreads();
    int tx = tid & 15, ty = tid >> 4;
    float acc[4][4];
    #pragma unroll
    for (int i = 0; i < 4; i++)
        #pragma unroll
        for (int j = 0; j < 4; j++) acc[i][j] = 0.f;
    #pragma unroll 8
    for (int d = 0; d < 64; d++) {
        float a[4], bb[4];
        *(float4*)a  = *(const float4*)(&Qs[d][ty * 4]);
        *(float4*)bb = *(const float4*)(&Ks[d][tx * 4]);
        #pragma unroll
        for (int i = 0; i < 4; i++)
            #pragma unroll
            for (int j = 0; j < 4; j++)
                acc[i][j] = fmaf(a[i], bb[j], acc[i][j]);
    }
    #pragma unroll
    for (int i = 0; i < 4; i++) {
        size_t roff = ((size_t)bh * T_ + qt + ty * 4 + i) * T_ + kt + tx * 4;
        *(float4*)(wei + roff) = *(float4*)(acc[i]);
    }
}

// ---------------- masked softmax ----------------
__global__ void __launch_bounds__(256) softmax_kernel(float* __restrict__ wei)
{
    __shared__ float red[256];
    int row = blockIdx.x;
    int q = row & (T_ - 1);
    float* w = wei + (size_t)row * T_;
    int kend = ((q >> 6) + 1) << 6;
    int t = threadIdx.x;
    int k0 = t * 4;
    float vals[4];
    float mx = -INFINITY;
    #pragma unroll
    for (int j = 0; j < 4; j++) {
        int kk = k0 + j;
        float v = (kk <= q) ? w[kk] * 0.125f : -INFINITY;
        vals[j] = v;
        mx = fmaxf(mx, v);
    }
    red[t] = mx; __syncthreads();
    for (int o = 128; o > 0; o >>= 1) { if (t < o) red[t] = fmaxf(red[t], red[t + o]); __syncthreads(); }
    float Mx = red[0]; __syncthreads();
    float s = 0.f;
    #pragma unroll
    for (int j = 0; j < 4; j++) {
        int kk = k0 + j;
        float e = (kk <= q) ? __expf(vals[j] - Mx) : 0.f;
        vals[j] = e;
        s += e;
    }
    red[t] = s; __syncthreads();
    for (int o = 128; o > 0; o >>= 1) { if (t < o) red[t] += red[t + o]; __syncthreads(); }
    float invS = 1.f / red[0];
    #pragma unroll
    for (int j = 0; j < 4; j++) {
        int kk = k0 + j;
        if (kk < kend) w[kk] = vals[j] * invS;
    }
}

// ---------------- att = wei @ V -> fp16 hi/lo ----------------
__global__ void __launch_bounds__(256) attn_av_kernel(
    const float* __restrict__ wei, const float* __restrict__ qkv,
    __half* __restrict__ atthi, __half* __restrict__ attlo)
{
    int qt = blockIdx.x << 6;
    int bh = blockIdx.y;
    int b = bh >> 4, h = bh & 15;
    __shared__ float Ws[64][68];
    __shared__ float Vs[64][68];
    int tid = threadIdx.x;
    int tx = tid & 15, ty = tid >> 4;
    const int RS = 3 * C_;
    float acc[4][4];
    #pragma unroll
    for (int i = 0; i < 4; i++)
        #pragma unroll
        for (int j = 0; j < 4; j++) acc[i][j] = 0.f;

    for (int kt = 0; kt <= qt; kt += 64) {
        const float* wbase = wei + ((size_t)bh * T_ + qt) * T_ + kt;
        const float* vbase = qkv + (size_t)(b * T_ + kt) * RS + 2 * C_ + h * HS_;
        #pragma unroll
        for (int l = tid; l < 1024; l += 256) {
            int r = l >> 4, c4 = l & 15;
            *(float4*)(&Ws[r][c4 * 4]) = *(const float4*)(wbase + (size_t)r * T_ + c4 * 4);
            *(float4*)(&Vs[r][c4 * 4]) = *(const float4*)(vbase + (size_t)r * RS + c4 * 4);
        }
        __syncthreads();
        #pragma unroll 8
        for (int kk = 0; kk < 64; kk++) {
            float bb[4];
            *(float4*)bb = *(const float4*)(&Vs[kk][tx * 4]);
            float a0 = Ws[ty * 4 + 0][kk];
            float a1 = Ws[ty * 4 + 1][kk];
            float a2 = Ws[ty * 4 + 2][kk];
            float a3 = Ws[ty * 4 + 3][kk];
            #pragma unroll
            for (int j = 0; j < 4; j++) {
                acc[0][j] = fmaf(a0, bb[j], acc[0][j]);
                acc[1][j] = fmaf(a1, bb[j], acc[1][j]);
                acc[2][j] = fmaf(a2, bb[j], acc[2][j]);
                acc[3][j] = fmaf(a3, bb[j], acc[3][j]);
            }
        }
        __syncthreads();
    }
    #pragma unroll
    for (int i = 0; i < 4; i++) {
        size_t roff = ((size_t)(b * T_ + qt + ty * 4 + i)) * C_ + h * HS_ + tx * 4;
        __half h0, l0, h1, l1, h2, l2, h3, l3;
        split_f16(acc[i][0], h0, l0); split_f16(acc[i][1], h1, l1);
        split_f16(acc[i][2], h2, l2); split_f16(acc[i][3], h3, l3);
        *(__half2*)(atthi + roff)     = __halves2half2(h0, h1);
        *(__half2*)(atthi + roff + 2) = __halves2half2(h2, h3);
        *(__half2*)(attlo + roff)     = __halves2half2(l0, l1);
        *(__half2*)(attlo + roff + 2) = __halves2half2(l2, l3);
    }
}

// ---------------- loss ----------------
__global__ void zero_acc_kernel(float* acc) { *acc = 0.f; }

__global__ void __launch_bounds__(256) loss_kernel(
    const float* __restrict__ logits, const int* __restrict__ targets, float* __restrict__ acc)
{
    __shared__ float red[256];
    int row = blockIdx.x;
    const float* lr = logits + (size_t)row * V_;
    int t = threadIdx.x;
    float mx = -INFINITY;
    for (int c = t; c < V_; c += 256) mx = fmaxf(mx, lr[c]);
    red[t] = mx; __syncthreads();
    for (int o = 128; o > 0; o >>= 1) { if (t < o) red[t] = fmaxf(red[t], red[t + o]); __syncthreads(); }
    float Mx = red[0]; __syncthreads();
    float s = 0.f;
    for (int c = t; c < V_; c += 256) s += __expf(lr[c] - Mx);
    red[t] = s; __syncthreads();
    for (int o = 128; o > 0; o >>= 1) { if (t < o) red[t] += red[t + o]; __syncthreads(); }
    if (t == 0) {
        float lse = logf(red[0]) + Mx;
        int tgt = targets[row];
        atomicAdd(acc, (lse - lr[tgt]) * (1.f / M_));
    }
}

__global__ void write_loss_kernel(const float* acc, float* out) { out[0] = *acc; }

// ---------------- launch ----------------
extern "C" void kernel_launch(void* const* d_in, const int* in_sizes, int n_in,
                              void* d_out, int out_size)
{
    const int*   idx   = (const int*)d_in[0];
    const int*   tgt   = (const int*)d_in[1];
    const float* tok   = (const float*)d_in[2];
    const float* pos   = (const float*)d_in[3];
    const float* ln1g  = (const float*)d_in[4];
    const float* ln1b  = (const float*)d_in[5];
    const float* Wq    = (const float*)d_in[6];
    const float* Wk    = (const float*)d_in[7];
    const float* Wv    = (const float*)d_in[8];
    const float* Wo    = (const float*)d_in[9];
    const float* bo    = (const float*)d_in[10];
    const float* ln2g  = (const float*)d_in[11];
    const float* ln2b  = (const float*)d_in[12];
    const float* W1    = (const float*)d_in[13];
    const float* b1    = (const float*)d_in[14];
    const float* W2    = (const float*)d_in[15];
    const float* b2    = (const float*)d_in[16];
    const float* lnfg  = (const float*)d_in[17];
    const float* lnfb  = (const float*)d_in[18];
    const float* Wlm   = (const float*)d_in[19];
    const float* blm   = (const float*)d_in[20];

    float *xb, *qkvb, *wb, *accp;
    __half *hh, *hl, *ah, *al, *mh, *ml, *wt;
    cudaGetSymbolAddress((void**)&xb, g_x);
    cudaGetSymbolAddress((void**)&qkvb, g_qkv);
    cudaGetSymbolAddress((void**)&wb, g_wei);
    cudaGetSymbolAddress((void**)&accp, g_loss_acc);
    cudaGetSymbolAddress((void**)&hh, g_h_hi);
    cudaGetSymbolAddress((void**)&hl, g_h_lo);
    cudaGetSymbolAddress((void**)&ah, g_att_hi);
    cudaGetSymbolAddress((void**)&al, g_att_lo);
    cudaGetSymbolAddress((void**)&mh, g_mlp_hi);
    cudaGetSymbolAddress((void**)&ml, g_mlp_lo);
    cudaGetSymbolAddress((void**)&wt, g_wT);

    cudaFuncSetAttribute(gemm_mma_kernel, cudaFuncAttributeMaxDynamicSharedMemorySize, GSMEM);

    embed_kernel<<<M_, 256>>>(idx, tok, pos, xb);

    dim3 gC(C_ / 128, M_ / 128);
    dim3 gQKV(3 * C_ / 128, M_ / 128);
    dim3 gF(4 * C_ / 128, M_ / 128);
    dim3 gScore(T_ / 64, T_ / 64, B_ * H_);
    dim3 gAV(T_ / 64, B_ * H_);
    dim3 cvC(C_ / 32, C_ / 32);
    dim3 cv1(4 * C_ / 32, C_ / 32);
    dim3 cv2(C_ / 32, 4 * C_ / 32);
    dim3 cvLM(V_ / 32, C_ / 32);

    for (int l = 0; l < L_; l++) {
        ln_kernel<<<M_, 256>>>(xb, ln1g + (size_t)l * C_, ln1b + (size_t)l * C_, hh, hl);

        convw_kernel<<<cvC, 256>>>(Wq + (size_t)l * C_ * C_, wt,                       C_, C_);
        convw_kernel<<<cvC, 256>>>(Wk + (size_t)l * C_ * C_, wt + (size_t)C_ * C_,     C_, C_);
        convw_kernel<<<cvC, 256>>>(Wv + (size_t)l * C_ * C_, wt + (size_t)2 * C_ * C_, C_, C_);
        gemm_mma_kernel<<<gQKV, 256, GSMEM>>>(hh, hl, wt, nullptr, nullptr, qkvb, nullptr, nullptr, M_, 3 * C_, C_, 0);

        attn_scores_kernel<<<gScore, 256>>>(qkvb, wb);
        softmax_kernel<<<B_ * H_ * T_, 256>>>(wb);
        attn_av_kernel<<<gAV, 256>>>(wb, qkvb, ah, al);

        convw_kernel<<<cvC, 256>>>(Wo + (size_t)l * C_ * C_, wt, C_, C_);
        gemm_mma_kernel<<<gC, 256, GSMEM>>>(ah, al, wt, bo + (size_t)l * C_, xb, xb, nullptr, nullptr, M_, C_, C_, 0);

        ln_kernel<<<M_, 256>>>(xb, ln2g + (size_t)l * C_, ln2b + (size_t)l * C_, hh, hl);

        convw_kernel<<<cv1, 256>>>(W1 + (size_t)l * C_ * 4 * C_, wt, C_, 4 * C_);
        gemm_mma_kernel<<<gF, 256, GSMEM>>>(hh, hl, wt, b1 + (size_t)l * 4 * C_, nullptr, nullptr, mh, ml, M_, 4 * C_, C_, 1);
        convw_kernel<<<cv2, 256>>>(W2 + (size_t)l * 4 * C_ * C_, wt, 4 * C_, C_);
        gemm_mma_kernel<<<gC, 256, GSMEM>>>(mh, ml, wt, b2 + (size_t)l * C_, xb, xb, nullptr, nullptr, M_, C_, 4 * C_, 0);
    }

    ln_kernel<<<M_, 256>>>(xb, lnfg, lnfb, hh, hl);

    float* out = (float*)d_out;
    convw_kernel<<<cvLM, 256>>>(Wlm, wt, C_, V_);
    dim3 gLM(V_ / 128, M_ / 128);
    // LM head: 1-pass (Alo = nullptr)
    gemm_mma_kernel<<<gLM, 256, GSMEM>>>(hh, nullptr, wt, blm, nullptr, out, nullptr, nullptr, M_, V_, C_, 0);

    if ((size_t)out_size > NLOGITS) {
        zero_acc_kernel<<<1, 1>>>(accp);
        loss_kernel<<<M_, 256>>>(out, tgt, accp);
        write_loss_kernel<<<1, 1>>>(accp, out + NLOGITS);
    }
}

// round 7
// speedup vs baseline: 1.5105x; 1.1884x over previous
#include <cuda_runtime.h>
#include <cuda_fp16.h>
#include <math.h>
#include <stdint.h>

#define B_ 4
#define T_ 1024
#define C_ 1024
#define H_ 16
#define HS_ 64
#define L_ 12
#define V_ 50304
#define M_ 4096  // B*T

static const size_t NLOGITS = (size_t)M_ * V_;

// ---------------- scratch (device globals; no allocs allowed) ----------------
__device__ float g_x[(size_t)M_ * C_];
__device__ float g_wei[(size_t)B_ * H_ * T_ * T_];      // fp32 raw scores
__device__ __half g_wei16[(size_t)B_ * H_ * T_ * T_];   // fp16 softmax weights
__device__ float g_loss_acc;

__device__ __half g_qkv_hi[(size_t)M_ * 3 * C_];
__device__ __half g_qkv_lo[(size_t)M_ * 3 * C_];
__device__ __half g_h_hi[(size_t)M_ * C_];
__device__ __half g_h_lo[(size_t)M_ * C_];
__device__ __half g_att_hi[(size_t)M_ * C_];
__device__ __half g_att_lo[(size_t)M_ * C_];
__device__ __half g_mlp_hi[(size_t)M_ * 4 * C_];
__device__ __half g_mlp_lo[(size_t)M_ * 4 * C_];
__device__ __half g_wT[(size_t)V_ * C_];

// ---------------- helpers ----------------
__device__ __forceinline__ uint32_t smem_u32(const void* p) {
    uint32_t a;
    asm("{ .reg .u64 t; cvta.to.shared.u64 t, %1; cvt.u32.u64 %0, t; }" : "=r"(a) : "l"(p));
    return a;
}
#define CP16(dst, src) asm volatile("cp.async.cg.shared.global [%0], [%1], 16;" :: "r"(dst), "l"(src) : "memory")
#define CP_COMMIT() asm volatile("cp.async.commit_group;" ::: "memory")
#define CP_WAIT(n)  asm volatile("cp.async.wait_group %0;" :: "n"(n) : "memory")

__device__ __forceinline__ void split_f16(float x, __half& h, __half& l) {
    h = __float2half_rn(x);
    l = __float2half_rn(x - __half2float(h));
}

__device__ __forceinline__ void mma_f16(float* c, const uint32_t* a, const uint32_t* b) {
    asm volatile(
        "mma.sync.aligned.m16n8k16.row.col.f32.f16.f16.f32 "
        "{%0,%1,%2,%3}, {%4,%5,%6,%7}, {%8,%9}, {%0,%1,%2,%3};"
        : "+f"(c[0]), "+f"(c[1]), "+f"(c[2]), "+f"(c[3])
        : "r"(a[0]), "r"(a[1]), "r"(a[2]), "r"(a[3]), "r"(b[0]), "r"(b[1]));
}

__device__ __forceinline__ void ldm_x4(uint32_t* r, uint32_t addr) {
    asm volatile("ldmatrix.sync.aligned.m8n8.x4.shared.b16 {%0,%1,%2,%3}, [%4];"
        : "=r"(r[0]), "=r"(r[1]), "=r"(r[2]), "=r"(r[3]) : "r"(addr));
}
__device__ __forceinline__ void ldm_x4_t(uint32_t* r, uint32_t addr) {
    asm volatile("ldmatrix.sync.aligned.m8n8.x4.trans.shared.b16 {%0,%1,%2,%3}, [%4];"
        : "=r"(r[0]), "=r"(r[1]), "=r"(r[2]), "=r"(r[3]) : "r"(addr));
}

// ---------------- weight convert + transpose: W[K][N] -> wT[N][K] fp16 ----------------
__global__ void __launch_bounds__(256) convw_kernel(
    const float* __restrict__ W, __half* __restrict__ wT, int K, int N)
{
    __shared__ float tile[32][33];
    int nt = blockIdx.x * 32, kt = blockIdx.y * 32;
    int tx = threadIdx.x & 31, ty = threadIdx.x >> 5;
    #pragma unroll
    for (int j = 0; j < 4; j++) {
        int kk = ty + j * 8;
        tile[kk][tx] = W[(size_t)(kt + kk) * N + nt + tx];
    }
    __syncthreads();
    #pragma unroll
    for (int j = 0; j < 4; j++) {
        int nn = ty + j * 8;
        wT[(size_t)(nt + nn) * K + kt + tx] = __float2half_rn(tile[tx][nn]);
    }
}

// ---------------- fp16 2-pass GEMM via mma.sync + ldmatrix ----------------
#define GSTAGE 30720
#define GSMEM  (3 * GSTAGE)
__global__ void __launch_bounds__(256) gemm_mma_kernel(
    const __half* __restrict__ Ahi, const __half* __restrict__ Alo,
    const __half* __restrict__ Bw,
    const float* __restrict__ bias, const float* __restrict__ res,
    float* __restrict__ Cout, __half* __restrict__ Ohi, __half* __restrict__ Olo,
    int M, int N, int K, int relu)
{
    extern __shared__ char sm[];
    const uint32_t sbase = smem_u32(sm);
    const int tid = threadIdx.x;
    const int lane = tid & 31, wid = tid >> 5;
    const int wm = wid >> 2, wn = wid & 3;
    const int g = lane >> 2, tig = lane & 3;
    const int bm = blockIdx.y << 7, bn = blockIdx.x << 7;
    const bool twopass = (Alo != nullptr);

    const uint32_t aoff = (uint32_t)((wm * 64 + (lane & 15)) * 80 + (lane >> 4) * 16);
    const uint32_t boff = (uint32_t)((wn * 32 + (lane & 7) + ((lane >> 4) << 3)) * 80 + ((lane >> 3) & 1) * 16);

    float acc[4][4][4];
    #pragma unroll
    for (int a = 0; a < 4; a++)
        #pragma unroll
        for (int b = 0; b < 4; b++)
            #pragma unroll
            for (int c = 0; c < 4; c++) acc[a][b][c] = 0.f;

    const int nIter = K >> 5;

    auto stage = [&](int it) {
        const uint32_t s0 = sbase + (uint32_t)(it % 3) * GSTAGE;
        const int k0 = it << 5;
        #pragma unroll
        for (int j = 0; j < 2; j++) {
            int c = tid + j * 256;
            int row = c >> 2, q = c & 3;
            uint32_t d = (uint32_t)(row * 80 + q * 16);
            size_t ga = (size_t)(bm + row) * K + k0 + q * 8;
            size_t gb = (size_t)(bn + row) * K + k0 + q * 8;
            CP16(s0 + d, Ahi + ga);
            if (twopass) CP16(s0 + 10240 + d, Alo + ga);
            CP16(s0 + 20480 + d, Bw + gb);
        }
    };

    stage(0); CP_COMMIT();
    if (nIter > 1) { stage(1); CP_COMMIT(); }

    for (int i = 0; i < nIter; i++) {
        if (i + 1 < nIter) { CP_WAIT(1); } else { CP_WAIT(0); }
        __syncthreads();
        if (i + 2 < nIter) { stage(i + 2); CP_COMMIT(); }

        const uint32_t s0 = sbase + (uint32_t)(i % 3) * GSTAGE;
        #pragma unroll
        for (int ks = 0; ks < 2; ks++) {
            const uint32_t kofs = (uint32_t)(ks * 32);
            uint32_t ah[4][4], al[4][4], bh[4][2];
            #pragma unroll
            for (int mf = 0; mf < 4; mf++) {
                uint32_t ad = s0 + aoff + (uint32_t)(mf * 16 * 80) + kofs;
                ldm_x4(ah[mf], ad);
                if (twopass) ldm_x4(al[mf], ad + 10240);
            }
            #pragma unroll
            for (int p = 0; p < 2; p++) {
                uint32_t bd = s0 + 20480 + boff + (uint32_t)(p * 16 * 80) + kofs;
                uint32_t r[4];
                ldm_x4(r, bd);
                bh[2 * p][0] = r[0]; bh[2 * p][1] = r[1];
                bh[2 * p + 1][0] = r[2]; bh[2 * p + 1][1] = r[3];
            }
            #pragma unroll
            for (int mf = 0; mf < 4; mf++)
                #pragma unroll
                for (int nf = 0; nf < 4; nf++)
                    mma_f16(acc[mf][nf], ah[mf], bh[nf]);
            if (twopass) {
                #pragma unroll
                for (int mf = 0; mf < 4; mf++)
                    #pragma unroll
                    for (int nf = 0; nf < 4; nf++)
                        mma_f16(acc[mf][nf], al[mf], bh[nf]);
            }
        }
    }

    #pragma unroll
    for (int nf = 0; nf < 4; nf++) {
        int col = bn + wn * 32 + nf * 8 + 2 * tig;
        float2 bz = make_float2(0.f, 0.f);
        if (bias) bz = *(const float2*)(bias + col);
        #pragma unroll
        for (int mf = 0; mf < 4; mf++) {
            int row0 = bm + wm * 64 + mf * 16 + g;
            int row1 = row0 + 8;
            float c0 = acc[mf][nf][0] + bz.x;
            float c1 = acc[mf][nf][1] + bz.y;
            float c2 = acc[mf][nf][2] + bz.x;
            float c3 = acc[mf][nf][3] + bz.y;
            if (res) {
                float2 r0 = *(const float2*)(res + (size_t)row0 * N + col);
                float2 r1 = *(const float2*)(res + (size_t)row1 * N + col);
                c0 += r0.x; c1 += r0.y; c2 += r1.x; c3 += r1.y;
            }
            if (relu) {
                c0 = fmaxf(c0, 0.f); c1 = fmaxf(c1, 0.f);
                c2 = fmaxf(c2, 0.f); c3 = fmaxf(c3, 0.f);
            }
            if (Cout) {
                *(float2*)(Cout + (size_t)row0 * N + col) = make_float2(c0, c1);
                *(float2*)(Cout + (size_t)row1 * N + col) = make_float2(c2, c3);
            }
            if (Ohi) {
                __half h0, l0, h1, l1, h2, l2, h3, l3;
                split_f16(c0, h0, l0); split_f16(c1, h1, l1);
                split_f16(c2, h2, l2); split_f16(c3, h3, l3);
                *(__half2*)(Ohi + (size_t)row0 * N + col) = __halves2half2(h0, h1);
                *(__half2*)(Olo + (size_t)row0 * N + col) = __halves2half2(l0, l1);
                *(__half2*)(Ohi + (size_t)row1 * N + col) = __halves2half2(h2, h3);
                *(__half2*)(Olo + (size_t)row1 * N + col) = __halves2half2(l2, l3);
            }
        }
    }
}

// ---------------- embedding ----------------
__global__ void __launch_bounds__(256) embed_kernel(
    const int* __restrict__ idx, const float* __restrict__ tok,
    const float* __restrict__ pos, float* __restrict__ x)
{
    int row = blockIdx.x;
    int t = row & (T_ - 1);
    int token = idx[row];
    int c = threadIdx.x * 4;
    float4 a = *(const float4*)(tok + (size_t)token * C_ + c);
    float4 p = *(const float4*)(pos + (size_t)t * C_ + c);
    *(float4*)(x + (size_t)row * C_ + c) = make_float4(a.x + p.x, a.y + p.y, a.z + p.z, a.w + p.w);
}

// ---------------- layernorm -> fp16 hi/lo ----------------
__global__ void __launch_bounds__(256) ln_kernel(
    const float* __restrict__ x, const float* __restrict__ g,
    const float* __restrict__ b, __half* __restrict__ yhi, __half* __restrict__ ylo)
{
    __shared__ float red[256];
    int row = blockIdx.x;
    int t = threadIdx.x;
    const float* xr = x + (size_t)row * C_;
    float4 v = *(const float4*)(xr + t * 4);
    red[t] = v.x + v.y + v.z + v.w;
    __syncthreads();
    for (int o = 128; o > 0; o >>= 1) { if (t < o) red[t] += red[t + o]; __syncthreads(); }
    float mean = red[0] * (1.f / C_);
    __syncthreads();
    float dx = v.x - mean, dy = v.y - mean, dz = v.z - mean, dw = v.w - mean;
    red[t] = dx * dx + dy * dy + dz * dz + dw * dw;
    __syncthreads();
    for (int o = 128; o > 0; o >>= 1) { if (t < o) red[t] += red[t + o]; __syncthreads(); }
    float inv = rsqrtf(red[0] * (1.f / C_) + 1e-5f);
    float4 gv = *(const float4*)(g + t * 4);
    float4 bv = *(const float4*)(b + t * 4);
    float o0 = dx * inv * gv.x + bv.x;
    float o1 = dy * inv * gv.y + bv.y;
    float o2 = dz * inv * gv.z + bv.z;
    float o3 = dw * inv * gv.w + bv.w;
    __half h0, l0, h1, l1, h2, l2, h3, l3;
    split_f16(o0, h0, l0); split_f16(o1, h1, l1);
    split_f16(o2, h2, l2); split_f16(o3, h3, l3);
    size_t off = (size_t)row * C_ + t * 4;
    *(__half2*)(yhi + off)     = __halves2half2(h0, h1);
    *(__half2*)(yhi + off + 2) = __halves2half2(h2, h3);
    *(__half2*)(ylo + off)     = __halves2half2(l0, l1);
    *(__half2*)(ylo + off + 2) = __halves2half2(l2, l3);
}

// ---------------- attention scores via MMA: wei = Q.K^T (2-pass, Q exact) ----------------
// block: 128 thr (4 warps), tile 64q x 64k. smem rows: 72 halves (144B) stride.
__global__ void __launch_bounds__(128) attn_scores_mma(
    const __half* __restrict__ qkvh, const __half* __restrict__ qkvl,
    float* __restrict__ wei)
{
    int kt = blockIdx.x << 6;
    int qt = blockIdx.y << 6;
    if (kt > qt) return;
    int bh = blockIdx.z;
    int b = bh >> 4, h = bh & 15;
    __shared__ __half smbuf[3 * 64 * 72];
    const uint32_t s0 = smem_u32(smbuf);          // Qh
    const uint32_t sQl = s0 + 9216, sK = s0 + 18432;
    const int tid = threadIdx.x, lane = tid & 31, wid = tid >> 5;
    const int RS = 3 * C_;
    const int g = lane >> 2, tig = lane & 3;

    #pragma unroll
    for (int j = 0; j < 4; j++) {
        int c = tid + j * 128;                    // 0..511
        int row = c >> 3, q8 = c & 7;
        uint32_t d = (uint32_t)(row * 144 + q8 * 16);
        size_t gq = (size_t)(b * T_ + qt + row) * RS + h * HS_ + q8 * 8;
        size_t gk = (size_t)(b * T_ + kt + row) * RS + C_ + h * HS_ + q8 * 8;
        CP16(s0 + d, qkvh + gq);
        CP16(sQl + d, qkvl + gq);
        CP16(sK + d, qkvh + gk);
    }
    CP_COMMIT(); CP_WAIT(0);
    __syncthreads();

    float acc[8][4];
    #pragma unroll
    for (int n = 0; n < 8; n++)
        #pragma unroll
        for (int c = 0; c < 4; c++) acc[n][c] = 0.f;

    const uint32_t aoff = (uint32_t)((wid * 16 + (lane & 15)) * 144 + (lane >> 4) * 16);
    const uint32_t koff = (uint32_t)(((lane & 7) + ((lane >> 4) << 3)) * 144 + ((lane >> 3) & 1) * 16);

    #pragma unroll
    for (int kc = 0; kc < 4; kc++) {
        uint32_t ah[4], al[4], bb[8][2];
        ldm_x4(ah, s0 + aoff + kc * 32);
        ldm_x4(al, sQl + aoff + kc * 32);
        #pragma unroll
        for (int p = 0; p < 4; p++) {
            uint32_t r[4];
            ldm_x4(r, sK + koff + (uint32_t)(p * 16 * 144) + kc * 32);
            bb[2 * p][0] = r[0]; bb[2 * p][1] = r[1];
            bb[2 * p + 1][0] = r[2]; bb[2 * p + 1][1] = r[3];
        }
        #pragma unroll
        for (int nf = 0; nf < 8; nf++) mma_f16(acc[nf], ah, bb[nf]);
        #pragma unroll
        for (int nf = 0; nf < 8; nf++) mma_f16(acc[nf], al, bb[nf]);
    }

    #pragma unroll
    for (int nf = 0; nf < 8; nf++) {
        int col = kt + nf * 8 + 2 * tig;
        int row0 = qt + wid * 16 + g;
        *(float2*)(wei + (size_t)(bh * T_ + row0) * T_ + col) = make_float2(acc[nf][0], acc[nf][1]);
        *(float2*)(wei + (size_t)(bh * T_ + row0 + 8) * T_ + col) = make_float2(acc[nf][2], acc[nf][3]);
    }
}

// ---------------- masked softmax: fp32 scores in -> fp16 weights out ----------------
__global__ void __launch_bounds__(256) softmax_kernel(
    const float* __restrict__ wei, __half* __restrict__ wei16)
{
    __shared__ float red[256];
    int row = blockIdx.x;
    int q = row & (T_ - 1);
    const float* w = wei + (size_t)row * T_;
    __half* w16 = wei16 + (size_t)row * T_;
    int kend = ((q >> 6) + 1) << 6;
    int t = threadIdx.x;
    int k0 = t * 4;
    float vals[4];
    float mx = -INFINITY;
    #pragma unroll
    for (int j = 0; j < 4; j++) {
        int kk = k0 + j;
        float v = (kk <= q) ? w[kk] * 0.125f : -INFINITY;
        vals[j] = v;
        mx = fmaxf(mx, v);
    }
    red[t] = mx; __syncthreads();
    for (int o = 128; o > 0; o >>= 1) { if (t < o) red[t] = fmaxf(red[t], red[t + o]); __syncthreads(); }
    float Mx = red[0]; __syncthreads();
    float s = 0.f;
    #pragma unroll
    for (int j = 0; j < 4; j++) {
        int kk = k0 + j;
        float e = (kk <= q) ? __expf(vals[j] - Mx) : 0.f;
        vals[j] = e;
        s += e;
    }
    red[t] = s; __syncthreads();
    for (int o = 128; o > 0; o >>= 1) { if (t < o) red[t] += red[t + o]; __syncthreads(); }
    float invS = 1.f / red[0];
    if (k0 < kend) {
        __half2 a = __halves2half2(__float2half_rn(vals[0] * invS), __float2half_rn(vals[1] * invS));
        __half2 bq = __halves2half2(__float2half_rn(vals[2] * invS), __float2half_rn(vals[3] * invS));
        *(__half2*)(w16 + k0) = a;
        *(__half2*)(w16 + k0 + 2) = bq;
    }
}

// ---------------- attention AV via MMA: att = wei16 @ V (2-pass, V exact) ----------------
// block: 128 thr (4 warps), 64q rows x 64d; loop over kt tiles, double-buffered.
#define AVSTAGE 27648   // Ws 9216 + Vh 9216 + Vl 9216
#define AVSMEM  (2 * AVSTAGE)
__global__ void __launch_bounds__(128) attn_av_mma(
    const __half* __restrict__ wei16,
    const __half* __restrict__ qkvh, const __half* __restrict__ qkvl,
    __half* __restrict__ atthi, __half* __restrict__ attlo)
{
    extern __shared__ char avsm[];
    const uint32_t sbase = smem_u32(avsm);
    int qt = blockIdx.x << 6;
    int bh = blockIdx.y;
    int b = bh >> 4, h = bh & 15;
    const int tid = threadIdx.x, lane = tid & 31, wid = tid >> 5;
    const int RS = 3 * C_;
    const int g = lane >> 2, tig = lane & 3;
    const int nk = (qt >> 6) + 1;

    auto stage = [&](int it) {
        const uint32_t s0 = sbase + (uint32_t)(it & 1) * AVSTAGE;
        const int kt = it << 6;
        #pragma unroll
        for (int j = 0; j < 4; j++) {
            int c = tid + j * 128;
            int row = c >> 3, q8 = c & 7;
            uint32_t d = (uint32_t)(row * 144 + q8 * 16);
            size_t gw = (size_t)(bh * T_ + qt + row) * T_ + kt + q8 * 8;
            size_t gv = (size_t)(b * T_ + kt + row) * RS + 2 * C_ + h * HS_ + q8 * 8;
            CP16(s0 + d, wei16 + gw);
            CP16(s0 + 9216 + d, qkvh + gv);
            CP16(s0 + 18432 + d, qkvl + gv);
        }
    };

    float acc[8][4];
    #pragma unroll
    for (int n = 0; n < 8; n++)
        #pragma unroll
        for (int c = 0; c < 4; c++) acc[n][c] = 0.f;

    const uint32_t aoff = (uint32_t)((wid * 16 + (lane & 15)) * 144 + (lane >> 4) * 16);
    const uint32_t voff = (uint32_t)((lane & 15) * 144 + (lane >> 4) * 16);

    stage(0); CP_COMMIT();

    for (int i = 0; i < nk; i++) {
        if (i + 1 < nk) { stage(i + 1); CP_COMMIT(); CP_WAIT(1); } else { CP_WAIT(0); }
        __syncthreads();
        const uint32_t s0 = sbase + (uint32_t)(i & 1) * AVSTAGE;
        #pragma unroll
        for (int kc = 0; kc < 4; kc++) {
            uint32_t aw[4];
            ldm_x4(aw, s0 + aoff + kc * 32);
            #pragma unroll
            for (int db = 0; db < 4; db++) {
                uint32_t rh[4], rl[4];
                uint32_t vaddr = s0 + 9216 + voff + (uint32_t)(kc * 16 * 144) + db * 32;
                ldm_x4_t(rh, vaddr);
                ldm_x4_t(rl, vaddr + 9216);
                uint32_t bhf[2][2] = {{rh[0], rh[1]}, {rh[2], rh[3]}};
                uint32_t blf[2][2] = {{rl[0], rl[1]}, {rl[2], rl[3]}};
                mma_f16(acc[db * 2 + 0], aw, bhf[0]);
                mma_f16(acc[db * 2 + 1], aw, bhf[1]);
                mma_f16(acc[db * 2 + 0], aw, blf[0]);
                mma_f16(acc[db * 2 + 1], aw, blf[1]);
            }
        }
        __syncthreads();
    }

    #pragma unroll
    for (int nf = 0; nf < 8; nf++) {
        int col = h * HS_ + nf * 8 + 2 * tig;
        int row0 = qt + wid * 16 + g;
        #pragma unroll
        for (int half = 0; half < 2; half++) {
            int row = row0 + half * 8;
            float c0 = acc[nf][half * 2 + 0], c1 = acc[nf][half * 2 + 1];
            __half h0, l0, h1, l1;
            split_f16(c0, h0, l0); split_f16(c1, h1, l1);
            size_t off = (size_t)(b * T_ + row) * C_ + col;
            *(__half2*)(atthi + off) = __halves2half2(h0, h1);
            *(__half2*)(attlo + off) = __halves2half2(l0, l1);
        }
    }
}

// ---------------- loss ----------------
__global__ void zero_acc_kernel(float* acc) { *acc = 0.f; }

__global__ void __launch_bounds__(256) loss_kernel(
    const float* __restrict__ logits, const int* __restrict__ targets, float* __restrict__ acc)
{
    __shared__ float red[256];
    int row = blockIdx.x;
    const float* lr = logits + (size_t)row * V_;
    int t = threadIdx.x;
    float mx = -INFINITY;
    for (int c = t; c < V_; c += 256) mx = fmaxf(mx, lr[c]);
    red[t] = mx; __syncthreads();
    for (int o = 128; o > 0; o >>= 1) { if (t < o) red[t] = fmaxf(red[t], red[t + o]); __syncthreads(); }
    float Mx = red[0]; __syncthreads();
    float s = 0.f;
    for (int c = t; c < V_; c += 256) s += __expf(lr[c] - Mx);
    red[t] = s; __syncthreads();
    for (int o = 128; o > 0; o >>= 1) { if (t < o) red[t] += red[t + o]; __syncthreads(); }
    if (t == 0) {
        float lse = logf(red[0]) + Mx;
        int tgt = targets[row];
        atomicAdd(acc, (lse - lr[tgt]) * (1.f / M_));
    }
}

__global__ void write_loss_kernel(const float* acc, float* out) { out[0] = *acc; }

// ---------------- launch ----------------
extern "C" void kernel_launch(void* const* d_in, const int* in_sizes, int n_in,
                              void* d_out, int out_size)
{
    const int*   idx   = (const int*)d_in[0];
    const int*   tgt   = (const int*)d_in[1];
    const float* tok   = (const float*)d_in[2];
    const float* pos   = (const float*)d_in[3];
    const float* ln1g  = (const float*)d_in[4];
    const float* ln1b  = (const float*)d_in[5];
    const float* Wq    = (const float*)d_in[6];
    const float* Wk    = (const float*)d_in[7];
    const float* Wv    = (const float*)d_in[8];
    const float* Wo    = (const float*)d_in[9];
    const float* bo    = (const float*)d_in[10];
    const float* ln2g  = (const float*)d_in[11];
    const float* ln2b  = (const float*)d_in[12];
    const float* W1    = (const float*)d_in[13];
    const float* b1    = (const float*)d_in[14];
    const float* W2    = (const float*)d_in[15];
    const float* b2    = (const float*)d_in[16];
    const float* lnfg  = (const float*)d_in[17];
    const float* lnfb  = (const float*)d_in[18];
    const float* Wlm   = (const float*)d_in[19];
    const float* blm   = (const float*)d_in[20];

    float *xb, *wb, *accp;
    __half *w16, *qh, *ql, *hh, *hl, *ah, *al, *mh, *ml, *wt;
    cudaGetSymbolAddress((void**)&xb, g_x);
    cudaGetSymbolAddress((void**)&wb, g_wei);
    cudaGetSymbolAddress((void**)&w16, g_wei16);
    cudaGetSymbolAddress((void**)&accp, g_loss_acc);
    cudaGetSymbolAddress((void**)&qh, g_qkv_hi);
    cudaGetSymbolAddress((void**)&ql, g_qkv_lo);
    cudaGetSymbolAddress((void**)&hh, g_h_hi);
    cudaGetSymbolAddress((void**)&hl, g_h_lo);
    cudaGetSymbolAddress((void**)&ah, g_att_hi);
    cudaGetSymbolAddress((void**)&al, g_att_lo);
    cudaGetSymbolAddress((void**)&mh, g_mlp_hi);
    cudaGetSymbolAddress((void**)&ml, g_mlp_lo);
    cudaGetSymbolAddress((void**)&wt, g_wT);

    cudaFuncSetAttribute(gemm_mma_kernel, cudaFuncAttributeMaxDynamicSharedMemorySize, GSMEM);
    cudaFuncSetAttribute(attn_av_mma, cudaFuncAttributeMaxDynamicSharedMemorySize, AVSMEM);

    embed_kernel<<<M_, 256>>>(idx, tok, pos, xb);

    dim3 gC(C_ / 128, M_ / 128);
    dim3 gQKV(3 * C_ / 128, M_ / 128);
    dim3 gF(4 * C_ / 128, M_ / 128);
    dim3 gScore(T_ / 64, T_ / 64, B_ * H_);
    dim3 gAV(T_ / 64, B_ * H_);
    dim3 cvC(C_ / 32, C_ / 32);
    dim3 cv1(4 * C_ / 32, C_ / 32);
    dim3 cv2(C_ / 32, 4 * C_ / 32);
    dim3 cvLM(V_ / 32, C_ / 32);

    for (int l = 0; l < L_; l++) {
        ln_kernel<<<M_, 256>>>(xb, ln1g + (size_t)l * C_, ln1b + (size_t)l * C_, hh, hl);

        convw_kernel<<<cvC, 256>>>(Wq + (size_t)l * C_ * C_, wt,                       C_, C_);
        convw_kernel<<<cvC, 256>>>(Wk + (size_t)l * C_ * C_, wt + (size_t)C_ * C_,     C_, C_);
        convw_kernel<<<cvC, 256>>>(Wv + (size_t)l * C_ * C_, wt + (size_t)2 * C_ * C_, C_, C_);
        gemm_mma_kernel<<<gQKV, 256, GSMEM>>>(hh, hl, wt, nullptr, nullptr, nullptr, qh, ql, M_, 3 * C_, C_, 0);

        attn_scores_mma<<<gScore, 128>>>(qh, ql, wb);
        softmax_kernel<<<B_ * H_ * T_, 256>>>(wb, w16);
        attn_av_mma<<<gAV, 128, AVSMEM>>>(w16, qh, ql, ah, al);

        convw_kernel<<<cvC, 256>>>(Wo + (size_t)l * C_ * C_, wt, C_, C_);
        gemm_mma_kernel<<<gC, 256, GSMEM>>>(ah, al, wt, bo + (size_t)l * C_, xb, xb, nullptr, nullptr, M_, C_, C_, 0);

        ln_kernel<<<M_, 256>>>(xb, ln2g + (size_t)l * C_, ln2b + (size_t)l * C_, hh, hl);

        convw_kernel<<<cv1, 256>>>(W1 + (size_t)l * C_ * 4 * C_, wt, C_, 4 * C_);
        gemm_mma_kernel<<<gF, 256, GSMEM>>>(hh, hl, wt, b1 + (size_t)l * 4 * C_, nullptr, nullptr, mh, ml, M_, 4 * C_, C_, 1);
        convw_kernel<<<cv2, 256>>>(W2 + (size_t)l * 4 * C_ * C_, wt, 4 * C_, C_);
        gemm_mma_kernel<<<gC, 256, GSMEM>>>(mh, ml, wt, b2 + (size_t)l * C_, xb, xb, nullptr, nullptr, M_, C_, 4 * C_, 0);
    }

    ln_kernel<<<M_, 256>>>(xb, lnfg, lnfb, hh, hl);

    float* out = (float*)d_out;
    convw_kernel<<<cvLM, 256>>>(Wlm, wt, C_, V_);
    dim3 gLM(V_ / 128, M_ / 128);
    gemm_mma_kernel<<<gLM, 256, GSMEM>>>(hh, nullptr, wt, blm, nullptr, out, nullptr, nullptr, M_, V_, C_, 0);

    if ((size_t)out_size > NLOGITS) {
        zero_acc_kernel<<<1, 1>>>(accp);
        loss_kernel<<<M_, 256>>>(out, tgt, accp);
        write_loss_kernel<<<1, 1>>>(accp, out + NLOGITS);
    }
}

// round 8
// speedup vs baseline: 1.6837x; 1.1147x over previous
#include <cuda_runtime.h>
#include <cuda_fp16.h>
#include <math.h>
#include <stdint.h>

#define B_ 4
#define T_ 1024
#define C_ 1024
#define H_ 16
#define HS_ 64
#define L_ 12
#define V_ 50304
#define M_ 4096  // B*T

static const size_t NLOGITS = (size_t)M_ * V_;

// ---------------- scratch (device globals; no allocs allowed) ----------------
__device__ float g_x[(size_t)M_ * C_];
__device__ float g_loss_acc;

__device__ __half g_qkv_hi[(size_t)M_ * 3 * C_];
__device__ __half g_qkv_lo[(size_t)M_ * 3 * C_];
__device__ __half g_h_hi[(size_t)M_ * C_];
__device__ __half g_h_lo[(size_t)M_ * C_];
__device__ __half g_att_hi[(size_t)M_ * C_];
__device__ __half g_att_lo[(size_t)M_ * C_];
__device__ __half g_mlp_hi[(size_t)M_ * 4 * C_];
__device__ __half g_mlp_lo[(size_t)M_ * 4 * C_];
__device__ __half g_wT[(size_t)V_ * C_];

// ---------------- helpers ----------------
__device__ __forceinline__ uint32_t smem_u32(const void* p) {
    uint32_t a;
    asm("{ .reg .u64 t; cvta.to.shared.u64 t, %1; cvt.u32.u64 %0, t; }" : "=r"(a) : "l"(p));
    return a;
}
#define CP16(dst, src) asm volatile("cp.async.cg.shared.global [%0], [%1], 16;" :: "r"(dst), "l"(src) : "memory")
#define CP_COMMIT() asm volatile("cp.async.commit_group;" ::: "memory")
#define CP_WAIT(n)  asm volatile("cp.async.wait_group %0;" :: "n"(n) : "memory")

__device__ __forceinline__ void split_f16(float x, __half& h, __half& l) {
    h = __float2half_rn(x);
    l = __float2half_rn(x - __half2float(h));
}
__device__ __forceinline__ uint32_t packh2(float x, float y) {
    __half2 t = __halves2half2(__float2half_rn(x), __float2half_rn(y));
    return *(uint32_t*)&t;
}

__device__ __forceinline__ void mma_f16(float* c, const uint32_t* a, const uint32_t* b) {
    asm volatile(
        "mma.sync.aligned.m16n8k16.row.col.f32.f16.f16.f32 "
        "{%0,%1,%2,%3}, {%4,%5,%6,%7}, {%8,%9}, {%0,%1,%2,%3};"
        : "+f"(c[0]), "+f"(c[1]), "+f"(c[2]), "+f"(c[3])
        : "r"(a[0]), "r"(a[1]), "r"(a[2]), "r"(a[3]), "r"(b[0]), "r"(b[1]));
}

__device__ __forceinline__ void ldm_x4(uint32_t* r, uint32_t addr) {
    asm volatile("ldmatrix.sync.aligned.m8n8.x4.shared.b16 {%0,%1,%2,%3}, [%4];"
        : "=r"(r[0]), "=r"(r[1]), "=r"(r[2]), "=r"(r[3]) : "r"(addr));
}
__device__ __forceinline__ void ldm_x4_t(uint32_t* r, uint32_t addr) {
    asm volatile("ldmatrix.sync.aligned.m8n8.x4.trans.shared.b16 {%0,%1,%2,%3}, [%4];"
        : "=r"(r[0]), "=r"(r[1]), "=r"(r[2]), "=r"(r[3]) : "r"(addr));
}

// ---------------- weight convert + transpose: W[K][N] -> wT[N][K] fp16 ----------------
__global__ void __launch_bounds__(256) convw_kernel(
    const float* __restrict__ W, __half* __restrict__ wT, int K, int N)
{
    __shared__ float tile[32][33];
    int nt = blockIdx.x * 32, kt = blockIdx.y * 32;
    int tx = threadIdx.x & 31, ty = threadIdx.x >> 5;
    #pragma unroll
    for (int j = 0; j < 4; j++) {
        int kk = ty + j * 8;
        tile[kk][tx] = W[(size_t)(kt + kk) * N + nt + tx];
    }
    __syncthreads();
    #pragma unroll
    for (int j = 0; j < 4; j++) {
        int nn = ty + j * 8;
        wT[(size_t)(nt + nn) * K + kt + tx] = __float2half_rn(tile[tx][nn]);
    }
}

// ---------------- fp16 2-pass GEMM via mma.sync + ldmatrix ----------------
#define GSTAGE 30720
#define GSMEM  (3 * GSTAGE)
__global__ void __launch_bounds__(256) gemm_mma_kernel(
    const __half* __restrict__ Ahi, const __half* __restrict__ Alo,
    const __half* __restrict__ Bw,
    const float* __restrict__ bias, const float* __restrict__ res,
    float* __restrict__ Cout, __half* __restrict__ Ohi, __half* __restrict__ Olo,
    int M, int N, int K, int relu)
{
    extern __shared__ char sm[];
    const uint32_t sbase = smem_u32(sm);
    const int tid = threadIdx.x;
    const int lane = tid & 31, wid = tid >> 5;
    const int wm = wid >> 2, wn = wid & 3;
    const int g = lane >> 2, tig = lane & 3;
    const int bm = blockIdx.y << 7, bn = blockIdx.x << 7;
    const bool twopass = (Alo != nullptr);

    const uint32_t aoff = (uint32_t)((wm * 64 + (lane & 15)) * 80 + (lane >> 4) * 16);
    const uint32_t boff = (uint32_t)((wn * 32 + (lane & 7) + ((lane >> 4) << 3)) * 80 + ((lane >> 3) & 1) * 16);

    float acc[4][4][4];
    #pragma unroll
    for (int a = 0; a < 4; a++)
        #pragma unroll
        for (int b = 0; b < 4; b++)
            #pragma unroll
            for (int c = 0; c < 4; c++) acc[a][b][c] = 0.f;

    const int nIter = K >> 5;

    auto stage = [&](int it) {
        const uint32_t s0 = sbase + (uint32_t)(it % 3) * GSTAGE;
        const int k0 = it << 5;
        #pragma unroll
        for (int j = 0; j < 2; j++) {
            int c = tid + j * 256;
            int row = c >> 2, q = c & 3;
            uint32_t d = (uint32_t)(row * 80 + q * 16);
            size_t ga = (size_t)(bm + row) * K + k0 + q * 8;
            size_t gb = (size_t)(bn + row) * K + k0 + q * 8;
            CP16(s0 + d, Ahi + ga);
            if (twopass) CP16(s0 + 10240 + d, Alo + ga);
            CP16(s0 + 20480 + d, Bw + gb);
        }
    };

    stage(0); CP_COMMIT();
    if (nIter > 1) { stage(1); CP_COMMIT(); }

    for (int i = 0; i < nIter; i++) {
        if (i + 1 < nIter) { CP_WAIT(1); } else { CP_WAIT(0); }
        __syncthreads();
        if (i + 2 < nIter) { stage(i + 2); CP_COMMIT(); }

        const uint32_t s0 = sbase + (uint32_t)(i % 3) * GSTAGE;
        #pragma unroll
        for (int ks = 0; ks < 2; ks++) {
            const uint32_t kofs = (uint32_t)(ks * 32);
            uint32_t ah[4][4], al[4][4], bh[4][2];
            #pragma unroll
            for (int mf = 0; mf < 4; mf++) {
                uint32_t ad = s0 + aoff + (uint32_t)(mf * 16 * 80) + kofs;
                ldm_x4(ah[mf], ad);
                if (twopass) ldm_x4(al[mf], ad + 10240);
            }
            #pragma unroll
            for (int p = 0; p < 2; p++) {
                uint32_t bd = s0 + 20480 + boff + (uint32_t)(p * 16 * 80) + kofs;
                uint32_t r[4];
                ldm_x4(r, bd);
                bh[2 * p][0] = r[0]; bh[2 * p][1] = r[1];
                bh[2 * p + 1][0] = r[2]; bh[2 * p + 1][1] = r[3];
            }
            #pragma unroll
            for (int mf = 0; mf < 4; mf++)
                #pragma unroll
                for (int nf = 0; nf < 4; nf++)
                    mma_f16(acc[mf][nf], ah[mf], bh[nf]);
            if (twopass) {
                #pragma unroll
                for (int mf = 0; mf < 4; mf++)
                    #pragma unroll
                    for (int nf = 0; nf < 4; nf++)
                        mma_f16(acc[mf][nf], al[mf], bh[nf]);
            }
        }
    }

    #pragma unroll
    for (int nf = 0; nf < 4; nf++) {
        int col = bn + wn * 32 + nf * 8 + 2 * tig;
        float2 bz = make_float2(0.f, 0.f);
        if (bias) bz = *(const float2*)(bias + col);
        #pragma unroll
        for (int mf = 0; mf < 4; mf++) {
            int row0 = bm + wm * 64 + mf * 16 + g;
            int row1 = row0 + 8;
            float c0 = acc[mf][nf][0] + bz.x;
            float c1 = acc[mf][nf][1] + bz.y;
            float c2 = acc[mf][nf][2] + bz.x;
            float c3 = acc[mf][nf][3] + bz.y;
            if (res) {
                float2 r0 = *(const float2*)(res + (size_t)row0 * N + col);
                float2 r1 = *(const float2*)(res + (size_t)row1 * N + col);
                c0 += r0.x; c1 += r0.y; c2 += r1.x; c3 += r1.y;
            }
            if (relu) {
                c0 = fmaxf(c0, 0.f); c1 = fmaxf(c1, 0.f);
                c2 = fmaxf(c2, 0.f); c3 = fmaxf(c3, 0.f);
            }
            if (Cout) {
                *(float2*)(Cout + (size_t)row0 * N + col) = make_float2(c0, c1);
                *(float2*)(Cout + (size_t)row1 * N + col) = make_float2(c2, c3);
            }
            if (Ohi) {
                __half h0, l0, h1, l1, h2, l2, h3, l3;
                split_f16(c0, h0, l0); split_f16(c1, h1, l1);
                split_f16(c2, h2, l2); split_f16(c3, h3, l3);
                *(__half2*)(Ohi + (size_t)row0 * N + col) = __halves2half2(h0, h1);
                *(__half2*)(Olo + (size_t)row0 * N + col) = __halves2half2(l0, l1);
                *(__half2*)(Ohi + (size_t)row1 * N + col) = __halves2half2(h2, h3);
                *(__half2*)(Olo + (size_t)row1 * N + col) = __halves2half2(l2, l3);
            }
        }
    }
}

// ---------------- embedding ----------------
__global__ void __launch_bounds__(256) embed_kernel(
    const int* __restrict__ idx, const float* __restrict__ tok,
    const float* __restrict__ pos, float* __restrict__ x)
{
    int row = blockIdx.x;
    int t = row & (T_ - 1);
    int token = idx[row];
    int c = threadIdx.x * 4;
    float4 a = *(const float4*)(tok + (size_t)token * C_ + c);
    float4 p = *(const float4*)(pos + (size_t)t * C_ + c);
    *(float4*)(x + (size_t)row * C_ + c) = make_float4(a.x + p.x, a.y + p.y, a.z + p.z, a.w + p.w);
}

// ---------------- layernorm -> fp16 hi/lo ----------------
__global__ void __launch_bounds__(256) ln_kernel(
    const float* __restrict__ x, const float* __restrict__ g,
    const float* __restrict__ b, __half* __restrict__ yhi, __half* __restrict__ ylo)
{
    __shared__ float red[256];
    int row = blockIdx.x;
    int t = threadIdx.x;
    const float* xr = x + (size_t)row * C_;
    float4 v = *(const float4*)(xr + t * 4);
    red[t] = v.x + v.y + v.z + v.w;
    __syncthreads();
    for (int o = 128; o > 0; o >>= 1) { if (t < o) red[t] += red[t + o]; __syncthreads(); }
    float mean = red[0] * (1.f / C_);
    __syncthreads();
    float dx = v.x - mean, dy = v.y - mean, dz = v.z - mean, dw = v.w - mean;
    red[t] = dx * dx + dy * dy + dz * dz + dw * dw;
    __syncthreads();
    for (int o = 128; o > 0; o >>= 1) { if (t < o) red[t] += red[t + o]; __syncthreads(); }
    float inv = rsqrtf(red[0] * (1.f / C_) + 1e-5f);
    float4 gv = *(const float4*)(g + t * 4);
    float4 bv = *(const float4*)(b + t * 4);
    float o0 = dx * inv * gv.x + bv.x;
    float o1 = dy * inv * gv.y + bv.y;
    float o2 = dz * inv * gv.z + bv.z;
    float o3 = dw * inv * gv.w + bv.w;
    __half h0, l0, h1, l1, h2, l2, h3, l3;
    split_f16(o0, h0, l0); split_f16(o1, h1, l1);
    split_f16(o2, h2, l2); split_f16(o3, h3, l3);
    size_t off = (size_t)row * C_ + t * 4;
    *(__half2*)(yhi + off)     = __halves2half2(h0, h1);
    *(__half2*)(yhi + off + 2) = __halves2half2(h2, h3);
    *(__half2*)(ylo + off)     = __halves2half2(l0, l1);
    *(__half2*)(ylo + off + 2) = __halves2half2(l2, l3);
}

// ---------------- fused flash attention ----------------
// block: 128 thr (4 warps), 64 q-rows; loop over 64-key tiles with online softmax.
// Q: 2-pass exact (hi/lo), K: single fp16, wei: fp16 in-register, V: 2-pass exact.
#define FSTAGE 27648   // K 9216 + Vh 9216 + Vl 9216
#define FSMEM  (2 * FSTAGE + 18432)  // + Qh/Ql
__global__ void __launch_bounds__(128) flash_attn_kernel(
    const __half* __restrict__ qkvh, const __half* __restrict__ qkvl,
    __half* __restrict__ atthi, __half* __restrict__ attlo)
{
    extern __shared__ char fsm[];
    const uint32_t sbase = smem_u32(fsm);
    const uint32_t sQ = sbase + 2 * FSTAGE;
    const int qt = blockIdx.x << 6;
    const int bh = blockIdx.y;
    const int b = bh >> 4, h = bh & 15;
    const int tid = threadIdx.x, lane = tid & 31, wid = tid >> 5;
    const int RS = 3 * C_;
    const int g = lane >> 2, tig = lane & 3;
    const int nk = (qt >> 6) + 1;

    // load Q hi/lo (once)
    #pragma unroll
    for (int j = 0; j < 4; j++) {
        int c = tid + j * 128;
        int row = c >> 3, q8 = c & 7;
        uint32_t d = (uint32_t)(row * 144 + q8 * 16);
        size_t gq = (size_t)(b * T_ + qt + row) * RS + h * HS_ + q8 * 8;
        CP16(sQ + d, qkvh + gq);
        CP16(sQ + 9216 + d, qkvl + gq);
    }

    auto stage = [&](int it) {
        const uint32_t s0 = sbase + (uint32_t)(it & 1) * FSTAGE;
        const int kt = it << 6;
        #pragma unroll
        for (int j = 0; j < 4; j++) {
            int c = tid + j * 128;
            int row = c >> 3, q8 = c & 7;
            uint32_t d = (uint32_t)(row * 144 + q8 * 16);
            size_t gk = (size_t)(b * T_ + kt + row) * RS + C_ + h * HS_ + q8 * 8;
            size_t gv = (size_t)(b * T_ + kt + row) * RS + 2 * C_ + h * HS_ + q8 * 8;
            CP16(s0 + d, qkvh + gk);
            CP16(s0 + 9216 + d, qkvh + gv);
            CP16(s0 + 18432 + d, qkvl + gv);
        }
    };

    stage(0); CP_COMMIT();     // group: Q + K0/V0

    const uint32_t aoff = (uint32_t)((wid * 16 + (lane & 15)) * 144 + (lane >> 4) * 16);
    const uint32_t koff = (uint32_t)(((lane & 7) + ((lane >> 4) << 3)) * 144 + ((lane >> 3) & 1) * 16);
    const uint32_t voff = (uint32_t)((lane & 15) * 144 + (lane >> 4) * 16);

    float m0 = -INFINITY, m1 = -INFINITY, l0 = 0.f, l1 = 0.f;
    float accO[8][4];
    #pragma unroll
    for (int n = 0; n < 8; n++)
        #pragma unroll
        for (int c = 0; c < 4; c++) accO[n][c] = 0.f;

    uint32_t qhf[4][4], qlf[4][4];
    bool qloaded = false;

    for (int i = 0; i < nk; i++) {
        if (i + 1 < nk) { stage(i + 1); CP_COMMIT(); CP_WAIT(1); } else { CP_WAIT(0); }
        __syncthreads();
        if (!qloaded) {
            #pragma unroll
            for (int kc = 0; kc < 4; kc++) {
                ldm_x4(qhf[kc], sQ + aoff + kc * 32);
                ldm_x4(qlf[kc], sQ + 9216 + aoff + kc * 32);
            }
            qloaded = true;
        }
        const uint32_t s0 = sbase + (uint32_t)(i & 1) * FSTAGE;

        // ---- scores: 64x64 tile, Q exact 2-pass ----
        float acc[8][4];
        #pragma unroll
        for (int n = 0; n < 8; n++)
            #pragma unroll
            for (int c = 0; c < 4; c++) acc[n][c] = 0.f;
        #pragma unroll
        for (int kc = 0; kc < 4; kc++) {
            uint32_t bb[8][2];
            #pragma unroll
            for (int p = 0; p < 4; p++) {
                uint32_t r[4];
                ldm_x4(r, s0 + koff + (uint32_t)(p * 16 * 144) + kc * 32);
                bb[2 * p][0] = r[0]; bb[2 * p][1] = r[1];
                bb[2 * p + 1][0] = r[2]; bb[2 * p + 1][1] = r[3];
            }
            #pragma unroll
            for (int nf = 0; nf < 8; nf++) mma_f16(acc[nf], qhf[kc], bb[nf]);
            #pragma unroll
            for (int nf = 0; nf < 8; nf++) mma_f16(acc[nf], qlf[kc], bb[nf]);
        }

        // ---- mask + scale ----
        const bool diag = (i == nk - 1);
        const int lr0 = wid * 16 + g, lr1 = lr0 + 8;
        #pragma unroll
        for (int nf = 0; nf < 8; nf++) {
            int c0 = nf * 8 + 2 * tig;
            acc[nf][0] = (diag && (c0     > lr0)) ? -INFINITY : acc[nf][0] * 0.125f;
            acc[nf][1] = (diag && (c0 + 1 > lr0)) ? -INFINITY : acc[nf][1] * 0.125f;
            acc[nf][2] = (diag && (c0     > lr1)) ? -INFINITY : acc[nf][2] * 0.125f;
            acc[nf][3] = (diag && (c0 + 1 > lr1)) ? -INFINITY : acc[nf][3] * 0.125f;
        }

        // ---- online softmax (rows r0, r1) ----
        float mt0 = -INFINITY, mt1 = -INFINITY;
        #pragma unroll
        for (int nf = 0; nf < 8; nf++) {
            mt0 = fmaxf(mt0, fmaxf(acc[nf][0], acc[nf][1]));
            mt1 = fmaxf(mt1, fmaxf(acc[nf][2], acc[nf][3]));
        }
        mt0 = fmaxf(mt0, __shfl_xor_sync(0xffffffff, mt0, 1));
        mt0 = fmaxf(mt0, __shfl_xor_sync(0xffffffff, mt0, 2));
        mt1 = fmaxf(mt1, __shfl_xor_sync(0xffffffff, mt1, 1));
        mt1 = fmaxf(mt1, __shfl_xor_sync(0xffffffff, mt1, 2));
        float mn0 = fmaxf(m0, mt0), mn1 = fmaxf(m1, mt1);
        float al0 = __expf(m0 - mn0), al1 = __expf(m1 - mn1);
        float sum0 = 0.f, sum1 = 0.f;
        #pragma unroll
        for (int nf = 0; nf < 8; nf++) {
            acc[nf][0] = __expf(acc[nf][0] - mn0);
            acc[nf][1] = __expf(acc[nf][1] - mn0);
            acc[nf][2] = __expf(acc[nf][2] - mn1);
            acc[nf][3] = __expf(acc[nf][3] - mn1);
            sum0 += acc[nf][0] + acc[nf][1];
            sum1 += acc[nf][2] + acc[nf][3];
        }
        sum0 += __shfl_xor_sync(0xffffffff, sum0, 1);
        sum0 += __shfl_xor_sync(0xffffffff, sum0, 2);
        sum1 += __shfl_xor_sync(0xffffffff, sum1, 1);
        sum1 += __shfl_xor_sync(0xffffffff, sum1, 2);
        l0 = l0 * al0 + sum0;
        l1 = l1 * al1 + sum1;
        m0 = mn0; m1 = mn1;
        #pragma unroll
        for (int nf = 0; nf < 8; nf++) {
            accO[nf][0] *= al0; accO[nf][1] *= al0;
            accO[nf][2] *= al1; accO[nf][3] *= al1;
        }

        // ---- AV: wei(fp16, in-register) @ V (exact 2-pass) ----
        #pragma unroll
        for (int kc = 0; kc < 4; kc++) {
            uint32_t aw[4];
            aw[0] = packh2(acc[2 * kc][0],     acc[2 * kc][1]);
            aw[1] = packh2(acc[2 * kc][2],     acc[2 * kc][3]);
            aw[2] = packh2(acc[2 * kc + 1][0], acc[2 * kc + 1][1]);
            aw[3] = packh2(acc[2 * kc + 1][2], acc[2 * kc + 1][3]);
            #pragma unroll
            for (int db = 0; db < 4; db++) {
                uint32_t rh[4], rl[4];
                uint32_t vaddr = s0 + 9216 + voff + (uint32_t)(kc * 16 * 144) + db * 32;
                ldm_x4_t(rh, vaddr);
                ldm_x4_t(rl, vaddr + 9216);
                mma_f16(accO[2 * db],     aw, rh);
                mma_f16(accO[2 * db + 1], aw, rh + 2);
                mma_f16(accO[2 * db],     aw, rl);
                mma_f16(accO[2 * db + 1], aw, rl + 2);
            }
        }
        __syncthreads();
    }

    // ---- epilogue: O / l -> att hi/lo ----
    float il0 = 1.f / l0, il1 = 1.f / l1;
    #pragma unroll
    for (int nf = 0; nf < 8; nf++) {
        int col = h * HS_ + nf * 8 + 2 * tig;
        int row0 = qt + wid * 16 + g;
        float c0 = accO[nf][0] * il0, c1 = accO[nf][1] * il0;
        float c2 = accO[nf][2] * il1, c3 = accO[nf][3] * il1;
        __half h0, lo0, h1, lo1, h2, lo2, h3, lo3;
        split_f16(c0, h0, lo0); split_f16(c1, h1, lo1);
        split_f16(c2, h2, lo2); split_f16(c3, h3, lo3);
        size_t off0 = (size_t)(b * T_ + row0) * C_ + col;
        size_t off1 = (size_t)(b * T_ + row0 + 8) * C_ + col;
        *(__half2*)(atthi + off0) = __halves2half2(h0, h1);
        *(__half2*)(attlo + off0) = __halves2half2(lo0, lo1);
        *(__half2*)(atthi + off1) = __halves2half2(h2, h3);
        *(__half2*)(attlo + off1) = __halves2half2(lo2, lo3);
    }
}

// ---------------- loss ----------------
__global__ void zero_acc_kernel(float* acc) { *acc = 0.f; }

__global__ void __launch_bounds__(256) loss_kernel(
    const float* __restrict__ logits, const int* __restrict__ targets, float* __restrict__ acc)
{
    __shared__ float red[256];
    int row = blockIdx.x;
    const float* lr = logits + (size_t)row * V_;
    int t = threadIdx.x;
    float mx = -INFINITY;
    for (int c = t; c < V_; c += 256) mx = fmaxf(mx, lr[c]);
    red[t] = mx; __syncthreads();
    for (int o = 128; o > 0; o >>= 1) { if (t < o) red[t] = fmaxf(red[t], red[t + o]); __syncthreads(); }
    float Mx = red[0]; __syncthreads();
    float s = 0.f;
    for (int c = t; c < V_; c += 256) s += __expf(lr[c] - Mx);
    red[t] = s; __syncthreads();
    for (int o = 128; o > 0; o >>= 1) { if (t < o) red[t] += red[t + o]; __syncthreads(); }
    if (t == 0) {
        float lse = logf(red[0]) + Mx;
        int tgt = targets[row];
        atomicAdd(acc, (lse - lr[tgt]) * (1.f / M_));
    }
}

__global__ void write_loss_kernel(const float* acc, float* out) { out[0] = *acc; }

// ---------------- launch ----------------
extern "C" void kernel_launch(void* const* d_in, const int* in_sizes, int n_in,
                              void* d_out, int out_size)
{
    const int*   idx   = (const int*)d_in[0];
    const int*   tgt   = (const int*)d_in[1];
    const float* tok   = (const float*)d_in[2];
    const float* pos   = (const float*)d_in[3];
    const float* ln1g  = (const float*)d_in[4];
    const float* ln1b  = (const float*)d_in[5];
    const float* Wq    = (const float*)d_in[6];
    const float* Wk    = (const float*)d_in[7];
    const float* Wv    = (const float*)d_in[8];
    const float* Wo    = (const float*)d_in[9];
    const float* bo    = (const float*)d_in[10];
    const float* ln2g  = (const float*)d_in[11];
    const float* ln2b  = (const float*)d_in[12];
    const float* W1    = (const float*)d_in[13];
    const float* b1    = (const float*)d_in[14];
    const float* W2    = (const float*)d_in[15];
    const float* b2    = (const float*)d_in[16];
    const float* lnfg  = (const float*)d_in[17];
    const float* lnfb  = (const float*)d_in[18];
    const float* Wlm   = (const float*)d_in[19];
    const float* blm   = (const float*)d_in[20];

    float *xb, *accp;
    __half *qh, *ql, *hh, *hl, *ah, *al, *mh, *ml, *wt;
    cudaGetSymbolAddress((void**)&xb, g_x);
    cudaGetSymbolAddress((void**)&accp, g_loss_acc);
    cudaGetSymbolAddress((void**)&qh, g_qkv_hi);
    cudaGetSymbolAddress((void**)&ql, g_qkv_lo);
    cudaGetSymbolAddress((void**)&hh, g_h_hi);
    cudaGetSymbolAddress((void**)&hl, g_h_lo);
    cudaGetSymbolAddress((void**)&ah, g_att_hi);
    cudaGetSymbolAddress((void**)&al, g_att_lo);
    cudaGetSymbolAddress((void**)&mh, g_mlp_hi);
    cudaGetSymbolAddress((void**)&ml, g_mlp_lo);
    cudaGetSymbolAddress((void**)&wt, g_wT);

    cudaFuncSetAttribute(gemm_mma_kernel, cudaFuncAttributeMaxDynamicSharedMemorySize, GSMEM);
    cudaFuncSetAttribute(flash_attn_kernel, cudaFuncAttributeMaxDynamicSharedMemorySize, FSMEM);

    embed_kernel<<<M_, 256>>>(idx, tok, pos, xb);

    dim3 gC(C_ / 128, M_ / 128);
    dim3 gQKV(3 * C_ / 128, M_ / 128);
    dim3 gF(4 * C_ / 128, M_ / 128);
    dim3 gFlash(T_ / 64, B_ * H_);
    dim3 cvC(C_ / 32, C_ / 32);
    dim3 cv1(4 * C_ / 32, C_ / 32);
    dim3 cv2(C_ / 32, 4 * C_ / 32);
    dim3 cvLM(V_ / 32, C_ / 32);

    for (int l = 0; l < L_; l++) {
        ln_kernel<<<M_, 256>>>(xb, ln1g + (size_t)l * C_, ln1b + (size_t)l * C_, hh, hl);

        convw_kernel<<<cvC, 256>>>(Wq + (size_t)l * C_ * C_, wt,                       C_, C_);
        convw_kernel<<<cvC, 256>>>(Wk + (size_t)l * C_ * C_, wt + (size_t)C_ * C_,     C_, C_);
        convw_kernel<<<cvC, 256>>>(Wv + (size_t)l * C_ * C_, wt + (size_t)2 * C_ * C_, C_, C_);
        gemm_mma_kernel<<<gQKV, 256, GSMEM>>>(hh, hl, wt, nullptr, nullptr, nullptr, qh, ql, M_, 3 * C_, C_, 0);

        flash_attn_kernel<<<gFlash, 128, FSMEM>>>(qh, ql, ah, al);

        convw_kernel<<<cvC, 256>>>(Wo + (size_t)l * C_ * C_, wt, C_, C_);
        gemm_mma_kernel<<<gC, 256, GSMEM>>>(ah, al, wt, bo + (size_t)l * C_, xb, xb, nullptr, nullptr, M_, C_, C_, 0);

        ln_kernel<<<M_, 256>>>(xb, ln2g + (size_t)l * C_, ln2b + (size_t)l * C_, hh, hl);

        convw_kernel<<<cv1, 256>>>(W1 + (size_t)l * C_ * 4 * C_, wt, C_, 4 * C_);
        gemm_mma_kernel<<<gF, 256, GSMEM>>>(hh, hl, wt, b1 + (size_t)l * 4 * C_, nullptr, nullptr, mh, ml, M_, 4 * C_, C_, 1);
        convw_kernel<<<cv2, 256>>>(W2 + (size_t)l * 4 * C_ * C_, wt, 4 * C_, C_);
        gemm_mma_kernel<<<gC, 256, GSMEM>>>(mh, ml, wt, b2 + (size_t)l * C_, xb, xb, nullptr, nullptr, M_, C_, 4 * C_, 0);
    }

    ln_kernel<<<M_, 256>>>(xb, lnfg, lnfb, hh, hl);

    float* out = (float*)d_out;
    convw_kernel<<<cvLM, 256>>>(Wlm, wt, C_, V_);
    dim3 gLM(V_ / 128, M_ / 128);
    gemm_mma_kernel<<<gLM, 256, GSMEM>>>(hh, nullptr, wt, blm, nullptr, out, nullptr, nullptr, M_, V_, C_, 0);

    if ((size_t)out_size > NLOGITS) {
        zero_acc_kernel<<<1, 1>>>(accp);
        loss_kernel<<<M_, 256>>>(out, tgt, accp);
        write_loss_kernel<<<1, 1>>>(accp, out + NLOGITS);
    }
}

// round 9
// speedup vs baseline: 1.8702x; 1.1108x over previous
#include <cuda_runtime.h>
#include <cuda_fp16.h>
#include <math.h>
#include <stdint.h>

#define B_ 4
#define T_ 1024
#define C_ 1024
#define H_ 16
#define HS_ 64
#define L_ 12
#define V_ 50304
#define M_ 4096  // B*T

static const size_t NLOGITS = (size_t)M_ * V_;

// ---------------- scratch (device globals; no allocs allowed) ----------------
__device__ float g_x[(size_t)M_ * C_];
__device__ float g_loss_acc;

__device__ __half g_qkv[(size_t)M_ * 3 * C_];     // fp16 q,k,v (exact fp16)
__device__ __half g_h_hi[(size_t)M_ * C_];
__device__ __half g_h_lo[(size_t)M_ * C_];
__device__ __half g_att_hi[(size_t)M_ * C_];
__device__ __half g_att_lo[(size_t)M_ * C_];
__device__ __half g_mlp_hi[(size_t)M_ * 4 * C_];
__device__ __half g_mlp_lo[(size_t)M_ * 4 * C_];
__device__ __half g_wT[(size_t)V_ * C_];

// ---------------- helpers ----------------
__device__ __forceinline__ uint32_t smem_u32(const void* p) {
    uint32_t a;
    asm("{ .reg .u64 t; cvta.to.shared.u64 t, %1; cvt.u32.u64 %0, t; }" : "=r"(a) : "l"(p));
    return a;
}
#define CP16(dst, src) asm volatile("cp.async.cg.shared.global [%0], [%1], 16;" :: "r"(dst), "l"(src) : "memory")
#define CP_COMMIT() asm volatile("cp.async.commit_group;" ::: "memory")
#define CP_WAIT(n)  asm volatile("cp.async.wait_group %0;" :: "n"(n) : "memory")

__device__ __forceinline__ void split_f16(float x, __half& h, __half& l) {
    h = __float2half_rn(x);
    l = __float2half_rn(x - __half2float(h));
}
__device__ __forceinline__ uint32_t packh2(float x, float y) {
    __half2 t = __halves2half2(__float2half_rn(x), __float2half_rn(y));
    return *(uint32_t*)&t;
}

__device__ __forceinline__ void mma_f16(float* c, const uint32_t* a, const uint32_t* b) {
    asm volatile(
        "mma.sync.aligned.m16n8k16.row.col.f32.f16.f16.f32 "
        "{%0,%1,%2,%3}, {%4,%5,%6,%7}, {%8,%9}, {%0,%1,%2,%3};"
        : "+f"(c[0]), "+f"(c[1]), "+f"(c[2]), "+f"(c[3])
        : "r"(a[0]), "r"(a[1]), "r"(a[2]), "r"(a[3]), "r"(b[0]), "r"(b[1]));
}

__device__ __forceinline__ void ldm_x4(uint32_t* r, uint32_t addr) {
    asm volatile("ldmatrix.sync.aligned.m8n8.x4.shared.b16 {%0,%1,%2,%3}, [%4];"
        : "=r"(r[0]), "=r"(r[1]), "=r"(r[2]), "=r"(r[3]) : "r"(addr));
}
__device__ __forceinline__ void ldm_x4_t(uint32_t* r, uint32_t addr) {
    asm volatile("ldmatrix.sync.aligned.m8n8.x4.trans.shared.b16 {%0,%1,%2,%3}, [%4];"
        : "=r"(r[0]), "=r"(r[1]), "=r"(r[2]), "=r"(r[3]) : "r"(addr));
}

// ---------------- weight convert + transpose: W[K][N] -> wT[N][K] fp16 ----------------
__global__ void __launch_bounds__(256) convw_kernel(
    const float* __restrict__ W, __half* __restrict__ wT, int K, int N)
{
    __shared__ float tile[32][33];
    int nt = blockIdx.x * 32, kt = blockIdx.y * 32;
    int tx = threadIdx.x & 31, ty = threadIdx.x >> 5;
    #pragma unroll
    for (int j = 0; j < 4; j++) {
        int kk = ty + j * 8;
        tile[kk][tx] = W[(size_t)(kt + kk) * N + nt + tx];
    }
    __syncthreads();
    #pragma unroll
    for (int j = 0; j < 4; j++) {
        int nn = ty + j * 8;
        wT[(size_t)(nt + nn) * K + kt + tx] = __float2half_rn(tile[tx][nn]);
    }
}

// fused QKV weight convert: z selects Wq/Wk/Wv (all C x C)
__global__ void __launch_bounds__(256) convw3_kernel(
    const float* __restrict__ Wq, const float* __restrict__ Wk,
    const float* __restrict__ Wv, __half* __restrict__ wT)
{
    __shared__ float tile[32][33];
    int z = blockIdx.z;
    const float* W = (z == 0) ? Wq : (z == 1) ? Wk : Wv;
    __half* out = wT + (size_t)z * C_ * C_;
    int nt = blockIdx.x * 32, kt = blockIdx.y * 32;
    int tx = threadIdx.x & 31, ty = threadIdx.x >> 5;
    #pragma unroll
    for (int j = 0; j < 4; j++) {
        int kk = ty + j * 8;
        tile[kk][tx] = W[(size_t)(kt + kk) * C_ + nt + tx];
    }
    __syncthreads();
    #pragma unroll
    for (int j = 0; j < 4; j++) {
        int nn = ty + j * 8;
        out[(size_t)(nt + nn) * C_ + kt + tx] = __float2half_rn(tile[tx][nn]);
    }
}

// ---------------- fp16 GEMM via mma.sync + ldmatrix (1- or 2-pass) ----------------
#define GSTAGE 30720
#define GSMEM  (3 * GSTAGE)
__global__ void __launch_bounds__(256) gemm_mma_kernel(
    const __half* __restrict__ Ahi, const __half* __restrict__ Alo,
    const __half* __restrict__ Bw,
    const float* __restrict__ bias, const float* __restrict__ res,
    float* __restrict__ Cout, __half* __restrict__ Ohi, __half* __restrict__ Olo,
    int M, int N, int K, int relu)
{
    extern __shared__ char sm[];
    const uint32_t sbase = smem_u32(sm);
    const int tid = threadIdx.x;
    const int lane = tid & 31, wid = tid >> 5;
    const int wm = wid >> 2, wn = wid & 3;
    const int g = lane >> 2, tig = lane & 3;
    const int bm = blockIdx.y << 7, bn = blockIdx.x << 7;
    const bool twopass = (Alo != nullptr);

    const uint32_t aoff = (uint32_t)((wm * 64 + (lane & 15)) * 80 + (lane >> 4) * 16);
    const uint32_t boff = (uint32_t)((wn * 32 + (lane & 7) + ((lane >> 4) << 3)) * 80 + ((lane >> 3) & 1) * 16);

    float acc[4][4][4];
    #pragma unroll
    for (int a = 0; a < 4; a++)
        #pragma unroll
        for (int b = 0; b < 4; b++)
            #pragma unroll
            for (int c = 0; c < 4; c++) acc[a][b][c] = 0.f;

    const int nIter = K >> 5;

    auto stage = [&](int it) {
        const uint32_t s0 = sbase + (uint32_t)(it % 3) * GSTAGE;
        const int k0 = it << 5;
        #pragma unroll
        for (int j = 0; j < 2; j++) {
            int c = tid + j * 256;
            int row = c >> 2, q = c & 3;
            uint32_t d = (uint32_t)(row * 80 + q * 16);
            size_t ga = (size_t)(bm + row) * K + k0 + q * 8;
            size_t gb = (size_t)(bn + row) * K + k0 + q * 8;
            CP16(s0 + d, Ahi + ga);
            if (twopass) CP16(s0 + 10240 + d, Alo + ga);
            CP16(s0 + 20480 + d, Bw + gb);
        }
    };

    stage(0); CP_COMMIT();
    if (nIter > 1) { stage(1); CP_COMMIT(); }

    for (int i = 0; i < nIter; i++) {
        if (i + 1 < nIter) { CP_WAIT(1); } else { CP_WAIT(0); }
        __syncthreads();
        if (i + 2 < nIter) { stage(i + 2); CP_COMMIT(); }

        const uint32_t s0 = sbase + (uint32_t)(i % 3) * GSTAGE;
        #pragma unroll
        for (int ks = 0; ks < 2; ks++) {
            const uint32_t kofs = (uint32_t)(ks * 32);
            uint32_t ah[4][4], al[4][4], bh[4][2];
            #pragma unroll
            for (int mf = 0; mf < 4; mf++) {
                uint32_t ad = s0 + aoff + (uint32_t)(mf * 16 * 80) + kofs;
                ldm_x4(ah[mf], ad);
                if (twopass) ldm_x4(al[mf], ad + 10240);
            }
            #pragma unroll
            for (int p = 0; p < 2; p++) {
                uint32_t bd = s0 + 20480 + boff + (uint32_t)(p * 16 * 80) + kofs;
                uint32_t r[4];
                ldm_x4(r, bd);
                bh[2 * p][0] = r[0]; bh[2 * p][1] = r[1];
                bh[2 * p + 1][0] = r[2]; bh[2 * p + 1][1] = r[3];
            }
            #pragma unroll
            for (int mf = 0; mf < 4; mf++)
                #pragma unroll
                for (int nf = 0; nf < 4; nf++)
                    mma_f16(acc[mf][nf], ah[mf], bh[nf]);
            if (twopass) {
                #pragma unroll
                for (int mf = 0; mf < 4; mf++)
                    #pragma unroll
                    for (int nf = 0; nf < 4; nf++)
                        mma_f16(acc[mf][nf], al[mf], bh[nf]);
            }
        }
    }

    #pragma unroll
    for (int nf = 0; nf < 4; nf++) {
        int col = bn + wn * 32 + nf * 8 + 2 * tig;
        float2 bz = make_float2(0.f, 0.f);
        if (bias) bz = *(const float2*)(bias + col);
        #pragma unroll
        for (int mf = 0; mf < 4; mf++) {
            int row0 = bm + wm * 64 + mf * 16 + g;
            int row1 = row0 + 8;
            float c0 = acc[mf][nf][0] + bz.x;
            float c1 = acc[mf][nf][1] + bz.y;
            float c2 = acc[mf][nf][2] + bz.x;
            float c3 = acc[mf][nf][3] + bz.y;
            if (res) {
                float2 r0 = *(const float2*)(res + (size_t)row0 * N + col);
                float2 r1 = *(const float2*)(res + (size_t)row1 * N + col);
                c0 += r0.x; c1 += r0.y; c2 += r1.x; c3 += r1.y;
            }
            if (relu) {
                c0 = fmaxf(c0, 0.f); c1 = fmaxf(c1, 0.f);
                c2 = fmaxf(c2, 0.f); c3 = fmaxf(c3, 0.f);
            }
            if (Cout) {
                *(float2*)(Cout + (size_t)row0 * N + col) = make_float2(c0, c1);
                *(float2*)(Cout + (size_t)row1 * N + col) = make_float2(c2, c3);
            }
            if (Ohi) {
                if (Olo) {
                    __half h0, l0, h1, l1, h2, l2, h3, l3;
                    split_f16(c0, h0, l0); split_f16(c1, h1, l1);
                    split_f16(c2, h2, l2); split_f16(c3, h3, l3);
                    *(__half2*)(Ohi + (size_t)row0 * N + col) = __halves2half2(h0, h1);
                    *(__half2*)(Olo + (size_t)row0 * N + col) = __halves2half2(l0, l1);
                    *(__half2*)(Ohi + (size_t)row1 * N + col) = __halves2half2(h2, h3);
                    *(__half2*)(Olo + (size_t)row1 * N + col) = __halves2half2(l2, l3);
                } else {
                    *(uint32_t*)(Ohi + (size_t)row0 * N + col) = packh2(c0, c1);
                    *(uint32_t*)(Ohi + (size_t)row1 * N + col) = packh2(c2, c3);
                }
            }
        }
    }
}

// ---------------- embedding ----------------
__global__ void __launch_bounds__(256) embed_kernel(
    const int* __restrict__ idx, const float* __restrict__ tok,
    const float* __restrict__ pos, float* __restrict__ x)
{
    int row = blockIdx.x;
    int t = row & (T_ - 1);
    int token = idx[row];
    int c = threadIdx.x * 4;
    float4 a = *(const float4*)(tok + (size_t)token * C_ + c);
    float4 p = *(const float4*)(pos + (size_t)t * C_ + c);
    *(float4*)(x + (size_t)row * C_ + c) = make_float4(a.x + p.x, a.y + p.y, a.z + p.z, a.w + p.w);
}

// ---------------- layernorm -> fp16 hi/lo ----------------
__global__ void __launch_bounds__(256) ln_kernel(
    const float* __restrict__ x, const float* __restrict__ g,
    const float* __restrict__ b, __half* __restrict__ yhi, __half* __restrict__ ylo)
{
    __shared__ float red[256];
    int row = blockIdx.x;
    int t = threadIdx.x;
    const float* xr = x + (size_t)row * C_;
    float4 v = *(const float4*)(xr + t * 4);
    red[t] = v.x + v.y + v.z + v.w;
    __syncthreads();
    for (int o = 128; o > 0; o >>= 1) { if (t < o) red[t] += red[t + o]; __syncthreads(); }
    float mean = red[0] * (1.f / C_);
    __syncthreads();
    float dx = v.x - mean, dy = v.y - mean, dz = v.z - mean, dw = v.w - mean;
    red[t] = dx * dx + dy * dy + dz * dz + dw * dw;
    __syncthreads();
    for (int o = 128; o > 0; o >>= 1) { if (t < o) red[t] += red[t + o]; __syncthreads(); }
    float inv = rsqrtf(red[0] * (1.f / C_) + 1e-5f);
    float4 gv = *(const float4*)(g + t * 4);
    float4 bv = *(const float4*)(b + t * 4);
    float o0 = dx * inv * gv.x + bv.x;
    float o1 = dy * inv * gv.y + bv.y;
    float o2 = dz * inv * gv.z + bv.z;
    float o3 = dw * inv * gv.w + bv.w;
    __half h0, l0, h1, l1, h2, l2, h3, l3;
    split_f16(o0, h0, l0); split_f16(o1, h1, l1);
    split_f16(o2, h2, l2); split_f16(o3, h3, l3);
    size_t off = (size_t)row * C_ + t * 4;
    *(__half2*)(yhi + off)     = __halves2half2(h0, h1);
    *(__half2*)(yhi + off + 2) = __halves2half2(h2, h3);
    *(__half2*)(ylo + off)     = __halves2half2(l0, l1);
    *(__half2*)(ylo + off + 2) = __halves2half2(l2, l3);
}

// ---------------- fused flash attention (q,k,v all exact fp16 -> 1-pass MMAs) ----------------
#define FSTAGE 18432   // K 9216 + V 9216
#define FSMEM  (2 * FSTAGE + 9216)  // + Qh
__global__ void __launch_bounds__(128) flash_attn_kernel(
    const __half* __restrict__ qkv,
    __half* __restrict__ atthi, __half* __restrict__ attlo)
{
    extern __shared__ char fsm[];
    const uint32_t sbase = smem_u32(fsm);
    const uint32_t sQ = sbase + 2 * FSTAGE;
    const int qt = blockIdx.x << 6;
    const int bh = blockIdx.y;
    const int b = bh >> 4, h = bh & 15;
    const int tid = threadIdx.x, lane = tid & 31, wid = tid >> 5;
    const int RS = 3 * C_;
    const int g = lane >> 2, tig = lane & 3;
    const int nk = (qt >> 6) + 1;

    // load Q (once)
    #pragma unroll
    for (int j = 0; j < 4; j++) {
        int c = tid + j * 128;
        int row = c >> 3, q8 = c & 7;
        uint32_t d = (uint32_t)(row * 144 + q8 * 16);
        size_t gq = (size_t)(b * T_ + qt + row) * RS + h * HS_ + q8 * 8;
        CP16(sQ + d, qkv + gq);
    }

    auto stage = [&](int it) {
        const uint32_t s0 = sbase + (uint32_t)(it & 1) * FSTAGE;
        const int kt = it << 6;
        #pragma unroll
        for (int j = 0; j < 4; j++) {
            int c = tid + j * 128;
            int row = c >> 3, q8 = c & 7;
            uint32_t d = (uint32_t)(row * 144 + q8 * 16);
            size_t gk = (size_t)(b * T_ + kt + row) * RS + C_ + h * HS_ + q8 * 8;
            size_t gv = (size_t)(b * T_ + kt + row) * RS + 2 * C_ + h * HS_ + q8 * 8;
            CP16(s0 + d, qkv + gk);
            CP16(s0 + 9216 + d, qkv + gv);
        }
    };

    stage(0); CP_COMMIT();

    const uint32_t aoff = (uint32_t)((wid * 16 + (lane & 15)) * 144 + (lane >> 4) * 16);
    const uint32_t koff = (uint32_t)(((lane & 7) + ((lane >> 4) << 3)) * 144 + ((lane >> 3) & 1) * 16);
    const uint32_t voff = (uint32_t)((lane & 15) * 144 + (lane >> 4) * 16);

    float m0 = -INFINITY, m1 = -INFINITY, l0 = 0.f, l1 = 0.f;
    float accO[8][4];
    #pragma unroll
    for (int n = 0; n < 8; n++)
        #pragma unroll
        for (int c = 0; c < 4; c++) accO[n][c] = 0.f;

    uint32_t qhf[4][4];
    bool qloaded = false;

    for (int i = 0; i < nk; i++) {
        if (i + 1 < nk) { stage(i + 1); CP_COMMIT(); CP_WAIT(1); } else { CP_WAIT(0); }
        __syncthreads();
        if (!qloaded) {
            #pragma unroll
            for (int kc = 0; kc < 4; kc++)
                ldm_x4(qhf[kc], sQ + aoff + kc * 32);
            qloaded = true;
        }
        const uint32_t s0 = sbase + (uint32_t)(i & 1) * FSTAGE;

        // ---- scores: 64x64, exact fp16 operands ----
        float acc[8][4];
        #pragma unroll
        for (int n = 0; n < 8; n++)
            #pragma unroll
            for (int c = 0; c < 4; c++) acc[n][c] = 0.f;
        #pragma unroll
        for (int kc = 0; kc < 4; kc++) {
            uint32_t bb[8][2];
            #pragma unroll
            for (int p = 0; p < 4; p++) {
                uint32_t r[4];
                ldm_x4(r, s0 + koff + (uint32_t)(p * 16 * 144) + kc * 32);
                bb[2 * p][0] = r[0]; bb[2 * p][1] = r[1];
                bb[2 * p + 1][0] = r[2]; bb[2 * p + 1][1] = r[3];
            }
            #pragma unroll
            for (int nf = 0; nf < 8; nf++) mma_f16(acc[nf], qhf[kc], bb[nf]);
        }

        // ---- mask + scale ----
        const bool diag = (i == nk - 1);
        const int lr0 = wid * 16 + g, lr1 = lr0 + 8;
        #pragma unroll
        for (int nf = 0; nf < 8; nf++) {
            int c0 = nf * 8 + 2 * tig;
            acc[nf][0] = (diag && (c0     > lr0)) ? -INFINITY : acc[nf][0] * 0.125f;
            acc[nf][1] = (diag && (c0 + 1 > lr0)) ? -INFINITY : acc[nf][1] * 0.125f;
            acc[nf][2] = (diag && (c0     > lr1)) ? -INFINITY : acc[nf][2] * 0.125f;
            acc[nf][3] = (diag && (c0 + 1 > lr1)) ? -INFINITY : acc[nf][3] * 0.125f;
        }

        // ---- online softmax ----
        float mt0 = -INFINITY, mt1 = -INFINITY;
        #pragma unroll
        for (int nf = 0; nf < 8; nf++) {
            mt0 = fmaxf(mt0, fmaxf(acc[nf][0], acc[nf][1]));
            mt1 = fmaxf(mt1, fmaxf(acc[nf][2], acc[nf][3]));
        }
        mt0 = fmaxf(mt0, __shfl_xor_sync(0xffffffff, mt0, 1));
        mt0 = fmaxf(mt0, __shfl_xor_sync(0xffffffff, mt0, 2));
        mt1 = fmaxf(mt1, __shfl_xor_sync(0xffffffff, mt1, 1));
        mt1 = fmaxf(mt1, __shfl_xor_sync(0xffffffff, mt1, 2));
        float mn0 = fmaxf(m0, mt0), mn1 = fmaxf(m1, mt1);
        float al0 = __expf(m0 - mn0), al1 = __expf(m1 - mn1);
        float sum0 = 0.f, sum1 = 0.f;
        #pragma unroll
        for (int nf = 0; nf < 8; nf++) {
            acc[nf][0] = __expf(acc[nf][0] - mn0);
            acc[nf][1] = __expf(acc[nf][1] - mn0);
            acc[nf][2] = __expf(acc[nf][2] - mn1);
            acc[nf][3] = __expf(acc[nf][3] - mn1);
            sum0 += acc[nf][0] + acc[nf][1];
            sum1 += acc[nf][2] + acc[nf][3];
        }
        sum0 += __shfl_xor_sync(0xffffffff, sum0, 1);
        sum0 += __shfl_xor_sync(0xffffffff, sum0, 2);
        sum1 += __shfl_xor_sync(0xffffffff, sum1, 1);
        sum1 += __shfl_xor_sync(0xffffffff, sum1, 2);
        l0 = l0 * al0 + sum0;
        l1 = l1 * al1 + sum1;
        m0 = mn0; m1 = mn1;
        #pragma unroll
        for (int nf = 0; nf < 8; nf++) {
            accO[nf][0] *= al0; accO[nf][1] *= al0;
            accO[nf][2] *= al1; accO[nf][3] *= al1;
        }

        // ---- AV: wei(fp16, in-register) @ V (fp16-exact, 1-pass) ----
        #pragma unroll
        for (int kc = 0; kc < 4; kc++) {
            uint32_t aw[4];
            aw[0] = packh2(acc[2 * kc][0],     acc[2 * kc][1]);
            aw[1] = packh2(acc[2 * kc][2],     acc[2 * kc][3]);
            aw[2] = packh2(acc[2 * kc + 1][0], acc[2 * kc + 1][1]);
            aw[3] = packh2(acc[2 * kc + 1][2], acc[2 * kc + 1][3]);
            #pragma unroll
            for (int db = 0; db < 4; db++) {
                uint32_t rh[4];
                uint32_t vaddr = s0 + 9216 + voff + (uint32_t)(kc * 16 * 144) + db * 32;
                ldm_x4_t(rh, vaddr);
                mma_f16(accO[2 * db],     aw, rh);
                mma_f16(accO[2 * db + 1], aw, rh + 2);
            }
        }
        __syncthreads();
    }

    // ---- epilogue: O / l -> att hi/lo ----
    float il0 = 1.f / l0, il1 = 1.f / l1;
    #pragma unroll
    for (int nf = 0; nf < 8; nf++) {
        int col = h * HS_ + nf * 8 + 2 * tig;
        int row0 = qt + wid * 16 + g;
        float c0 = accO[nf][0] * il0, c1 = accO[nf][1] * il0;
        float c2 = accO[nf][2] * il1, c3 = accO[nf][3] * il1;
        __half h0, lo0, h1, lo1, h2, lo2, h3, lo3;
        split_f16(c0, h0, lo0); split_f16(c1, h1, lo1);
        split_f16(c2, h2, lo2); split_f16(c3, h3, lo3);
        size_t off0 = (size_t)(b * T_ + row0) * C_ + col;
        size_t off1 = (size_t)(b * T_ + row0 + 8) * C_ + col;
        *(__half2*)(atthi + off0) = __halves2half2(h0, h1);
        *(__half2*)(attlo + off0) = __halves2half2(lo0, lo1);
        *(__half2*)(atthi + off1) = __halves2half2(h2, h3);
        *(__half2*)(attlo + off1) = __halves2half2(lo2, lo3);
    }
}

// ---------------- loss ----------------
__global__ void zero_acc_kernel(float* acc) { *acc = 0.f; }

__global__ void __launch_bounds__(256) loss_kernel(
    const float* __restrict__ logits, const int* __restrict__ targets, float* __restrict__ acc)
{
    __shared__ float red[256];
    int row = blockIdx.x;
    const float* lr = logits + (size_t)row * V_;
    int t = threadIdx.x;
    float mx = -INFINITY;
    for (int c = t; c < V_; c += 256) mx = fmaxf(mx, lr[c]);
    red[t] = mx; __syncthreads();
    for (int o = 128; o > 0; o >>= 1) { if (t < o) red[t] = fmaxf(red[t], red[t + o]); __syncthreads(); }
    float Mx = red[0]; __syncthreads();
    float s = 0.f;
    for (int c = t; c < V_; c += 256) s += __expf(lr[c] - Mx);
    red[t] = s; __syncthreads();
    for (int o = 128; o > 0; o >>= 1) { if (t < o) red[t] += red[t + o]; __syncthreads(); }
    if (t == 0) {
        float lse = logf(red[0]) + Mx;
        int tgt = targets[row];
        atomicAdd(acc, (lse - lr[tgt]) * (1.f / M_));
    }
}

__global__ void write_loss_kernel(const float* acc, float* out) { out[0] = *acc; }

// ---------------- launch ----------------
extern "C" void kernel_launch(void* const* d_in, const int* in_sizes, int n_in,
                              void* d_out, int out_size)
{
    const int*   idx   = (const int*)d_in[0];
    const int*   tgt   = (const int*)d_in[1];
    const float* tok   = (const float*)d_in[2];
    const float* pos   = (const float*)d_in[3];
    const float* ln1g  = (const float*)d_in[4];
    const float* ln1b  = (const float*)d_in[5];
    const float* Wq    = (const float*)d_in[6];
    const float* Wk    = (const float*)d_in[7];
    const float* Wv    = (const float*)d_in[8];
    const float* Wo    = (const float*)d_in[9];
    const float* bo    = (const float*)d_in[10];
    const float* ln2g  = (const float*)d_in[11];
    const float* ln2b  = (const float*)d_in[12];
    const float* W1    = (const float*)d_in[13];
    const float* b1    = (const float*)d_in[14];
    const float* W2    = (const float*)d_in[15];
    const float* b2    = (const float*)d_in[16];
    const float* lnfg  = (const float*)d_in[17];
    const float* lnfb  = (const float*)d_in[18];
    const float* Wlm   = (const float*)d_in[19];
    const float* blm   = (const float*)d_in[20];

    float *xb, *accp;
    __half *qk, *hh, *hl, *ah, *al, *mh, *ml, *wt;
    cudaGetSymbolAddress((void**)&xb, g_x);
    cudaGetSymbolAddress((void**)&accp, g_loss_acc);
    cudaGetSymbolAddress((void**)&qk, g_qkv);
    cudaGetSymbolAddress((void**)&hh, g_h_hi);
    cudaGetSymbolAddress((void**)&hl, g_h_lo);
    cudaGetSymbolAddress((void**)&ah, g_att_hi);
    cudaGetSymbolAddress((void**)&al, g_att_lo);
    cudaGetSymbolAddress((void**)&mh, g_mlp_hi);
    cudaGetSymbolAddress((void**)&ml, g_mlp_lo);
    cudaGetSymbolAddress((void**)&wt, g_wT);

    cudaFuncSetAttribute(gemm_mma_kernel, cudaFuncAttributeMaxDynamicSharedMemorySize, GSMEM);
    cudaFuncSetAttribute(flash_attn_kernel, cudaFuncAttributeMaxDynamicSharedMemorySize, FSMEM);

    embed_kernel<<<M_, 256>>>(idx, tok, pos, xb);

    dim3 gC(C_ / 128, M_ / 128);
    dim3 gQKV(3 * C_ / 128, M_ / 128);
    dim3 gF(4 * C_ / 128, M_ / 128);
    dim3 gFlash(T_ / 64, B_ * H_);
    dim3 cv3(C_ / 32, C_ / 32, 3);
    dim3 cvC(C_ / 32, C_ / 32);
    dim3 cv1(4 * C_ / 32, C_ / 32);
    dim3 cv2(C_ / 32, 4 * C_ / 32);
    dim3 cvLM(V_ / 32, C_ / 32);

    for (int l = 0; l < L_; l++) {
        ln_kernel<<<M_, 256>>>(xb, ln1g + (size_t)l * C_, ln1b + (size_t)l * C_, hh, hl);

        convw3_kernel<<<cv3, 256>>>(Wq + (size_t)l * C_ * C_, Wk + (size_t)l * C_ * C_,
                                    Wv + (size_t)l * C_ * C_, wt);
        // QKV: 1-pass (A = fp16-rounded LN out), output plain fp16 q/k/v
        gemm_mma_kernel<<<gQKV, 256, GSMEM>>>(hh, nullptr, wt, nullptr, nullptr, nullptr, qk, nullptr, M_, 3 * C_, C_, 0);

        flash_attn_kernel<<<gFlash, 128, FSMEM>>>(qk, ah, al);

        convw_kernel<<<cvC, 256>>>(Wo + (size_t)l * C_ * C_, wt, C_, C_);
        gemm_mma_kernel<<<gC, 256, GSMEM>>>(ah, al, wt, bo + (size_t)l * C_, xb, xb, nullptr, nullptr, M_, C_, C_, 0);

        ln_kernel<<<M_, 256>>>(xb, ln2g + (size_t)l * C_, ln2b + (size_t)l * C_, hh, hl);

        convw_kernel<<<cv1, 256>>>(W1 + (size_t)l * C_ * 4 * C_, wt, C_, 4 * C_);
        gemm_mma_kernel<<<gF, 256, GSMEM>>>(hh, hl, wt, b1 + (size_t)l * 4 * C_, nullptr, nullptr, mh, ml, M_, 4 * C_, C_, 1);
        convw_kernel<<<cv2, 256>>>(W2 + (size_t)l * 4 * C_ * C_, wt, 4 * C_, C_);
        gemm_mma_kernel<<<gC, 256, GSMEM>>>(mh, ml, wt, b2 + (size_t)l * C_, xb, xb, nullptr, nullptr, M_, C_, 4 * C_, 0);
    }

    ln_kernel<<<M_, 256>>>(xb, lnfg, lnfb, hh, hl);

    float* out = (float*)d_out;
    convw_kernel<<<cvLM, 256>>>(Wlm, wt, C_, V_);
    dim3 gLM(V_ / 128, M_ / 128);
    gemm_mma_kernel<<<gLM, 256, GSMEM>>>(hh, nullptr, wt, blm, nullptr, out, nullptr, nullptr, M_, V_, C_, 0);

    if ((size_t)out_size > NLOGITS) {
        zero_acc_kernel<<<1, 1>>>(accp);
        loss_kernel<<<M_, 256>>>(out, tgt, accp);
        write_loss_kernel<<<1, 1>>>(accp, out + NLOGITS);
    }
}

// round 10
// speedup vs baseline: 2.2482x; 1.2021x over previous
#include <cuda_runtime.h>
#include <cuda_fp16.h>
#include <math.h>
#include <stdint.h>

#define B_ 4
#define T_ 1024
#define C_ 1024
#define H_ 16
#define HS_ 64
#define L_ 12
#define V_ 50304
#define M_ 4096  // B*T

static const size_t NLOGITS = (size_t)M_ * V_;

// ---------------- scratch (device globals; no allocs allowed) ----------------
__device__ float g_x[(size_t)M_ * C_];
__device__ float g_loss_acc;

__device__ __half g_qkv[(size_t)M_ * 3 * C_];     // fp16 q,k,v (exact fp16)
__device__ __half g_h_hi[(size_t)M_ * C_];
__device__ __half g_h_lo[(size_t)M_ * C_];
__device__ __half g_att_hi[(size_t)M_ * C_];
__device__ __half g_att_lo[(size_t)M_ * C_];
__device__ __half g_mlp_hi[(size_t)M_ * 4 * C_];
__device__ __half g_mlp_lo[(size_t)M_ * 4 * C_];
__device__ __half g_wT[(size_t)V_ * C_];

// ---------------- helpers ----------------
__device__ __forceinline__ uint32_t smem_u32(const void* p) {
    uint32_t a;
    asm("{ .reg .u64 t; cvta.to.shared.u64 t, %1; cvt.u32.u64 %0, t; }" : "=r"(a) : "l"(p));
    return a;
}
#define CP16(dst, src) asm volatile("cp.async.cg.shared.global [%0], [%1], 16;" :: "r"(dst), "l"(src) : "memory")
#define CP_COMMIT() asm volatile("cp.async.commit_group;" ::: "memory")
#define CP_WAIT(n)  asm volatile("cp.async.wait_group %0;" :: "n"(n) : "memory")

__device__ __forceinline__ void split_f16(float x, __half& h, __half& l) {
    h = __float2half_rn(x);
    l = __float2half_rn(x - __half2float(h));
}
__device__ __forceinline__ uint32_t packh2(float x, float y) {
    __half2 t = __halves2half2(__float2half_rn(x), __float2half_rn(y));
    return *(uint32_t*)&t;
}

__device__ __forceinline__ void mma_f16(float* c, const uint32_t* a, const uint32_t* b) {
    asm volatile(
        "mma.sync.aligned.m16n8k16.row.col.f32.f16.f16.f32 "
        "{%0,%1,%2,%3}, {%4,%5,%6,%7}, {%8,%9}, {%0,%1,%2,%3};"
        : "+f"(c[0]), "+f"(c[1]), "+f"(c[2]), "+f"(c[3])
        : "r"(a[0]), "r"(a[1]), "r"(a[2]), "r"(a[3]), "r"(b[0]), "r"(b[1]));
}

__device__ __forceinline__ void ldm_x4(uint32_t* r, uint32_t addr) {
    asm volatile("ldmatrix.sync.aligned.m8n8.x4.shared.b16 {%0,%1,%2,%3}, [%4];"
        : "=r"(r[0]), "=r"(r[1]), "=r"(r[2]), "=r"(r[3]) : "r"(addr));
}
__device__ __forceinline__ void ldm_x4_t(uint32_t* r, uint32_t addr) {
    asm volatile("ldmatrix.sync.aligned.m8n8.x4.trans.shared.b16 {%0,%1,%2,%3}, [%4];"
        : "=r"(r[0]), "=r"(r[1]), "=r"(r[2]), "=r"(r[3]) : "r"(addr));
}

// ---------------- weight convert + transpose: W[K][N] -> wT[N][K] fp16 ----------------
__global__ void __launch_bounds__(256) convw_kernel(
    const float* __restrict__ W, __half* __restrict__ wT, int K, int N)
{
    __shared__ float tile[32][33];
    int nt = blockIdx.x * 32, kt = blockIdx.y * 32;
    int tx = threadIdx.x & 31, ty = threadIdx.x >> 5;
    #pragma unroll
    for (int j = 0; j < 4; j++) {
        int kk = ty + j * 8;
        tile[kk][tx] = W[(size_t)(kt + kk) * N + nt + tx];
    }
    __syncthreads();
    #pragma unroll
    for (int j = 0; j < 4; j++) {
        int nn = ty + j * 8;
        wT[(size_t)(nt + nn) * K + kt + tx] = __float2half_rn(tile[tx][nn]);
    }
}

// fused QKV weight convert: z selects Wq/Wk/Wv (all C x C)
__global__ void __launch_bounds__(256) convw3_kernel(
    const float* __restrict__ Wq, const float* __restrict__ Wk,
    const float* __restrict__ Wv, __half* __restrict__ wT)
{
    __shared__ float tile[32][33];
    int z = blockIdx.z;
    const float* W = (z == 0) ? Wq : (z == 1) ? Wk : Wv;
    __half* out = wT + (size_t)z * C_ * C_;
    int nt = blockIdx.x * 32, kt = blockIdx.y * 32;
    int tx = threadIdx.x & 31, ty = threadIdx.x >> 5;
    #pragma unroll
    for (int j = 0; j < 4; j++) {
        int kk = ty + j * 8;
        tile[kk][tx] = W[(size_t)(kt + kk) * C_ + nt + tx];
    }
    __syncthreads();
    #pragma unroll
    for (int j = 0; j < 4; j++) {
        int nn = ty + j * 8;
        out[(size_t)(nt + nn) * C_ + kt + tx] = __float2half_rn(tile[tx][nn]);
    }
}

// ---------------- fp16 GEMM via mma.sync + ldmatrix (1- or 2-pass), 2 CTAs/SM ----------------
#define GSTAGE 30720
#define GSMEM  (3 * GSTAGE)
__global__ void __launch_bounds__(256, 2) gemm_mma_kernel(
    const __half* __restrict__ Ahi, const __half* __restrict__ Alo,
    const __half* __restrict__ Bw,
    const float* __restrict__ bias, const float* __restrict__ res,
    float* __restrict__ Cout, __half* __restrict__ Ohi, __half* __restrict__ Olo,
    int M, int N, int K, int relu)
{
    extern __shared__ char sm[];
    const uint32_t sbase = smem_u32(sm);
    const int tid = threadIdx.x;
    const int lane = tid & 31, wid = tid >> 5;
    const int wm = wid >> 2, wn = wid & 3;
    const int g = lane >> 2, tig = lane & 3;
    const int bm = blockIdx.y << 7, bn = blockIdx.x << 7;
    const bool twopass = (Alo != nullptr);

    const uint32_t aoff = (uint32_t)((wm * 64 + (lane & 15)) * 80 + (lane >> 4) * 16);
    const uint32_t boff = (uint32_t)((wn * 32 + (lane & 7) + ((lane >> 4) << 3)) * 80 + ((lane >> 3) & 1) * 16);

    float acc[4][4][4];
    #pragma unroll
    for (int a = 0; a < 4; a++)
        #pragma unroll
        for (int b = 0; b < 4; b++)
            #pragma unroll
            for (int c = 0; c < 4; c++) acc[a][b][c] = 0.f;

    const int nIter = K >> 5;

    auto stage = [&](int it) {
        const uint32_t s0 = sbase + (uint32_t)(it % 3) * GSTAGE;
        const int k0 = it << 5;
        #pragma unroll
        for (int j = 0; j < 2; j++) {
            int c = tid + j * 256;
            int row = c >> 2, q = c & 3;
            uint32_t d = (uint32_t)(row * 80 + q * 16);
            size_t ga = (size_t)(bm + row) * K + k0 + q * 8;
            size_t gb = (size_t)(bn + row) * K + k0 + q * 8;
            CP16(s0 + d, Ahi + ga);
            if (twopass) CP16(s0 + 10240 + d, Alo + ga);
            CP16(s0 + 20480 + d, Bw + gb);
        }
    };

    stage(0); CP_COMMIT();
    if (nIter > 1) { stage(1); CP_COMMIT(); }

    for (int i = 0; i < nIter; i++) {
        if (i + 1 < nIter) { CP_WAIT(1); } else { CP_WAIT(0); }
        __syncthreads();
        if (i + 2 < nIter) { stage(i + 2); CP_COMMIT(); }

        const uint32_t s0 = sbase + (uint32_t)(i % 3) * GSTAGE;
        #pragma unroll
        for (int ks = 0; ks < 2; ks++) {
            const uint32_t kofs = (uint32_t)(ks * 32);
            uint32_t ah[4][4], al[4][4], bh[4][2];
            #pragma unroll
            for (int mf = 0; mf < 4; mf++) {
                uint32_t ad = s0 + aoff + (uint32_t)(mf * 16 * 80) + kofs;
                ldm_x4(ah[mf], ad);
                if (twopass) ldm_x4(al[mf], ad + 10240);
            }
            #pragma unroll
            for (int p = 0; p < 2; p++) {
                uint32_t bd = s0 + 20480 + boff + (uint32_t)(p * 16 * 80) + kofs;
                uint32_t r[4];
                ldm_x4(r, bd);
                bh[2 * p][0] = r[0]; bh[2 * p][1] = r[1];
                bh[2 * p + 1][0] = r[2]; bh[2 * p + 1][1] = r[3];
            }
            #pragma unroll
            for (int mf = 0; mf < 4; mf++)
                #pragma unroll
                for (int nf = 0; nf < 4; nf++)
                    mma_f16(acc[mf][nf], ah[mf], bh[nf]);
            if (twopass) {
                #pragma unroll
                for (int mf = 0; mf < 4; mf++)
                    #pragma unroll
                    for (int nf = 0; nf < 4; nf++)
                        mma_f16(acc[mf][nf], al[mf], bh[nf]);
            }
        }
    }

    #pragma unroll
    for (int nf = 0; nf < 4; nf++) {
        int col = bn + wn * 32 + nf * 8 + 2 * tig;
        float2 bz = make_float2(0.f, 0.f);
        if (bias) bz = *(const float2*)(bias + col);
        #pragma unroll
        for (int mf = 0; mf < 4; mf++) {
            int row0 = bm + wm * 64 + mf * 16 + g;
            int row1 = row0 + 8;
            float c0 = acc[mf][nf][0] + bz.x;
            float c1 = acc[mf][nf][1] + bz.y;
            float c2 = acc[mf][nf][2] + bz.x;
            float c3 = acc[mf][nf][3] + bz.y;
            if (res) {
                float2 r0 = *(const float2*)(res + (size_t)row0 * N + col);
                float2 r1 = *(const float2*)(res + (size_t)row1 * N + col);
                c0 += r0.x; c1 += r0.y; c2 += r1.x; c3 += r1.y;
            }
            if (relu) {
                c0 = fmaxf(c0, 0.f); c1 = fmaxf(c1, 0.f);
                c2 = fmaxf(c2, 0.f); c3 = fmaxf(c3, 0.f);
            }
            if (Cout) {
                *(float2*)(Cout + (size_t)row0 * N + col) = make_float2(c0, c1);
                *(float2*)(Cout + (size_t)row1 * N + col) = make_float2(c2, c3);
            }
            if (Ohi) {
                if (Olo) {
                    __half h0, l0, h1, l1, h2, l2, h3, l3;
                    split_f16(c0, h0, l0); split_f16(c1, h1, l1);
                    split_f16(c2, h2, l2); split_f16(c3, h3, l3);
                    *(__half2*)(Ohi + (size_t)row0 * N + col) = __halves2half2(h0, h1);
                    *(__half2*)(Olo + (size_t)row0 * N + col) = __halves2half2(l0, l1);
                    *(__half2*)(Ohi + (size_t)row1 * N + col) = __halves2half2(h2, h3);
                    *(__half2*)(Olo + (size_t)row1 * N + col) = __halves2half2(l2, l3);
                } else {
                    *(uint32_t*)(Ohi + (size_t)row0 * N + col) = packh2(c0, c1);
                    *(uint32_t*)(Ohi + (size_t)row1 * N + col) = packh2(c2, c3);
                }
            }
        }
    }
}

// ---------------- embedding ----------------
__global__ void __launch_bounds__(256) embed_kernel(
    const int* __restrict__ idx, const float* __restrict__ tok,
    const float* __restrict__ pos, float* __restrict__ x)
{
    int row = blockIdx.x;
    int t = row & (T_ - 1);
    int token = idx[row];
    int c = threadIdx.x * 4;
    float4 a = *(const float4*)(tok + (size_t)token * C_ + c);
    float4 p = *(const float4*)(pos + (size_t)t * C_ + c);
    *(float4*)(x + (size_t)row * C_ + c) = make_float4(a.x + p.x, a.y + p.y, a.z + p.z, a.w + p.w);
}

// ---------------- layernorm -> fp16 hi/lo ----------------
__global__ void __launch_bounds__(256) ln_kernel(
    const float* __restrict__ x, const float* __restrict__ g,
    const float* __restrict__ b, __half* __restrict__ yhi, __half* __restrict__ ylo)
{
    __shared__ float red[256];
    int row = blockIdx.x;
    int t = threadIdx.x;
    const float* xr = x + (size_t)row * C_;
    float4 v = *(const float4*)(xr + t * 4);
    red[t] = v.x + v.y + v.z + v.w;
    __syncthreads();
    for (int o = 128; o > 0; o >>= 1) { if (t < o) red[t] += red[t + o]; __syncthreads(); }
    float mean = red[0] * (1.f / C_);
    __syncthreads();
    float dx = v.x - mean, dy = v.y - mean, dz = v.z - mean, dw = v.w - mean;
    red[t] = dx * dx + dy * dy + dz * dz + dw * dw;
    __syncthreads();
    for (int o = 128; o > 0; o >>= 1) { if (t < o) red[t] += red[t + o]; __syncthreads(); }
    float inv = rsqrtf(red[0] * (1.f / C_) + 1e-5f);
    float4 gv = *(const float4*)(g + t * 4);
    float4 bv = *(const float4*)(b + t * 4);
    float o0 = dx * inv * gv.x + bv.x;
    float o1 = dy * inv * gv.y + bv.y;
    float o2 = dz * inv * gv.z + bv.z;
    float o3 = dw * inv * gv.w + bv.w;
    __half h0, l0, h1, l1, h2, l2, h3, l3;
    split_f16(o0, h0, l0); split_f16(o1, h1, l1);
    split_f16(o2, h2, l2); split_f16(o3, h3, l3);
    size_t off = (size_t)row * C_ + t * 4;
    *(__half2*)(yhi + off)     = __halves2half2(h0, h1);
    *(__half2*)(yhi + off + 2) = __halves2half2(h2, h3);
    *(__half2*)(ylo + off)     = __halves2half2(l0, l1);
    *(__half2*)(ylo + off + 2) = __halves2half2(l2, l3);
}

// ---------------- fused flash attention (q,k,v all exact fp16 -> 1-pass MMAs) ----------------
#define FSTAGE 18432   // K 9216 + V 9216
#define FSMEM  (2 * FSTAGE + 9216)  // + Qh
__global__ void __launch_bounds__(128) flash_attn_kernel(
    const __half* __restrict__ qkv,
    __half* __restrict__ atthi, __half* __restrict__ attlo)
{
    extern __shared__ char fsm[];
    const uint32_t sbase = smem_u32(fsm);
    const uint32_t sQ = sbase + 2 * FSTAGE;
    const int qt = blockIdx.x << 6;
    const int bh = blockIdx.y;
    const int b = bh >> 4, h = bh & 15;
    const int tid = threadIdx.x, lane = tid & 31, wid = tid >> 5;
    const int RS = 3 * C_;
    const int g = lane >> 2, tig = lane & 3;
    const int nk = (qt >> 6) + 1;

    // load Q (once)
    #pragma unroll
    for (int j = 0; j < 4; j++) {
        int c = tid + j * 128;
        int row = c >> 3, q8 = c & 7;
        uint32_t d = (uint32_t)(row * 144 + q8 * 16);
        size_t gq = (size_t)(b * T_ + qt + row) * RS + h * HS_ + q8 * 8;
        CP16(sQ + d, qkv + gq);
    }

    auto stage = [&](int it) {
        const uint32_t s0 = sbase + (uint32_t)(it & 1) * FSTAGE;
        const int kt = it << 6;
        #pragma unroll
        for (int j = 0; j < 4; j++) {
            int c = tid + j * 128;
            int row = c >> 3, q8 = c & 7;
            uint32_t d = (uint32_t)(row * 144 + q8 * 16);
            size_t gk = (size_t)(b * T_ + kt + row) * RS + C_ + h * HS_ + q8 * 8;
            size_t gv = (size_t)(b * T_ + kt + row) * RS + 2 * C_ + h * HS_ + q8 * 8;
            CP16(s0 + d, qkv + gk);
            CP16(s0 + 9216 + d, qkv + gv);
        }
    };

    stage(0); CP_COMMIT();

    const uint32_t aoff = (uint32_t)((wid * 16 + (lane & 15)) * 144 + (lane >> 4) * 16);
    const uint32_t koff = (uint32_t)(((lane & 7) + ((lane >> 4) << 3)) * 144 + ((lane >> 3) & 1) * 16);
    const uint32_t voff = (uint32_t)((lane & 15) * 144 + (lane >> 4) * 16);

    float m0 = -INFINITY, m1 = -INFINITY, l0 = 0.f, l1 = 0.f;
    float accO[8][4];
    #pragma unroll
    for (int n = 0; n < 8; n++)
        #pragma unroll
        for (int c = 0; c < 4; c++) accO[n][c] = 0.f;

    uint32_t qhf[4][4];
    bool qloaded = false;

    for (int i = 0; i < nk; i++) {
        if (i + 1 < nk) { stage(i + 1); CP_COMMIT(); CP_WAIT(1); } else { CP_WAIT(0); }
        __syncthreads();
        if (!qloaded) {
            #pragma unroll
            for (int kc = 0; kc < 4; kc++)
                ldm_x4(qhf[kc], sQ + aoff + kc * 32);
            qloaded = true;
        }
        const uint32_t s0 = sbase + (uint32_t)(i & 1) * FSTAGE;

        // ---- scores: 64x64, exact fp16 operands ----
        float acc[8][4];
        #pragma unroll
        for (int n = 0; n < 8; n++)
            #pragma unroll
            for (int c = 0; c < 4; c++) acc[n][c] = 0.f;
        #pragma unroll
        for (int kc = 0; kc < 4; kc++) {
            uint32_t bb[8][2];
            #pragma unroll
            for (int p = 0; p < 4; p++) {
                uint32_t r[4];
                ldm_x4(r, s0 + koff + (uint32_t)(p * 16 * 144) + kc * 32);
                bb[2 * p][0] = r[0]; bb[2 * p][1] = r[1];
                bb[2 * p + 1][0] = r[2]; bb[2 * p + 1][1] = r[3];
            }
            #pragma unroll
            for (int nf = 0; nf < 8; nf++) mma_f16(acc[nf], qhf[kc], bb[nf]);
        }

        // ---- mask + scale ----
        const bool diag = (i == nk - 1);
        const int lr0 = wid * 16 + g, lr1 = lr0 + 8;
        #pragma unroll
        for (int nf = 0; nf < 8; nf++) {
            int c0 = nf * 8 + 2 * tig;
            acc[nf][0] = (diag && (c0     > lr0)) ? -INFINITY : acc[nf][0] * 0.125f;
            acc[nf][1] = (diag && (c0 + 1 > lr0)) ? -INFINITY : acc[nf][1] * 0.125f;
            acc[nf][2] = (diag && (c0     > lr1)) ? -INFINITY : acc[nf][2] * 0.125f;
            acc[nf][3] = (diag && (c0 + 1 > lr1)) ? -INFINITY : acc[nf][3] * 0.125f;
        }

        // ---- online softmax ----
        float mt0 = -INFINITY, mt1 = -INFINITY;
        #pragma unroll
        for (int nf = 0; nf < 8; nf++) {
            mt0 = fmaxf(mt0, fmaxf(acc[nf][0], acc[nf][1]));
            mt1 = fmaxf(mt1, fmaxf(acc[nf][2], acc[nf][3]));
        }
        mt0 = fmaxf(mt0, __shfl_xor_sync(0xffffffff, mt0, 1));
        mt0 = fmaxf(mt0, __shfl_xor_sync(0xffffffff, mt0, 2));
        mt1 = fmaxf(mt1, __shfl_xor_sync(0xffffffff, mt1, 1));
        mt1 = fmaxf(mt1, __shfl_xor_sync(0xffffffff, mt1, 2));
        float mn0 = fmaxf(m0, mt0), mn1 = fmaxf(m1, mt1);
        float al0 = __expf(m0 - mn0), al1 = __expf(m1 - mn1);
        float sum0 = 0.f, sum1 = 0.f;
        #pragma unroll
        for (int nf = 0; nf < 8; nf++) {
            acc[nf][0] = __expf(acc[nf][0] - mn0);
            acc[nf][1] = __expf(acc[nf][1] - mn0);
            acc[nf][2] = __expf(acc[nf][2] - mn1);
            acc[nf][3] = __expf(acc[nf][3] - mn1);
            sum0 += acc[nf][0] + acc[nf][1];
            sum1 += acc[nf][2] + acc[nf][3];
        }
        sum0 += __shfl_xor_sync(0xffffffff, sum0, 1);
        sum0 += __shfl_xor_sync(0xffffffff, sum0, 2);
        sum1 += __shfl_xor_sync(0xffffffff, sum1, 1);
        sum1 += __shfl_xor_sync(0xffffffff, sum1, 2);
        l0 = l0 * al0 + sum0;
        l1 = l1 * al1 + sum1;
        m0 = mn0; m1 = mn1;
        #pragma unroll
        for (int nf = 0; nf < 8; nf++) {
            accO[nf][0] *= al0; accO[nf][1] *= al0;
            accO[nf][2] *= al1; accO[nf][3] *= al1;
        }

        // ---- AV: wei(fp16, in-register) @ V (fp16-exact, 1-pass) ----
        #pragma unroll
        for (int kc = 0; kc < 4; kc++) {
            uint32_t aw[4];
            aw[0] = packh2(acc[2 * kc][0],     acc[2 * kc][1]);
            aw[1] = packh2(acc[2 * kc][2],     acc[2 * kc][3]);
            aw[2] = packh2(acc[2 * kc + 1][0], acc[2 * kc + 1][1]);
            aw[3] = packh2(acc[2 * kc + 1][2], acc[2 * kc + 1][3]);
            #pragma unroll
            for (int db = 0; db < 4; db++) {
                uint32_t rh[4];
                uint32_t vaddr = s0 + 9216 + voff + (uint32_t)(kc * 16 * 144) + db * 32;
                ldm_x4_t(rh, vaddr);
                mma_f16(accO[2 * db],     aw, rh);
                mma_f16(accO[2 * db + 1], aw, rh + 2);
            }
        }
        __syncthreads();
    }

    // ---- epilogue: O / l -> att hi/lo ----
    float il0 = 1.f / l0, il1 = 1.f / l1;
    #pragma unroll
    for (int nf = 0; nf < 8; nf++) {
        int col = h * HS_ + nf * 8 + 2 * tig;
        int row0 = qt + wid * 16 + g;
        float c0 = accO[nf][0] * il0, c1 = accO[nf][1] * il0;
        float c2 = accO[nf][2] * il1, c3 = accO[nf][3] * il1;
        __half h0, lo0, h1, lo1, h2, lo2, h3, lo3;
        split_f16(c0, h0, lo0); split_f16(c1, h1, lo1);
        split_f16(c2, h2, lo2); split_f16(c3, h3, lo3);
        size_t off0 = (size_t)(b * T_ + row0) * C_ + col;
        size_t off1 = (size_t)(b * T_ + row0 + 8) * C_ + col;
        *(__half2*)(atthi + off0) = __halves2half2(h0, h1);
        *(__half2*)(attlo + off0) = __halves2half2(lo0, lo1);
        *(__half2*)(atthi + off1) = __halves2half2(h2, h3);
        *(__half2*)(attlo + off1) = __halves2half2(lo2, lo3);
    }
}

// ---------------- loss ----------------
__global__ void zero_acc_kernel(float* acc) { *acc = 0.f; }

__global__ void __launch_bounds__(256) loss_kernel(
    const float* __restrict__ logits, const int* __restrict__ targets, float* __restrict__ acc)
{
    __shared__ float red[256];
    int row = blockIdx.x;
    const float* lr = logits + (size_t)row * V_;
    int t = threadIdx.x;
    float mx = -INFINITY;
    for (int c = t; c < V_; c += 256) mx = fmaxf(mx, lr[c]);
    red[t] = mx; __syncthreads();
    for (int o = 128; o > 0; o >>= 1) { if (t < o) red[t] = fmaxf(red[t], red[t + o]); __syncthreads(); }
    float Mx = red[0]; __syncthreads();
    float s = 0.f;
    for (int c = t; c < V_; c += 256) s += __expf(lr[c] - Mx);
    red[t] = s; __syncthreads();
    for (int o = 128; o > 0; o >>= 1) { if (t < o) red[t] += red[t + o]; __syncthreads(); }
    if (t == 0) {
        float lse = logf(red[0]) + Mx;
        int tgt = targets[row];
        atomicAdd(acc, (lse - lr[tgt]) * (1.f / M_));
    }
}

__global__ void write_loss_kernel(const float* acc, float* out) { out[0] = *acc; }

// ---------------- launch ----------------
extern "C" void kernel_launch(void* const* d_in, const int* in_sizes, int n_in,
                              void* d_out, int out_size)
{
    const int*   idx   = (const int*)d_in[0];
    const int*   tgt   = (const int*)d_in[1];
    const float* tok   = (const float*)d_in[2];
    const float* pos   = (const float*)d_in[3];
    const float* ln1g  = (const float*)d_in[4];
    const float* ln1b  = (const float*)d_in[5];
    const float* Wq    = (const float*)d_in[6];
    const float* Wk    = (const float*)d_in[7];
    const float* Wv    = (const float*)d_in[8];
    const float* Wo    = (const float*)d_in[9];
    const float* bo    = (const float*)d_in[10];
    const float* ln2g  = (const float*)d_in[11];
    const float* ln2b  = (const float*)d_in[12];
    const float* W1    = (const float*)d_in[13];
    const float* b1    = (const float*)d_in[14];
    const float* W2    = (const float*)d_in[15];
    const float* b2    = (const float*)d_in[16];
    const float* lnfg  = (const float*)d_in[17];
    const float* lnfb  = (const float*)d_in[18];
    const float* Wlm   = (const float*)d_in[19];
    const float* blm   = (const float*)d_in[20];

    float *xb, *accp;
    __half *qk, *hh, *hl, *ah, *al, *mh, *ml, *wt;
    cudaGetSymbolAddress((void**)&xb, g_x);
    cudaGetSymbolAddress((void**)&accp, g_loss_acc);
    cudaGetSymbolAddress((void**)&qk, g_qkv);
    cudaGetSymbolAddress((void**)&hh, g_h_hi);
    cudaGetSymbolAddress((void**)&hl, g_h_lo);
    cudaGetSymbolAddress((void**)&ah, g_att_hi);
    cudaGetSymbolAddress((void**)&al, g_att_lo);
    cudaGetSymbolAddress((void**)&mh, g_mlp_hi);
    cudaGetSymbolAddress((void**)&ml, g_mlp_lo);
    cudaGetSymbolAddress((void**)&wt, g_wT);

    cudaFuncSetAttribute(gemm_mma_kernel, cudaFuncAttributeMaxDynamicSharedMemorySize, GSMEM);
    cudaFuncSetAttribute(flash_attn_kernel, cudaFuncAttributeMaxDynamicSharedMemorySize, FSMEM);

    embed_kernel<<<M_, 256>>>(idx, tok, pos, xb);

    dim3 gC(C_ / 128, M_ / 128);
    dim3 gQKV(3 * C_ / 128, M_ / 128);
    dim3 gF(4 * C_ / 128, M_ / 128);
    dim3 gFlash(T_ / 64, B_ * H_);
    dim3 cv3(C_ / 32, C_ / 32, 3);
    dim3 cvC(C_ / 32, C_ / 32);
    dim3 cv1(4 * C_ / 32, C_ / 32);
    dim3 cv2(C_ / 32, 4 * C_ / 32);
    dim3 cvLM(V_ / 32, C_ / 32);

    for (int l = 0; l < L_; l++) {
        ln_kernel<<<M_, 256>>>(xb, ln1g + (size_t)l * C_, ln1b + (size_t)l * C_, hh, hl);

        convw3_kernel<<<cv3, 256>>>(Wq + (size_t)l * C_ * C_, Wk + (size_t)l * C_ * C_,
                                    Wv + (size_t)l * C_ * C_, wt);
        gemm_mma_kernel<<<gQKV, 256, GSMEM>>>(hh, nullptr, wt, nullptr, nullptr, nullptr, qk, nullptr, M_, 3 * C_, C_, 0);

        flash_attn_kernel<<<gFlash, 128, FSMEM>>>(qk, ah, al);

        convw_kernel<<<cvC, 256>>>(Wo + (size_t)l * C_ * C_, wt, C_, C_);
        gemm_mma_kernel<<<gC, 256, GSMEM>>>(ah, al, wt, bo + (size_t)l * C_, xb, xb, nullptr, nullptr, M_, C_, C_, 0);

        ln_kernel<<<M_, 256>>>(xb, ln2g + (size_t)l * C_, ln2b + (size_t)l * C_, hh, hl);

        convw_kernel<<<cv1, 256>>>(W1 + (size_t)l * C_ * 4 * C_, wt, C_, 4 * C_);
        gemm_mma_kernel<<<gF, 256, GSMEM>>>(hh, hl, wt, b1 + (size_t)l * 4 * C_, nullptr, nullptr, mh, ml, M_, 4 * C_, C_, 1);
        convw_kernel<<<cv2, 256>>>(W2 + (size_t)l * 4 * C_ * C_, wt, 4 * C_, C_);
        gemm_mma_kernel<<<gC, 256, GSMEM>>>(mh, ml, wt, b2 + (size_t)l * C_, xb, xb, nullptr, nullptr, M_, C_, 4 * C_, 0);
    }

    ln_kernel<<<M_, 256>>>(xb, lnfg, lnfb, hh, hl);

    float* out = (float*)d_out;
    convw_kernel<<<cvLM, 256>>>(Wlm, wt, C_, V_);
    dim3 gLM(V_ / 128, M_ / 128);
    gemm_mma_kernel<<<gLM, 256, GSMEM>>>(hh, nullptr, wt, blm, nullptr, out, nullptr, nullptr, M_, V_, C_, 0);

    if ((size_t)out_size > NLOGITS) {
        zero_acc_kernel<<<1, 1>>>(accp);
        loss_kernel<<<M_, 256>>>(out, tgt, accp);
        write_loss_kernel<<<1, 1>>>(accp, out + NLOGITS);
    }
}

// round 11
// speedup vs baseline: 2.8491x; 1.2673x over previous
#include <cuda_runtime.h>
#include <cuda_fp16.h>
#include <math.h>
#include <stdint.h>

#define B_ 4
#define T_ 1024
#define C_ 1024
#define H_ 16
#define HS_ 64
#define L_ 12
#define V_ 50304
#define M_ 4096  // B*T

static const size_t NLOGITS = (size_t)M_ * V_;

// ---------------- scratch (device globals; no allocs allowed) ----------------
__device__ float g_x[(size_t)M_ * C_];
__device__ float g_loss_acc;

__device__ __half g_qkv[(size_t)M_ * 3 * C_];     // fp16 q,k,v
__device__ __half g_h[(size_t)M_ * C_];           // LN out (fp16)
__device__ __half g_att_hi[(size_t)M_ * C_];
__device__ __half g_att_lo[(size_t)M_ * C_];
__device__ __half g_mlp[(size_t)M_ * 4 * C_];     // ReLU out (fp16)
__device__ __half g_wT[(size_t)V_ * C_];

// ---------------- helpers ----------------
__device__ __forceinline__ uint32_t smem_u32(const void* p) {
    uint32_t a;
    asm("{ .reg .u64 t; cvta.to.shared.u64 t, %1; cvt.u32.u64 %0, t; }" : "=r"(a) : "l"(p));
    return a;
}
#define CP16(dst, src) asm volatile("cp.async.cg.shared.global [%0], [%1], 16;" :: "r"(dst), "l"(src) : "memory")
#define CP_COMMIT() asm volatile("cp.async.commit_group;" ::: "memory")
#define CP_WAIT(n)  asm volatile("cp.async.wait_group %0;" :: "n"(n) : "memory")

__device__ __forceinline__ void split_f16(float x, __half& h, __half& l) {
    h = __float2half_rn(x);
    l = __float2half_rn(x - __half2float(h));
}
__device__ __forceinline__ uint32_t packh2(float x, float y) {
    __half2 t = __halves2half2(__float2half_rn(x), __float2half_rn(y));
    return *(uint32_t*)&t;
}

__device__ __forceinline__ void mma_f16(float* c, const uint32_t* a, const uint32_t* b) {
    asm volatile(
        "mma.sync.aligned.m16n8k16.row.col.f32.f16.f16.f32 "
        "{%0,%1,%2,%3}, {%4,%5,%6,%7}, {%8,%9}, {%0,%1,%2,%3};"
        : "+f"(c[0]), "+f"(c[1]), "+f"(c[2]), "+f"(c[3])
        : "r"(a[0]), "r"(a[1]), "r"(a[2]), "r"(a[3]), "r"(b[0]), "r"(b[1]));
}

__device__ __forceinline__ void ldm_x4(uint32_t* r, uint32_t addr) {
    asm volatile("ldmatrix.sync.aligned.m8n8.x4.shared.b16 {%0,%1,%2,%3}, [%4];"
        : "=r"(r[0]), "=r"(r[1]), "=r"(r[2]), "=r"(r[3]) : "r"(addr));
}
__device__ __forceinline__ void ldm_x4_t(uint32_t* r, uint32_t addr) {
    asm volatile("ldmatrix.sync.aligned.m8n8.x4.trans.shared.b16 {%0,%1,%2,%3}, [%4];"
        : "=r"(r[0]), "=r"(r[1]), "=r"(r[2]), "=r"(r[3]) : "r"(addr));
}

// ---------------- weight convert + transpose: W[K][N] -> wT[N][K] fp16 ----------------
__global__ void __launch_bounds__(256) convw_kernel(
    const float* __restrict__ W, __half* __restrict__ wT, int K, int N)
{
    __shared__ float tile[32][33];
    int nt = blockIdx.x * 32, kt = blockIdx.y * 32;
    int tx = threadIdx.x & 31, ty = threadIdx.x >> 5;
    #pragma unroll
    for (int j = 0; j < 4; j++) {
        int kk = ty + j * 8;
        tile[kk][tx] = W[(size_t)(kt + kk) * N + nt + tx];
    }
    __syncthreads();
    #pragma unroll
    for (int j = 0; j < 4; j++) {
        int nn = ty + j * 8;
        wT[(size_t)(nt + nn) * K + kt + tx] = __float2half_rn(tile[tx][nn]);
    }
}

// fused QKV weight convert: z selects Wq/Wk/Wv (all C x C)
__global__ void __launch_bounds__(256) convw3_kernel(
    const float* __restrict__ Wq, const float* __restrict__ Wk,
    const float* __restrict__ Wv, __half* __restrict__ wT)
{
    __shared__ float tile[32][33];
    int z = blockIdx.z;
    const float* W = (z == 0) ? Wq : (z == 1) ? Wk : Wv;
    __half* out = wT + (size_t)z * C_ * C_;
    int nt = blockIdx.x * 32, kt = blockIdx.y * 32;
    int tx = threadIdx.x & 31, ty = threadIdx.x >> 5;
    #pragma unroll
    for (int j = 0; j < 4; j++) {
        int kk = ty + j * 8;
        tile[kk][tx] = W[(size_t)(kt + kk) * C_ + nt + tx];
    }
    __syncthreads();
    #pragma unroll
    for (int j = 0; j < 4; j++) {
        int nn = ty + j * 8;
        out[(size_t)(nt + nn) * C_ + kt + tx] = __float2half_rn(tile[tx][nn]);
    }
}

// ---------------- fp16 GEMM via mma.sync + ldmatrix (1- or 2-pass), 2 CTAs/SM ----------------
#define GSTAGE 30720
#define GSMEM  (3 * GSTAGE)
__global__ void __launch_bounds__(256, 2) gemm_mma_kernel(
    const __half* __restrict__ Ahi, const __half* __restrict__ Alo,
    const __half* __restrict__ Bw,
    const float* __restrict__ bias, const float* __restrict__ res,
    float* __restrict__ Cout, __half* __restrict__ Ohi, __half* __restrict__ Olo,
    int M, int N, int K, int relu)
{
    extern __shared__ char sm[];
    const uint32_t sbase = smem_u32(sm);
    const int tid = threadIdx.x;
    const int lane = tid & 31, wid = tid >> 5;
    const int wm = wid >> 2, wn = wid & 3;
    const int g = lane >> 2, tig = lane & 3;
    const int bm = blockIdx.y << 7, bn = blockIdx.x << 7;
    const bool twopass = (Alo != nullptr);

    const uint32_t aoff = (uint32_t)((wm * 64 + (lane & 15)) * 80 + (lane >> 4) * 16);
    const uint32_t boff = (uint32_t)((wn * 32 + (lane & 7) + ((lane >> 4) << 3)) * 80 + ((lane >> 3) & 1) * 16);

    float acc[4][4][4];
    #pragma unroll
    for (int a = 0; a < 4; a++)
        #pragma unroll
        for (int b = 0; b < 4; b++)
            #pragma unroll
            for (int c = 0; c < 4; c++) acc[a][b][c] = 0.f;

    const int nIter = K >> 5;

    auto stage = [&](int it) {
        const uint32_t s0 = sbase + (uint32_t)(it % 3) * GSTAGE;
        const int k0 = it << 5;
        #pragma unroll
        for (int j = 0; j < 2; j++) {
            int c = tid + j * 256;
            int row = c >> 2, q = c & 3;
            uint32_t d = (uint32_t)(row * 80 + q * 16);
            size_t ga = (size_t)(bm + row) * K + k0 + q * 8;
            size_t gb = (size_t)(bn + row) * K + k0 + q * 8;
            CP16(s0 + d, Ahi + ga);
            if (twopass) CP16(s0 + 10240 + d, Alo + ga);
            CP16(s0 + 20480 + d, Bw + gb);
        }
    };

    stage(0); CP_COMMIT();
    if (nIter > 1) { stage(1); CP_COMMIT(); }

    for (int i = 0; i < nIter; i++) {
        if (i + 1 < nIter) { CP_WAIT(1); } else { CP_WAIT(0); }
        __syncthreads();
        if (i + 2 < nIter) { stage(i + 2); CP_COMMIT(); }

        const uint32_t s0 = sbase + (uint32_t)(i % 3) * GSTAGE;
        #pragma unroll
        for (int ks = 0; ks < 2; ks++) {
            const uint32_t kofs = (uint32_t)(ks * 32);
            uint32_t ah[4][4], al[4][4], bh[4][2];
            #pragma unroll
            for (int mf = 0; mf < 4; mf++) {
                uint32_t ad = s0 + aoff + (uint32_t)(mf * 16 * 80) + kofs;
                ldm_x4(ah[mf], ad);
                if (twopass) ldm_x4(al[mf], ad + 10240);
            }
            #pragma unroll
            for (int p = 0; p < 2; p++) {
                uint32_t bd = s0 + 20480 + boff + (uint32_t)(p * 16 * 80) + kofs;
                uint32_t r[4];
                ldm_x4(r, bd);
                bh[2 * p][0] = r[0]; bh[2 * p][1] = r[1];
                bh[2 * p + 1][0] = r[2]; bh[2 * p + 1][1] = r[3];
            }
            #pragma unroll
            for (int mf = 0; mf < 4; mf++)
                #pragma unroll
                for (int nf = 0; nf < 4; nf++)
                    mma_f16(acc[mf][nf], ah[mf], bh[nf]);
            if (twopass) {
                #pragma unroll
                for (int mf = 0; mf < 4; mf++)
                    #pragma unroll
                    for (int nf = 0; nf < 4; nf++)
                        mma_f16(acc[mf][nf], al[mf], bh[nf]);
            }
        }
    }

    #pragma unroll
    for (int nf = 0; nf < 4; nf++) {
        int col = bn + wn * 32 + nf * 8 + 2 * tig;
        float2 bz = make_float2(0.f, 0.f);
        if (bias) bz = *(const float2*)(bias + col);
        #pragma unroll
        for (int mf = 0; mf < 4; mf++) {
            int row0 = bm + wm * 64 + mf * 16 + g;
            int row1 = row0 + 8;
            float c0 = acc[mf][nf][0] + bz.x;
            float c1 = acc[mf][nf][1] + bz.y;
            float c2 = acc[mf][nf][2] + bz.x;
            float c3 = acc[mf][nf][3] + bz.y;
            if (res) {
                float2 r0 = *(const float2*)(res + (size_t)row0 * N + col);
                float2 r1 = *(const float2*)(res + (size_t)row1 * N + col);
                c0 += r0.x; c1 += r0.y; c2 += r1.x; c3 += r1.y;
            }
            if (relu) {
                c0 = fmaxf(c0, 0.f); c1 = fmaxf(c1, 0.f);
                c2 = fmaxf(c2, 0.f); c3 = fmaxf(c3, 0.f);
            }
            if (Cout) {
                *(float2*)(Cout + (size_t)row0 * N + col) = make_float2(c0, c1);
                *(float2*)(Cout + (size_t)row1 * N + col) = make_float2(c2, c3);
            }
            if (Ohi) {
                if (Olo) {
                    __half h0, l0, h1, l1, h2, l2, h3, l3;
                    split_f16(c0, h0, l0); split_f16(c1, h1, l1);
                    split_f16(c2, h2, l2); split_f16(c3, h3, l3);
                    *(__half2*)(Ohi + (size_t)row0 * N + col) = __halves2half2(h0, h1);
                    *(__half2*)(Olo + (size_t)row0 * N + col) = __halves2half2(l0, l1);
                    *(__half2*)(Ohi + (size_t)row1 * N + col) = __halves2half2(h2, h3);
                    *(__half2*)(Olo + (size_t)row1 * N + col) = __halves2half2(l2, l3);
                } else {
                    *(uint32_t*)(Ohi + (size_t)row0 * N + col) = packh2(c0, c1);
                    *(uint32_t*)(Ohi + (size_t)row1 * N + col) = packh2(c2, c3);
                }
            }
        }
    }
}

// ---------------- embedding ----------------
__global__ void __launch_bounds__(256) embed_kernel(
    const int* __restrict__ idx, const float* __restrict__ tok,
    const float* __restrict__ pos, float* __restrict__ x)
{
    int row = blockIdx.x;
    int t = row & (T_ - 1);
    int token = idx[row];
    int c = threadIdx.x * 4;
    float4 a = *(const float4*)(tok + (size_t)token * C_ + c);
    float4 p = *(const float4*)(pos + (size_t)t * C_ + c);
    *(float4*)(x + (size_t)row * C_ + c) = make_float4(a.x + p.x, a.y + p.y, a.z + p.z, a.w + p.w);
}

// ---------------- layernorm -> fp16 ----------------
__global__ void __launch_bounds__(256) ln_kernel(
    const float* __restrict__ x, const float* __restrict__ g,
    const float* __restrict__ b, __half* __restrict__ y)
{
    __shared__ float red[256];
    int row = blockIdx.x;
    int t = threadIdx.x;
    const float* xr = x + (size_t)row * C_;
    float4 v = *(const float4*)(xr + t * 4);
    red[t] = v.x + v.y + v.z + v.w;
    __syncthreads();
    for (int o = 128; o > 0; o >>= 1) { if (t < o) red[t] += red[t + o]; __syncthreads(); }
    float mean = red[0] * (1.f / C_);
    __syncthreads();
    float dx = v.x - mean, dy = v.y - mean, dz = v.z - mean, dw = v.w - mean;
    red[t] = dx * dx + dy * dy + dz * dz + dw * dw;
    __syncthreads();
    for (int o = 128; o > 0; o >>= 1) { if (t < o) red[t] += red[t + o]; __syncthreads(); }
    float inv = rsqrtf(red[0] * (1.f / C_) + 1e-5f);
    float4 gv = *(const float4*)(g + t * 4);
    float4 bv = *(const float4*)(b + t * 4);
    float o0 = dx * inv * gv.x + bv.x;
    float o1 = dy * inv * gv.y + bv.y;
    float o2 = dz * inv * gv.z + bv.z;
    float o3 = dw * inv * gv.w + bv.w;
    size_t off = (size_t)row * C_ + t * 4;
    *(uint32_t*)(y + off)     = packh2(o0, o1);
    *(uint32_t*)(y + off + 2) = packh2(o2, o3);
}

// ---------------- fused flash attention (q,k,v all exact fp16 -> 1-pass MMAs) ----------------
#define FSTAGE 18432   // K 9216 + V 9216
#define FSMEM  (2 * FSTAGE + 9216)  // + Qh
__global__ void __launch_bounds__(128) flash_attn_kernel(
    const __half* __restrict__ qkv,
    __half* __restrict__ atthi, __half* __restrict__ attlo)
{
    extern __shared__ char fsm[];
    const uint32_t sbase = smem_u32(fsm);
    const uint32_t sQ = sbase + 2 * FSTAGE;
    const int qt = blockIdx.x << 6;
    const int bh = blockIdx.y;
    const int b = bh >> 4, h = bh & 15;
    const int tid = threadIdx.x, lane = tid & 31, wid = tid >> 5;
    const int RS = 3 * C_;
    const int g = lane >> 2, tig = lane & 3;
    const int nk = (qt >> 6) + 1;

    #pragma unroll
    for (int j = 0; j < 4; j++) {
        int c = tid + j * 128;
        int row = c >> 3, q8 = c & 7;
        uint32_t d = (uint32_t)(row * 144 + q8 * 16);
        size_t gq = (size_t)(b * T_ + qt + row) * RS + h * HS_ + q8 * 8;
        CP16(sQ + d, qkv + gq);
    }

    auto stage = [&](int it) {
        const uint32_t s0 = sbase + (uint32_t)(it & 1) * FSTAGE;
        const int kt = it << 6;
        #pragma unroll
        for (int j = 0; j < 4; j++) {
            int c = tid + j * 128;
            int row = c >> 3, q8 = c & 7;
            uint32_t d = (uint32_t)(row * 144 + q8 * 16);
            size_t gk = (size_t)(b * T_ + kt + row) * RS + C_ + h * HS_ + q8 * 8;
            size_t gv = (size_t)(b * T_ + kt + row) * RS + 2 * C_ + h * HS_ + q8 * 8;
            CP16(s0 + d, qkv + gk);
            CP16(s0 + 9216 + d, qkv + gv);
        }
    };

    stage(0); CP_COMMIT();

    const uint32_t aoff = (uint32_t)((wid * 16 + (lane & 15)) * 144 + (lane >> 4) * 16);
    const uint32_t koff = (uint32_t)(((lane & 7) + ((lane >> 4) << 3)) * 144 + ((lane >> 3) & 1) * 16);
    const uint32_t voff = (uint32_t)((lane & 15) * 144 + (lane >> 4) * 16);

    float m0 = -INFINITY, m1 = -INFINITY, l0 = 0.f, l1 = 0.f;
    float accO[8][4];
    #pragma unroll
    for (int n = 0; n < 8; n++)
        #pragma unroll
        for (int c = 0; c < 4; c++) accO[n][c] = 0.f;

    uint32_t qhf[4][4];
    bool qloaded = false;

    for (int i = 0; i < nk; i++) {
        if (i + 1 < nk) { stage(i + 1); CP_COMMIT(); CP_WAIT(1); } else { CP_WAIT(0); }
        __syncthreads();
        if (!qloaded) {
            #pragma unroll
            for (int kc = 0; kc < 4; kc++)
                ldm_x4(qhf[kc], sQ + aoff + kc * 32);
            qloaded = true;
        }
        const uint32_t s0 = sbase + (uint32_t)(i & 1) * FSTAGE;

        float acc[8][4];
        #pragma unroll
        for (int n = 0; n < 8; n++)
            #pragma unroll
            for (int c = 0; c < 4; c++) acc[n][c] = 0.f;
        #pragma unroll
        for (int kc = 0; kc < 4; kc++) {
            uint32_t bb[8][2];
            #pragma unroll
            for (int p = 0; p < 4; p++) {
                uint32_t r[4];
                ldm_x4(r, s0 + koff + (uint32_t)(p * 16 * 144) + kc * 32);
                bb[2 * p][0] = r[0]; bb[2 * p][1] = r[1];
                bb[2 * p + 1][0] = r[2]; bb[2 * p + 1][1] = r[3];
            }
            #pragma unroll
            for (int nf = 0; nf < 8; nf++) mma_f16(acc[nf], qhf[kc], bb[nf]);
        }

        const bool diag = (i == nk - 1);
        const int lr0 = wid * 16 + g, lr1 = lr0 + 8;
        #pragma unroll
        for (int nf = 0; nf < 8; nf++) {
            int c0 = nf * 8 + 2 * tig;
            acc[nf][0] = (diag && (c0     > lr0)) ? -INFINITY : acc[nf][0] * 0.125f;
            acc[nf][1] = (diag && (c0 + 1 > lr0)) ? -INFINITY : acc[nf][1] * 0.125f;
            acc[nf][2] = (diag && (c0     > lr1)) ? -INFINITY : acc[nf][2] * 0.125f;
            acc[nf][3] = (diag && (c0 + 1 > lr1)) ? -INFINITY : acc[nf][3] * 0.125f;
        }

        float mt0 = -INFINITY, mt1 = -INFINITY;
        #pragma unroll
        for (int nf = 0; nf < 8; nf++) {
            mt0 = fmaxf(mt0, fmaxf(acc[nf][0], acc[nf][1]));
            mt1 = fmaxf(mt1, fmaxf(acc[nf][2], acc[nf][3]));
        }
        mt0 = fmaxf(mt0, __shfl_xor_sync(0xffffffff, mt0, 1));
        mt0 = fmaxf(mt0, __shfl_xor_sync(0xffffffff, mt0, 2));
        mt1 = fmaxf(mt1, __shfl_xor_sync(0xffffffff, mt1, 1));
        mt1 = fmaxf(mt1, __shfl_xor_sync(0xffffffff, mt1, 2));
        float mn0 = fmaxf(m0, mt0), mn1 = fmaxf(m1, mt1);
        float al0 = __expf(m0 - mn0), al1 = __expf(m1 - mn1);
        float sum0 = 0.f, sum1 = 0.f;
        #pragma unroll
        for (int nf = 0; nf < 8; nf++) {
            acc[nf][0] = __expf(acc[nf][0] - mn0);
            acc[nf][1] = __expf(acc[nf][1] - mn0);
            acc[nf][2] = __expf(acc[nf][2] - mn1);
            acc[nf][3] = __expf(acc[nf][3] - mn1);
            sum0 += acc[nf][0] + acc[nf][1];
            sum1 += acc[nf][2] + acc[nf][3];
        }
        sum0 += __shfl_xor_sync(0xffffffff, sum0, 1);
        sum0 += __shfl_xor_sync(0xffffffff, sum0, 2);
        sum1 += __shfl_xor_sync(0xffffffff, sum1, 1);
        sum1 += __shfl_xor_sync(0xffffffff, sum1, 2);
        l0 = l0 * al0 + sum0;
        l1 = l1 * al1 + sum1;
        m0 = mn0; m1 = mn1;
        #pragma unroll
        for (int nf = 0; nf < 8; nf++) {
            accO[nf][0] *= al0; accO[nf][1] *= al0;
            accO[nf][2] *= al1; accO[nf][3] *= al1;
        }

        #pragma unroll
        for (int kc = 0; kc < 4; kc++) {
            uint32_t aw[4];
            aw[0] = packh2(acc[2 * kc][0],     acc[2 * kc][1]);
            aw[1] = packh2(acc[2 * kc][2],     acc[2 * kc][3]);
            aw[2] = packh2(acc[2 * kc + 1][0], acc[2 * kc + 1][1]);
            aw[3] = packh2(acc[2 * kc + 1][2], acc[2 * kc + 1][3]);
            #pragma unroll
            for (int db = 0; db < 4; db++) {
                uint32_t rh[4];
                uint32_t vaddr = s0 + 9216 + voff + (uint32_t)(kc * 16 * 144) + db * 32;
                ldm_x4_t(rh, vaddr);
                mma_f16(accO[2 * db],     aw, rh);
                mma_f16(accO[2 * db + 1], aw, rh + 2);
            }
        }
        __syncthreads();
    }

    float il0 = 1.f / l0, il1 = 1.f / l1;
    #pragma unroll
    for (int nf = 0; nf < 8; nf++) {
        int col = h * HS_ + nf * 8 + 2 * tig;
        int row0 = qt + wid * 16 + g;
        float c0 = accO[nf][0] * il0, c1 = accO[nf][1] * il0;
        float c2 = accO[nf][2] * il1, c3 = accO[nf][3] * il1;
        __half h0, lo0, h1, lo1, h2, lo2, h3, lo3;
        split_f16(c0, h0, lo0); split_f16(c1, h1, lo1);
        split_f16(c2, h2, lo2); split_f16(c3, h3, lo3);
        size_t off0 = (size_t)(b * T_ + row0) * C_ + col;
        size_t off1 = (size_t)(b * T_ + row0 + 8) * C_ + col;
        *(__half2*)(atthi + off0) = __halves2half2(h0, h1);
        *(__half2*)(attlo + off0) = __halves2half2(lo0, lo1);
        *(__half2*)(atthi + off1) = __halves2half2(h2, h3);
        *(__half2*)(attlo + off1) = __halves2half2(lo2, lo3);
    }
}

// ---------------- loss ----------------
__global__ void zero_acc_kernel(float* acc) { *acc = 0.f; }

__global__ void __launch_bounds__(256) loss_kernel(
    const float* __restrict__ logits, const int* __restrict__ targets, float* __restrict__ acc)
{
    __shared__ float red[256];
    int row = blockIdx.x;
    const float* lr = logits + (size_t)row * V_;
    int t = threadIdx.x;
    float mx = -INFINITY;
    for (int c = t; c < V_; c += 256) mx = fmaxf(mx, lr[c]);
    red[t] = mx; __syncthreads();
    for (int o = 128; o > 0; o >>= 1) { if (t < o) red[t] = fmaxf(red[t], red[t + o]); __syncthreads(); }
    float Mx = red[0]; __syncthreads();
    float s = 0.f;
    for (int c = t; c < V_; c += 256) s += __expf(lr[c] - Mx);
    red[t] = s; __syncthreads();
    for (int o = 128; o > 0; o >>= 1) { if (t < o) red[t] += red[t + o]; __syncthreads(); }
    if (t == 0) {
        float lse = logf(red[0]) + Mx;
        int tgt = targets[row];
        atomicAdd(acc, (lse - lr[tgt]) * (1.f / M_));
    }
}

__global__ void write_loss_kernel(const float* acc, float* out) { out[0] = *acc; }

// ---------------- launch ----------------
extern "C" void kernel_launch(void* const* d_in, const int* in_sizes, int n_in,
                              void* d_out, int out_size)
{
    const int*   idx   = (const int*)d_in[0];
    const int*   tgt   = (const int*)d_in[1];
    const float* tok   = (const float*)d_in[2];
    const float* pos   = (const float*)d_in[3];
    const float* ln1g  = (const float*)d_in[4];
    const float* ln1b  = (const float*)d_in[5];
    const float* Wq    = (const float*)d_in[6];
    const float* Wk    = (const float*)d_in[7];
    const float* Wv    = (const float*)d_in[8];
    const float* Wo    = (const float*)d_in[9];
    const float* bo    = (const float*)d_in[10];
    const float* ln2g  = (const float*)d_in[11];
    const float* ln2b  = (const float*)d_in[12];
    const float* W1    = (const float*)d_in[13];
    const float* b1    = (const float*)d_in[14];
    const float* W2    = (const float*)d_in[15];
    const float* b2    = (const float*)d_in[16];
    const float* lnfg  = (const float*)d_in[17];
    const float* lnfb  = (const float*)d_in[18];
    const float* Wlm   = (const float*)d_in[19];
    const float* blm   = (const float*)d_in[20];

    float *xb, *accp;
    __half *qk, *hb, *ah, *al, *mb, *wt;
    cudaGetSymbolAddress((void**)&xb, g_x);
    cudaGetSymbolAddress((void**)&accp, g_loss_acc);
    cudaGetSymbolAddress((void**)&qk, g_qkv);
    cudaGetSymbolAddress((void**)&hb, g_h);
    cudaGetSymbolAddress((void**)&ah, g_att_hi);
    cudaGetSymbolAddress((void**)&al, g_att_lo);
    cudaGetSymbolAddress((void**)&mb, g_mlp);
    cudaGetSymbolAddress((void**)&wt, g_wT);

    cudaFuncSetAttribute(gemm_mma_kernel, cudaFuncAttributeMaxDynamicSharedMemorySize, GSMEM);
    cudaFuncSetAttribute(flash_attn_kernel, cudaFuncAttributeMaxDynamicSharedMemorySize, FSMEM);

    embed_kernel<<<M_, 256>>>(idx, tok, pos, xb);

    dim3 gC(C_ / 128, M_ / 128);
    dim3 gQKV(3 * C_ / 128, M_ / 128);
    dim3 gF(4 * C_ / 128, M_ / 128);
    dim3 gFlash(T_ / 64, B_ * H_);
    dim3 cv3(C_ / 32, C_ / 32, 3);
    dim3 cvC(C_ / 32, C_ / 32);
    dim3 cv1(4 * C_ / 32, C_ / 32);
    dim3 cv2(C_ / 32, 4 * C_ / 32);
    dim3 cvLM(V_ / 32, C_ / 32);

    for (int l = 0; l < L_; l++) {
        ln_kernel<<<M_, 256>>>(xb, ln1g + (size_t)l * C_, ln1b + (size_t)l * C_, hb);

        convw3_kernel<<<cv3, 256>>>(Wq + (size_t)l * C_ * C_, Wk + (size_t)l * C_ * C_,
                                    Wv + (size_t)l * C_ * C_, wt);
        gemm_mma_kernel<<<gQKV, 256, GSMEM>>>(hb, nullptr, wt, nullptr, nullptr, nullptr, qk, nullptr, M_, 3 * C_, C_, 0);

        flash_attn_kernel<<<gFlash, 128, FSMEM>>>(qk, ah, al);

        convw_kernel<<<cvC, 256>>>(Wo + (size_t)l * C_ * C_, wt, C_, C_);
        gemm_mma_kernel<<<gC, 256, GSMEM>>>(ah, al, wt, bo + (size_t)l * C_, xb, xb, nullptr, nullptr, M_, C_, C_, 0);

        ln_kernel<<<M_, 256>>>(xb, ln2g + (size_t)l * C_, ln2b + (size_t)l * C_, hb);

        convw_kernel<<<cv1, 256>>>(W1 + (size_t)l * C_ * 4 * C_, wt, C_, 4 * C_);
        // MLP1: 1-pass, ReLU out -> fp16
        gemm_mma_kernel<<<gF, 256, GSMEM>>>(hb, nullptr, wt, b1 + (size_t)l * 4 * C_, nullptr, nullptr, mb, nullptr, M_, 4 * C_, C_, 1);
        convw_kernel<<<cv2, 256>>>(W2 + (size_t)l * 4 * C_ * C_, wt, 4 * C_, C_);
        // W2: 1-pass
        gemm_mma_kernel<<<gC, 256, GSMEM>>>(mb, nullptr, wt, b2 + (size_t)l * C_, xb, xb, nullptr, nullptr, M_, C_, 4 * C_, 0);
    }

    ln_kernel<<<M_, 256>>>(xb, lnfg, lnfb, hb);

    float* out = (float*)d_out;
    convw_kernel<<<cvLM, 256>>>(Wlm, wt, C_, V_);
    dim3 gLM(V_ / 128, M_ / 128);
    gemm_mma_kernel<<<gLM, 256, GSMEM>>>(hb, nullptr, wt, blm, nullptr, out, nullptr, nullptr, M_, V_, C_, 0);

    if ((size_t)out_size > NLOGITS) {
        zero_acc_kernel<<<1, 1>>>(accp);
        loss_kernel<<<M_, 256>>>(out, tgt, accp);
        write_loss_kernel<<<1, 1>>>(accp, out + NLOGITS);
    }
}

// round 12
// speedup vs baseline: 3.1659x; 1.1112x over previous
#include <cuda_runtime.h>
#include <cuda_fp16.h>
#include <math.h>
#include <stdint.h>

#define B_ 4
#define T_ 1024
#define C_ 1024
#define H_ 16
#define HS_ 64
#define L_ 12
#define V_ 50304
#define M_ 4096  // B*T

static const size_t NLOGITS = (size_t)M_ * V_;

// ---------------- scratch (device globals; no allocs allowed) ----------------
__device__ float g_x[(size_t)M_ * C_];
__device__ float g_loss_acc;

__device__ __half g_qkv[(size_t)M_ * 3 * C_];     // fp16 q,k,v
__device__ __half g_h[(size_t)M_ * C_];           // LN out (fp16)
__device__ __half g_att_hi[(size_t)M_ * C_];
__device__ __half g_att_lo[(size_t)M_ * C_];
__device__ __half g_mlp[(size_t)M_ * 4 * C_];     // ReLU out (fp16)
__device__ __half g_wT[(size_t)V_ * C_];

// ---------------- helpers ----------------
__device__ __forceinline__ uint32_t smem_u32(const void* p) {
    uint32_t a;
    asm("{ .reg .u64 t; cvta.to.shared.u64 t, %1; cvt.u32.u64 %0, t; }" : "=r"(a) : "l"(p));
    return a;
}
#define CP16(dst, src) asm volatile("cp.async.cg.shared.global [%0], [%1], 16;" :: "r"(dst), "l"(src) : "memory")
#define CP_COMMIT() asm volatile("cp.async.commit_group;" ::: "memory")
#define CP_WAIT(n)  asm volatile("cp.async.wait_group %0;" :: "n"(n) : "memory")

__device__ __forceinline__ void split_f16(float x, __half& h, __half& l) {
    h = __float2half_rn(x);
    l = __float2half_rn(x - __half2float(h));
}
__device__ __forceinline__ uint32_t packh2(float x, float y) {
    __half2 t = __halves2half2(__float2half_rn(x), __float2half_rn(y));
    return *(uint32_t*)&t;
}

__device__ __forceinline__ void mma_f16(float* c, const uint32_t* a, const uint32_t* b) {
    asm volatile(
        "mma.sync.aligned.m16n8k16.row.col.f32.f16.f16.f32 "
        "{%0,%1,%2,%3}, {%4,%5,%6,%7}, {%8,%9}, {%0,%1,%2,%3};"
        : "+f"(c[0]), "+f"(c[1]), "+f"(c[2]), "+f"(c[3])
        : "r"(a[0]), "r"(a[1]), "r"(a[2]), "r"(a[3]), "r"(b[0]), "r"(b[1]));
}

__device__ __forceinline__ void ldm_x4(uint32_t* r, uint32_t addr) {
    asm volatile("ldmatrix.sync.aligned.m8n8.x4.shared.b16 {%0,%1,%2,%3}, [%4];"
        : "=r"(r[0]), "=r"(r[1]), "=r"(r[2]), "=r"(r[3]) : "r"(addr));
}
__device__ __forceinline__ void ldm_x4_t(uint32_t* r, uint32_t addr) {
    asm volatile("ldmatrix.sync.aligned.m8n8.x4.trans.shared.b16 {%0,%1,%2,%3}, [%4];"
        : "=r"(r[0]), "=r"(r[1]), "=r"(r[2]), "=r"(r[3]) : "r"(addr));
}

// ---------------- weight convert + transpose: W[K][N] -> wT[N][K] fp16 ----------------
__global__ void __launch_bounds__(256) convw_kernel(
    const float* __restrict__ W, __half* __restrict__ wT, int K, int N)
{
    __shared__ float tile[32][33];
    int nt = blockIdx.x * 32, kt = blockIdx.y * 32;
    int tx = threadIdx.x & 31, ty = threadIdx.x >> 5;
    #pragma unroll
    for (int j = 0; j < 4; j++) {
        int kk = ty + j * 8;
        tile[kk][tx] = W[(size_t)(kt + kk) * N + nt + tx];
    }
    __syncthreads();
    #pragma unroll
    for (int j = 0; j < 4; j++) {
        int nn = ty + j * 8;
        wT[(size_t)(nt + nn) * K + kt + tx] = __float2half_rn(tile[tx][nn]);
    }
}

// fused QKV weight convert: z selects Wq/Wk/Wv (all C x C)
__global__ void __launch_bounds__(256) convw3_kernel(
    const float* __restrict__ Wq, const float* __restrict__ Wk,
    const float* __restrict__ Wv, __half* __restrict__ wT)
{
    __shared__ float tile[32][33];
    int z = blockIdx.z;
    const float* W = (z == 0) ? Wq : (z == 1) ? Wk : Wv;
    __half* out = wT + (size_t)z * C_ * C_;
    int nt = blockIdx.x * 32, kt = blockIdx.y * 32;
    int tx = threadIdx.x & 31, ty = threadIdx.x >> 5;
    #pragma unroll
    for (int j = 0; j < 4; j++) {
        int kk = ty + j * 8;
        tile[kk][tx] = W[(size_t)(kt + kk) * C_ + nt + tx];
    }
    __syncthreads();
    #pragma unroll
    for (int j = 0; j < 4; j++) {
        int nn = ty + j * 8;
        out[(size_t)(nt + nn) * C_ + kt + tx] = __float2half_rn(tile[tx][nn]);
    }
}

// ---------------- fp16 GEMM via mma.sync + ldmatrix (1- or 2-pass) ----------------
// 128 threads, 4 warps (2x2), warp tile 64x64, CTA tile 128x128, BK=32,
// 3-stage cp.async, 2 CTAs/SM.
#define GSTAGE 30720
#define GSMEM  (3 * GSTAGE)
__global__ void __launch_bounds__(128, 2) gemm_mma_kernel(
    const __half* __restrict__ Ahi, const __half* __restrict__ Alo,
    const __half* __restrict__ Bw,
    const float* __restrict__ bias, const float* __restrict__ res,
    float* __restrict__ Cout, __half* __restrict__ Ohi, __half* __restrict__ Olo,
    int M, int N, int K, int relu)
{
    extern __shared__ char sm[];
    const uint32_t sbase = smem_u32(sm);
    const int tid = threadIdx.x;
    const int lane = tid & 31, wid = tid >> 5;
    const int wm = wid >> 1, wn = wid & 1;          // 2 x 2 warps
    const int g = lane >> 2, tig = lane & 3;
    const int bm = blockIdx.y << 7, bn = blockIdx.x << 7;
    const bool twopass = (Alo != nullptr);

    const uint32_t aoff = (uint32_t)((wm * 64 + (lane & 15)) * 80 + (lane >> 4) * 16);
    const uint32_t boff = (uint32_t)((wn * 64 + (lane & 7) + ((lane >> 4) << 3)) * 80 + ((lane >> 3) & 1) * 16);

    float acc[4][8][4];
    #pragma unroll
    for (int a = 0; a < 4; a++)
        #pragma unroll
        for (int b = 0; b < 8; b++)
            #pragma unroll
            for (int c = 0; c < 4; c++) acc[a][b][c] = 0.f;

    const int nIter = K >> 5;

    auto stage = [&](int it) {
        const uint32_t s0 = sbase + (uint32_t)(it % 3) * GSTAGE;
        const int k0 = it << 5;
        #pragma unroll
        for (int j = 0; j < 4; j++) {
            int c = tid + j * 128;          // 0..511 chunk id
            int row = c >> 2, q = c & 3;
            uint32_t d = (uint32_t)(row * 80 + q * 16);
            size_t ga = (size_t)(bm + row) * K + k0 + q * 8;
            size_t gb = (size_t)(bn + row) * K + k0 + q * 8;
            CP16(s0 + d, Ahi + ga);
            if (twopass) CP16(s0 + 10240 + d, Alo + ga);
            CP16(s0 + 20480 + d, Bw + gb);
        }
    };

    stage(0); CP_COMMIT();
    if (nIter > 1) { stage(1); CP_COMMIT(); }

    for (int i = 0; i < nIter; i++) {
        if (i + 1 < nIter) { CP_WAIT(1); } else { CP_WAIT(0); }
        __syncthreads();
        if (i + 2 < nIter) { stage(i + 2); CP_COMMIT(); }

        const uint32_t s0 = sbase + (uint32_t)(i % 3) * GSTAGE;
        #pragma unroll
        for (int ks = 0; ks < 2; ks++) {
            const uint32_t kofs = (uint32_t)(ks * 32);
            uint32_t ah[4][4], al[4][4], bh[8][2];
            #pragma unroll
            for (int mf = 0; mf < 4; mf++) {
                uint32_t ad = s0 + aoff + (uint32_t)(mf * 16 * 80) + kofs;
                ldm_x4(ah[mf], ad);
                if (twopass) ldm_x4(al[mf], ad + 10240);
            }
            #pragma unroll
            for (int p = 0; p < 4; p++) {
                uint32_t bd = s0 + 20480 + boff + (uint32_t)(p * 16 * 80) + kofs;
                uint32_t r[4];
                ldm_x4(r, bd);
                bh[2 * p][0] = r[0]; bh[2 * p][1] = r[1];
                bh[2 * p + 1][0] = r[2]; bh[2 * p + 1][1] = r[3];
            }
            #pragma unroll
            for (int mf = 0; mf < 4; mf++)
                #pragma unroll
                for (int nf = 0; nf < 8; nf++)
                    mma_f16(acc[mf][nf], ah[mf], bh[nf]);
            if (twopass) {
                #pragma unroll
                for (int mf = 0; mf < 4; mf++)
                    #pragma unroll
                    for (int nf = 0; nf < 8; nf++)
                        mma_f16(acc[mf][nf], al[mf], bh[nf]);
            }
        }
    }

    #pragma unroll
    for (int nf = 0; nf < 8; nf++) {
        int col = bn + wn * 64 + nf * 8 + 2 * tig;
        float2 bz = make_float2(0.f, 0.f);
        if (bias) bz = *(const float2*)(bias + col);
        #pragma unroll
        for (int mf = 0; mf < 4; mf++) {
            int row0 = bm + wm * 64 + mf * 16 + g;
            int row1 = row0 + 8;
            float c0 = acc[mf][nf][0] + bz.x;
            float c1 = acc[mf][nf][1] + bz.y;
            float c2 = acc[mf][nf][2] + bz.x;
            float c3 = acc[mf][nf][3] + bz.y;
            if (res) {
                float2 r0 = *(const float2*)(res + (size_t)row0 * N + col);
                float2 r1 = *(const float2*)(res + (size_t)row1 * N + col);
                c0 += r0.x; c1 += r0.y; c2 += r1.x; c3 += r1.y;
            }
            if (relu) {
                c0 = fmaxf(c0, 0.f); c1 = fmaxf(c1, 0.f);
                c2 = fmaxf(c2, 0.f); c3 = fmaxf(c3, 0.f);
            }
            if (Cout) {
                *(float2*)(Cout + (size_t)row0 * N + col) = make_float2(c0, c1);
                *(float2*)(Cout + (size_t)row1 * N + col) = make_float2(c2, c3);
            }
            if (Ohi) {
                if (Olo) {
                    __half h0, l0, h1, l1, h2, l2, h3, l3;
                    split_f16(c0, h0, l0); split_f16(c1, h1, l1);
                    split_f16(c2, h2, l2); split_f16(c3, h3, l3);
                    *(__half2*)(Ohi + (size_t)row0 * N + col) = __halves2half2(h0, h1);
                    *(__half2*)(Olo + (size_t)row0 * N + col) = __halves2half2(l0, l1);
                    *(__half2*)(Ohi + (size_t)row1 * N + col) = __halves2half2(h2, h3);
                    *(__half2*)(Olo + (size_t)row1 * N + col) = __halves2half2(l2, l3);
                } else {
                    *(uint32_t*)(Ohi + (size_t)row0 * N + col) = packh2(c0, c1);
                    *(uint32_t*)(Ohi + (size_t)row1 * N + col) = packh2(c2, c3);
                }
            }
        }
    }
}

// ---------------- embedding ----------------
__global__ void __launch_bounds__(256) embed_kernel(
    const int* __restrict__ idx, const float* __restrict__ tok,
    const float* __restrict__ pos, float* __restrict__ x)
{
    int row = blockIdx.x;
    int t = row & (T_ - 1);
    int token = idx[row];
    int c = threadIdx.x * 4;
    float4 a = *(const float4*)(tok + (size_t)token * C_ + c);
    float4 p = *(const float4*)(pos + (size_t)t * C_ + c);
    *(float4*)(x + (size_t)row * C_ + c) = make_float4(a.x + p.x, a.y + p.y, a.z + p.z, a.w + p.w);
}

// ---------------- layernorm -> fp16 ----------------
__global__ void __launch_bounds__(256) ln_kernel(
    const float* __restrict__ x, const float* __restrict__ g,
    const float* __restrict__ b, __half* __restrict__ y)
{
    __shared__ float red[256];
    int row = blockIdx.x;
    int t = threadIdx.x;
    const float* xr = x + (size_t)row * C_;
    float4 v = *(const float4*)(xr + t * 4);
    red[t] = v.x + v.y + v.z + v.w;
    __syncthreads();
    for (int o = 128; o > 0; o >>= 1) { if (t < o) red[t] += red[t + o]; __syncthreads(); }
    float mean = red[0] * (1.f / C_);
    __syncthreads();
    float dx = v.x - mean, dy = v.y - mean, dz = v.z - mean, dw = v.w - mean;
    red[t] = dx * dx + dy * dy + dz * dz + dw * dw;
    __syncthreads();
    for (int o = 128; o > 0; o >>= 1) { if (t < o) red[t] += red[t + o]; __syncthreads(); }
    float inv = rsqrtf(red[0] * (1.f / C_) + 1e-5f);
    float4 gv = *(const float4*)(g + t * 4);
    float4 bv = *(const float4*)(b + t * 4);
    float o0 = dx * inv * gv.x + bv.x;
    float o1 = dy * inv * gv.y + bv.y;
    float o2 = dz * inv * gv.z + bv.z;
    float o3 = dw * inv * gv.w + bv.w;
    size_t off = (size_t)row * C_ + t * 4;
    *(uint32_t*)(y + off)     = packh2(o0, o1);
    *(uint32_t*)(y + off + 2) = packh2(o2, o3);
}

// ---------------- fused flash attention (q,k,v all exact fp16 -> 1-pass MMAs) ----------------
#define FSTAGE 18432   // K 9216 + V 9216
#define FSMEM  (2 * FSTAGE + 9216)  // + Qh
__global__ void __launch_bounds__(128) flash_attn_kernel(
    const __half* __restrict__ qkv,
    __half* __restrict__ atthi, __half* __restrict__ attlo)
{
    extern __shared__ char fsm[];
    const uint32_t sbase = smem_u32(fsm);
    const uint32_t sQ = sbase + 2 * FSTAGE;
    const int qt = blockIdx.x << 6;
    const int bh = blockIdx.y;
    const int b = bh >> 4, h = bh & 15;
    const int tid = threadIdx.x, lane = tid & 31, wid = tid >> 5;
    const int RS = 3 * C_;
    const int g = lane >> 2, tig = lane & 3;
    const int nk = (qt >> 6) + 1;

    #pragma unroll
    for (int j = 0; j < 4; j++) {
        int c = tid + j * 128;
        int row = c >> 3, q8 = c & 7;
        uint32_t d = (uint32_t)(row * 144 + q8 * 16);
        size_t gq = (size_t)(b * T_ + qt + row) * RS + h * HS_ + q8 * 8;
        CP16(sQ + d, qkv + gq);
    }

    auto stage = [&](int it) {
        const uint32_t s0 = sbase + (uint32_t)(it & 1) * FSTAGE;
        const int kt = it << 6;
        #pragma unroll
        for (int j = 0; j < 4; j++) {
            int c = tid + j * 128;
            int row = c >> 3, q8 = c & 7;
            uint32_t d = (uint32_t)(row * 144 + q8 * 16);
            size_t gk = (size_t)(b * T_ + kt + row) * RS + C_ + h * HS_ + q8 * 8;
            size_t gv = (size_t)(b * T_ + kt + row) * RS + 2 * C_ + h * HS_ + q8 * 8;
            CP16(s0 + d, qkv + gk);
            CP16(s0 + 9216 + d, qkv + gv);
        }
    };

    stage(0); CP_COMMIT();

    const uint32_t aoff = (uint32_t)((wid * 16 + (lane & 15)) * 144 + (lane >> 4) * 16);
    const uint32_t koff = (uint32_t)(((lane & 7) + ((lane >> 4) << 3)) * 144 + ((lane >> 3) & 1) * 16);
    const uint32_t voff = (uint32_t)((lane & 15) * 144 + (lane >> 4) * 16);

    float m0 = -INFINITY, m1 = -INFINITY, l0 = 0.f, l1 = 0.f;
    float accO[8][4];
    #pragma unroll
    for (int n = 0; n < 8; n++)
        #pragma unroll
        for (int c = 0; c < 4; c++) accO[n][c] = 0.f;

    uint32_t qhf[4][4];
    bool qloaded = false;

    for (int i = 0; i < nk; i++) {
        if (i + 1 < nk) { stage(i + 1); CP_COMMIT(); CP_WAIT(1); } else { CP_WAIT(0); }
        __syncthreads();
        if (!qloaded) {
            #pragma unroll
            for (int kc = 0; kc < 4; kc++)
                ldm_x4(qhf[kc], sQ + aoff + kc * 32);
            qloaded = true;
        }
        const uint32_t s0 = sbase + (uint32_t)(i & 1) * FSTAGE;

        float acc[8][4];
        #pragma unroll
        for (int n = 0; n < 8; n++)
            #pragma unroll
            for (int c = 0; c < 4; c++) acc[n][c] = 0.f;
        #pragma unroll
        for (int kc = 0; kc < 4; kc++) {
            uint32_t bb[8][2];
            #pragma unroll
            for (int p = 0; p < 4; p++) {
                uint32_t r[4];
                ldm_x4(r, s0 + koff + (uint32_t)(p * 16 * 144) + kc * 32);
                bb[2 * p][0] = r[0]; bb[2 * p][1] = r[1];
                bb[2 * p + 1][0] = r[2]; bb[2 * p + 1][1] = r[3];
            }
            #pragma unroll
            for (int nf = 0; nf < 8; nf++) mma_f16(acc[nf], qhf[kc], bb[nf]);
        }

        const bool diag = (i == nk - 1);
        const int lr0 = wid * 16 + g, lr1 = lr0 + 8;
        #pragma unroll
        for (int nf = 0; nf < 8; nf++) {
            int c0 = nf * 8 + 2 * tig;
            acc[nf][0] = (diag && (c0     > lr0)) ? -INFINITY : acc[nf][0] * 0.125f;
            acc[nf][1] = (diag && (c0 + 1 > lr0)) ? -INFINITY : acc[nf][1] * 0.125f;
            acc[nf][2] = (diag && (c0     > lr1)) ? -INFINITY : acc[nf][2] * 0.125f;
            acc[nf][3] = (diag && (c0 + 1 > lr1)) ? -INFINITY : acc[nf][3] * 0.125f;
        }

        float mt0 = -INFINITY, mt1 = -INFINITY;
        #pragma unroll
        for (int nf = 0; nf < 8; nf++) {
            mt0 = fmaxf(mt0, fmaxf(acc[nf][0], acc[nf][1]));
            mt1 = fmaxf(mt1, fmaxf(acc[nf][2], acc[nf][3]));
        }
        mt0 = fmaxf(mt0, __shfl_xor_sync(0xffffffff, mt0, 1));
        mt0 = fmaxf(mt0, __shfl_xor_sync(0xffffffff, mt0, 2));
        mt1 = fmaxf(mt1, __shfl_xor_sync(0xffffffff, mt1, 1));
        mt1 = fmaxf(mt1, __shfl_xor_sync(0xffffffff, mt1, 2));
        float mn0 = fmaxf(m0, mt0), mn1 = fmaxf(m1, mt1);
        float al0 = __expf(m0 - mn0), al1 = __expf(m1 - mn1);
        float sum0 = 0.f, sum1 = 0.f;
        #pragma unroll
        for (int nf = 0; nf < 8; nf++) {
            acc[nf][0] = __expf(acc[nf][0] - mn0);
            acc[nf][1] = __expf(acc[nf][1] - mn0);
            acc[nf][2] = __expf(acc[nf][2] - mn1);
            acc[nf][3] = __expf(acc[nf][3] - mn1);
            sum0 += acc[nf][0] + acc[nf][1];
            sum1 += acc[nf][2] + acc[nf][3];
        }
        sum0 += __shfl_xor_sync(0xffffffff, sum0, 1);
        sum0 += __shfl_xor_sync(0xffffffff, sum0, 2);
        sum1 += __shfl_xor_sync(0xffffffff, sum1, 1);
        sum1 += __shfl_xor_sync(0xffffffff, sum1, 2);
        l0 = l0 * al0 + sum0;
        l1 = l1 * al1 + sum1;
        m0 = mn0; m1 = mn1;
        #pragma unroll
        for (int nf = 0; nf < 8; nf++) {
            accO[nf][0] *= al0; accO[nf][1] *= al0;
            accO[nf][2] *= al1; accO[nf][3] *= al1;
        }

        #pragma unroll
        for (int kc = 0; kc < 4; kc++) {
            uint32_t aw[4];
            aw[0] = packh2(acc[2 * kc][0],     acc[2 * kc][1]);
            aw[1] = packh2(acc[2 * kc][2],     acc[2 * kc][3]);
            aw[2] = packh2(acc[2 * kc + 1][0], acc[2 * kc + 1][1]);
            aw[3] = packh2(acc[2 * kc + 1][2], acc[2 * kc + 1][3]);
            #pragma unroll
            for (int db = 0; db < 4; db++) {
                uint32_t rh[4];
                uint32_t vaddr = s0 + 9216 + voff + (uint32_t)(kc * 16 * 144) + db * 32;
                ldm_x4_t(rh, vaddr);
                mma_f16(accO[2 * db],     aw, rh);
                mma_f16(accO[2 * db + 1], aw, rh + 2);
            }
        }
        __syncthreads();
    }

    float il0 = 1.f / l0, il1 = 1.f / l1;
    #pragma unroll
    for (int nf = 0; nf < 8; nf++) {
        int col = h * HS_ + nf * 8 + 2 * tig;
        int row0 = qt + wid * 16 + g;
        float c0 = accO[nf][0] * il0, c1 = accO[nf][1] * il0;
        float c2 = accO[nf][2] * il1, c3 = accO[nf][3] * il1;
        __half h0, lo0, h1, lo1, h2, lo2, h3, lo3;
        split_f16(c0, h0, lo0); split_f16(c1, h1, lo1);
        split_f16(c2, h2, lo2); split_f16(c3, h3, lo3);
        size_t off0 = (size_t)(b * T_ + row0) * C_ + col;
        size_t off1 = (size_t)(b * T_ + row0 + 8) * C_ + col;
        *(__half2*)(atthi + off0) = __halves2half2(h0, h1);
        *(__half2*)(attlo + off0) = __halves2half2(lo0, lo1);
        *(__half2*)(atthi + off1) = __halves2half2(h2, h3);
        *(__half2*)(attlo + off1) = __halves2half2(lo2, lo3);
    }
}

// ---------------- loss ----------------
__global__ void zero_acc_kernel(float* acc) { *acc = 0.f; }

__global__ void __launch_bounds__(256) loss_kernel(
    const float* __restrict__ logits, const int* __restrict__ targets, float* __restrict__ acc)
{
    __shared__ float red[256];
    int row = blockIdx.x;
    const float* lr = logits + (size_t)row * V_;
    int t = threadIdx.x;
    float mx = -INFINITY;
    for (int c = t; c < V_; c += 256) mx = fmaxf(mx, lr[c]);
    red[t] = mx; __syncthreads();
    for (int o = 128; o > 0; o >>= 1) { if (t < o) red[t] = fmaxf(red[t], red[t + o]); __syncthreads(); }
    float Mx = red[0]; __syncthreads();
    float s = 0.f;
    for (int c = t; c < V_; c += 256) s += __expf(lr[c] - Mx);
    red[t] = s; __syncthreads();
    for (int o = 128; o > 0; o >>= 1) { if (t < o) red[t] += red[t + o]; __syncthreads(); }
    if (t == 0) {
        float lse = logf(red[0]) + Mx;
        int tgt = targets[row];
        atomicAdd(acc, (lse - lr[tgt]) * (1.f / M_));
    }
}

__global__ void write_loss_kernel(const float* acc, float* out) { out[0] = *acc; }

// ---------------- launch ----------------
extern "C" void kernel_launch(void* const* d_in, const int* in_sizes, int n_in,
                              void* d_out, int out_size)
{
    const int*   idx   = (const int*)d_in[0];
    const int*   tgt   = (const int*)d_in[1];
    const float* tok   = (const float*)d_in[2];
    const float* pos   = (const float*)d_in[3];
    const float* ln1g  = (const float*)d_in[4];
    const float* ln1b  = (const float*)d_in[5];
    const float* Wq    = (const float*)d_in[6];
    const float* Wk    = (const float*)d_in[7];
    const float* Wv    = (const float*)d_in[8];
    const float* Wo    = (const float*)d_in[9];
    const float* bo    = (const float*)d_in[10];
    const float* ln2g  = (const float*)d_in[11];
    const float* ln2b  = (const float*)d_in[12];
    const float* W1    = (const float*)d_in[13];
    const float* b1    = (const float*)d_in[14];
    const float* W2    = (const float*)d_in[15];
    const float* b2    = (const float*)d_in[16];
    const float* lnfg  = (const float*)d_in[17];
    const float* lnfb  = (const float*)d_in[18];
    const float* Wlm   = (const float*)d_in[19];
    const float* blm   = (const float*)d_in[20];

    float *xb, *accp;
    __half *qk, *hb, *ah, *al, *mb, *wt;
    cudaGetSymbolAddress((void**)&xb, g_x);
    cudaGetSymbolAddress((void**)&accp, g_loss_acc);
    cudaGetSymbolAddress((void**)&qk, g_qkv);
    cudaGetSymbolAddress((void**)&hb, g_h);
    cudaGetSymbolAddress((void**)&ah, g_att_hi);
    cudaGetSymbolAddress((void**)&al, g_att_lo);
    cudaGetSymbolAddress((void**)&mb, g_mlp);
    cudaGetSymbolAddress((void**)&wt, g_wT);

    cudaFuncSetAttribute(gemm_mma_kernel, cudaFuncAttributeMaxDynamicSharedMemorySize, GSMEM);
    cudaFuncSetAttribute(flash_attn_kernel, cudaFuncAttributeMaxDynamicSharedMemorySize, FSMEM);

    embed_kernel<<<M_, 256>>>(idx, tok, pos, xb);

    dim3 gC(C_ / 128, M_ / 128);
    dim3 gQKV(3 * C_ / 128, M_ / 128);
    dim3 gF(4 * C_ / 128, M_ / 128);
    dim3 gFlash(T_ / 64, B_ * H_);
    dim3 cv3(C_ / 32, C_ / 32, 3);
    dim3 cvC(C_ / 32, C_ / 32);
    dim3 cv1(4 * C_ / 32, C_ / 32);
    dim3 cv2(C_ / 32, 4 * C_ / 32);
    dim3 cvLM(V_ / 32, C_ / 32);

    for (int l = 0; l < L_; l++) {
        ln_kernel<<<M_, 256>>>(xb, ln1g + (size_t)l * C_, ln1b + (size_t)l * C_, hb);

        convw3_kernel<<<cv3, 256>>>(Wq + (size_t)l * C_ * C_, Wk + (size_t)l * C_ * C_,
                                    Wv + (size_t)l * C_ * C_, wt);
        gemm_mma_kernel<<<gQKV, 128, GSMEM>>>(hb, nullptr, wt, nullptr, nullptr, nullptr, qk, nullptr, M_, 3 * C_, C_, 0);

        flash_attn_kernel<<<gFlash, 128, FSMEM>>>(qk, ah, al);

        convw_kernel<<<cvC, 256>>>(Wo + (size_t)l * C_ * C_, wt, C_, C_);
        gemm_mma_kernel<<<gC, 128, GSMEM>>>(ah, al, wt, bo + (size_t)l * C_, xb, xb, nullptr, nullptr, M_, C_, C_, 0);

        ln_kernel<<<M_, 256>>>(xb, ln2g + (size_t)l * C_, ln2b + (size_t)l * C_, hb);

        convw_kernel<<<cv1, 256>>>(W1 + (size_t)l * C_ * 4 * C_, wt, C_, 4 * C_);
        gemm_mma_kernel<<<gF, 128, GSMEM>>>(hb, nullptr, wt, b1 + (size_t)l * 4 * C_, nullptr, nullptr, mb, nullptr, M_, 4 * C_, C_, 1);
        convw_kernel<<<cv2, 256>>>(W2 + (size_t)l * 4 * C_ * C_, wt, 4 * C_, C_);
        gemm_mma_kernel<<<gC, 128, GSMEM>>>(mb, nullptr, wt, b2 + (size_t)l * C_, xb, xb, nullptr, nullptr, M_, C_, 4 * C_, 0);
    }

    ln_kernel<<<M_, 256>>>(xb, lnfg, lnfb, hb);

    float* out = (float*)d_out;
    convw_kernel<<<cvLM, 256>>>(Wlm, wt, C_, V_);
    dim3 gLM(V_ / 128, M_ / 128);
    gemm_mma_kernel<<<gLM, 128, GSMEM>>>(hb, nullptr, wt, blm, nullptr, out, nullptr, nullptr, M_, V_, C_, 0);

    if ((size_t)out_size > NLOGITS) {
        zero_acc_kernel<<<1, 1>>>(accp);
        loss_kernel<<<M_, 256>>>(out, tgt, accp);
        write_loss_kernel<<<1, 1>>>(accp, out + NLOGITS);
    }
}

// round 13
// speedup vs baseline: 3.5874x; 1.1332x over previous
#include <cuda_runtime.h>
#include <cuda_fp16.h>
#include <math.h>
#include <stdint.h>

#define B_ 4
#define T_ 1024
#define C_ 1024
#define H_ 16
#define HS_ 64
#define L_ 12
#define V_ 50304
#define M_ 4096  // B*T

static const size_t NLOGITS = (size_t)M_ * V_;

// ---------------- scratch (device globals; no allocs allowed) ----------------
__device__ float g_x[(size_t)M_ * C_];
__device__ float g_loss_acc;

__device__ __half g_qkv[(size_t)M_ * 3 * C_];     // fp16 q,k,v
__device__ __half g_h[(size_t)M_ * C_];           // LN out (fp16)
__device__ __half g_att[(size_t)M_ * C_];         // attention out (fp16)
__device__ __half g_mlp[(size_t)M_ * 4 * C_];     // ReLU out (fp16)
__device__ __half g_wT[(size_t)V_ * C_];

// ---------------- helpers ----------------
__device__ __forceinline__ uint32_t smem_u32(const void* p) {
    uint32_t a;
    asm("{ .reg .u64 t; cvta.to.shared.u64 t, %1; cvt.u32.u64 %0, t; }" : "=r"(a) : "l"(p));
    return a;
}
#define CP16(dst, src) asm volatile("cp.async.cg.shared.global [%0], [%1], 16;" :: "r"(dst), "l"(src) : "memory")
#define CP_COMMIT() asm volatile("cp.async.commit_group;" ::: "memory")
#define CP_WAIT(n)  asm volatile("cp.async.wait_group %0;" :: "n"(n) : "memory")

__device__ __forceinline__ uint32_t packh2(float x, float y) {
    __half2 t = __halves2half2(__float2half_rn(x), __float2half_rn(y));
    return *(uint32_t*)&t;
}

__device__ __forceinline__ void mma_f16(float* c, const uint32_t* a, const uint32_t* b) {
    asm volatile(
        "mma.sync.aligned.m16n8k16.row.col.f32.f16.f16.f32 "
        "{%0,%1,%2,%3}, {%4,%5,%6,%7}, {%8,%9}, {%0,%1,%2,%3};"
        : "+f"(c[0]), "+f"(c[1]), "+f"(c[2]), "+f"(c[3])
        : "r"(a[0]), "r"(a[1]), "r"(a[2]), "r"(a[3]), "r"(b[0]), "r"(b[1]));
}

__device__ __forceinline__ void ldm_x4(uint32_t* r, uint32_t addr) {
    asm volatile("ldmatrix.sync.aligned.m8n8.x4.shared.b16 {%0,%1,%2,%3}, [%4];"
        : "=r"(r[0]), "=r"(r[1]), "=r"(r[2]), "=r"(r[3]) : "r"(addr));
}
__device__ __forceinline__ void ldm_x4_t(uint32_t* r, uint32_t addr) {
    asm volatile("ldmatrix.sync.aligned.m8n8.x4.trans.shared.b16 {%0,%1,%2,%3}, [%4];"
        : "=r"(r[0]), "=r"(r[1]), "=r"(r[2]), "=r"(r[3]) : "r"(addr));
}

// ---------------- weight convert + transpose: W[K][N] -> wT[N][K] fp16 ----------------
__global__ void __launch_bounds__(256) convw_kernel(
    const float* __restrict__ W, __half* __restrict__ wT, int K, int N)
{
    __shared__ float tile[32][33];
    int nt = blockIdx.x * 32, kt = blockIdx.y * 32;
    int tx = threadIdx.x & 31, ty = threadIdx.x >> 5;
    #pragma unroll
    for (int j = 0; j < 4; j++) {
        int kk = ty + j * 8;
        tile[kk][tx] = W[(size_t)(kt + kk) * N + nt + tx];
    }
    __syncthreads();
    #pragma unroll
    for (int j = 0; j < 4; j++) {
        int nn = ty + j * 8;
        wT[(size_t)(nt + nn) * K + kt + tx] = __float2half_rn(tile[tx][nn]);
    }
}

// fused QKV weight convert: z selects Wq/Wk/Wv (all C x C)
__global__ void __launch_bounds__(256) convw3_kernel(
    const float* __restrict__ Wq, const float* __restrict__ Wk,
    const float* __restrict__ Wv, __half* __restrict__ wT)
{
    __shared__ float tile[32][33];
    int z = blockIdx.z;
    const float* W = (z == 0) ? Wq : (z == 1) ? Wk : Wv;
    __half* out = wT + (size_t)z * C_ * C_;
    int nt = blockIdx.x * 32, kt = blockIdx.y * 32;
    int tx = threadIdx.x & 31, ty = threadIdx.x >> 5;
    #pragma unroll
    for (int j = 0; j < 4; j++) {
        int kk = ty + j * 8;
        tile[kk][tx] = W[(size_t)(kt + kk) * C_ + nt + tx];
    }
    __syncthreads();
    #pragma unroll
    for (int j = 0; j < 4; j++) {
        int nn = ty + j * 8;
        out[(size_t)(nt + nn) * C_ + kt + tx] = __float2half_rn(tile[tx][nn]);
    }
}

// ---------------- fp16 1-pass GEMM via mma.sync + ldmatrix ----------------
// 128 threads, 4 warps (2x2), warp tile 64x64, CTA tile 128x128, BK=32,
// 4-stage cp.async, 2 CTAs/SM.
#define GSTAGE 20480            // A 10240 + B 10240
#define GNSTAGE 4
#define GSMEM  (GNSTAGE * GSTAGE)   // 81920
__global__ void __launch_bounds__(128, 2) gemm_mma_kernel(
    const __half* __restrict__ Aw, const __half* __restrict__ Bw,
    const float* __restrict__ bias, const float* __restrict__ res,
    float* __restrict__ Cout, __half* __restrict__ Oh,
    int M, int N, int K, int relu)
{
    extern __shared__ char sm[];
    const uint32_t sbase = smem_u32(sm);
    const int tid = threadIdx.x;
    const int lane = tid & 31, wid = tid >> 5;
    const int wm = wid >> 1, wn = wid & 1;          // 2 x 2 warps
    const int g = lane >> 2, tig = lane & 3;
    const int bm = blockIdx.y << 7, bn = blockIdx.x << 7;

    const uint32_t aoff = (uint32_t)((wm * 64 + (lane & 15)) * 80 + (lane >> 4) * 16);
    const uint32_t boff = (uint32_t)((wn * 64 + (lane & 7) + ((lane >> 4) << 3)) * 80 + ((lane >> 3) & 1) * 16);

    float acc[4][8][4];
    #pragma unroll
    for (int a = 0; a < 4; a++)
        #pragma unroll
        for (int b = 0; b < 8; b++)
            #pragma unroll
            for (int c = 0; c < 4; c++) acc[a][b][c] = 0.f;

    const int nIter = K >> 5;

    auto stage = [&](int it) {
        const uint32_t s0 = sbase + (uint32_t)(it % GNSTAGE) * GSTAGE;
        const int k0 = it << 5;
        #pragma unroll
        for (int j = 0; j < 4; j++) {
            int c = tid + j * 128;          // 0..511 chunk id
            int row = c >> 2, q = c & 3;
            uint32_t d = (uint32_t)(row * 80 + q * 16);
            size_t ga = (size_t)(bm + row) * K + k0 + q * 8;
            size_t gb = (size_t)(bn + row) * K + k0 + q * 8;
            CP16(s0 + d, Aw + ga);
            CP16(s0 + 10240 + d, Bw + gb);
        }
    };

    stage(0); CP_COMMIT();
    if (nIter > 1) { stage(1); CP_COMMIT(); }
    if (nIter > 2) { stage(2); CP_COMMIT(); }

    for (int i = 0; i < nIter; i++) {
        int rem = nIter - 1 - i;
        if (rem >= 2) { CP_WAIT(2); } else if (rem == 1) { CP_WAIT(1); } else { CP_WAIT(0); }
        __syncthreads();
        if (i + 3 < nIter) { stage(i + 3); CP_COMMIT(); }

        const uint32_t s0 = sbase + (uint32_t)(i % GNSTAGE) * GSTAGE;
        #pragma unroll
        for (int ks = 0; ks < 2; ks++) {
            const uint32_t kofs = (uint32_t)(ks * 32);
            uint32_t ah[4][4], bh[8][2];
            #pragma unroll
            for (int mf = 0; mf < 4; mf++)
                ldm_x4(ah[mf], s0 + aoff + (uint32_t)(mf * 16 * 80) + kofs);
            #pragma unroll
            for (int p = 0; p < 4; p++) {
                uint32_t r[4];
                ldm_x4(r, s0 + 10240 + boff + (uint32_t)(p * 16 * 80) + kofs);
                bh[2 * p][0] = r[0]; bh[2 * p][1] = r[1];
                bh[2 * p + 1][0] = r[2]; bh[2 * p + 1][1] = r[3];
            }
            #pragma unroll
            for (int mf = 0; mf < 4; mf++)
                #pragma unroll
                for (int nf = 0; nf < 8; nf++)
                    mma_f16(acc[mf][nf], ah[mf], bh[nf]);
        }
    }

    #pragma unroll
    for (int nf = 0; nf < 8; nf++) {
        int col = bn + wn * 64 + nf * 8 + 2 * tig;
        float2 bz = make_float2(0.f, 0.f);
        if (bias) bz = *(const float2*)(bias + col);
        #pragma unroll
        for (int mf = 0; mf < 4; mf++) {
            int row0 = bm + wm * 64 + mf * 16 + g;
            int row1 = row0 + 8;
            float c0 = acc[mf][nf][0] + bz.x;
            float c1 = acc[mf][nf][1] + bz.y;
            float c2 = acc[mf][nf][2] + bz.x;
            float c3 = acc[mf][nf][3] + bz.y;
            if (res) {
                float2 r0 = *(const float2*)(res + (size_t)row0 * N + col);
                float2 r1 = *(const float2*)(res + (size_t)row1 * N + col);
                c0 += r0.x; c1 += r0.y; c2 += r1.x; c3 += r1.y;
            }
            if (relu) {
                c0 = fmaxf(c0, 0.f); c1 = fmaxf(c1, 0.f);
                c2 = fmaxf(c2, 0.f); c3 = fmaxf(c3, 0.f);
            }
            if (Cout) {
                *(float2*)(Cout + (size_t)row0 * N + col) = make_float2(c0, c1);
                *(float2*)(Cout + (size_t)row1 * N + col) = make_float2(c2, c3);
            }
            if (Oh) {
                *(uint32_t*)(Oh + (size_t)row0 * N + col) = packh2(c0, c1);
                *(uint32_t*)(Oh + (size_t)row1 * N + col) = packh2(c2, c3);
            }
        }
    }
}

// ---------------- embedding ----------------
__global__ void __launch_bounds__(256) embed_kernel(
    const int* __restrict__ idx, const float* __restrict__ tok,
    const float* __restrict__ pos, float* __restrict__ x)
{
    int row = blockIdx.x;
    int t = row & (T_ - 1);
    int token = idx[row];
    int c = threadIdx.x * 4;
    float4 a = *(const float4*)(tok + (size_t)token * C_ + c);
    float4 p = *(const float4*)(pos + (size_t)t * C_ + c);
    *(float4*)(x + (size_t)row * C_ + c) = make_float4(a.x + p.x, a.y + p.y, a.z + p.z, a.w + p.w);
}

// ---------------- layernorm -> fp16 ----------------
__global__ void __launch_bounds__(256) ln_kernel(
    const float* __restrict__ x, const float* __restrict__ g,
    const float* __restrict__ b, __half* __restrict__ y)
{
    __shared__ float red[256];
    int row = blockIdx.x;
    int t = threadIdx.x;
    const float* xr = x + (size_t)row * C_;
    float4 v = *(const float4*)(xr + t * 4);
    red[t] = v.x + v.y + v.z + v.w;
    __syncthreads();
    for (int o = 128; o > 0; o >>= 1) { if (t < o) red[t] += red[t + o]; __syncthreads(); }
    float mean = red[0] * (1.f / C_);
    __syncthreads();
    float dx = v.x - mean, dy = v.y - mean, dz = v.z - mean, dw = v.w - mean;
    red[t] = dx * dx + dy * dy + dz * dz + dw * dw;
    __syncthreads();
    for (int o = 128; o > 0; o >>= 1) { if (t < o) red[t] += red[t + o]; __syncthreads(); }
    float inv = rsqrtf(red[0] * (1.f / C_) + 1e-5f);
    float4 gv = *(const float4*)(g + t * 4);
    float4 bv = *(const float4*)(b + t * 4);
    float o0 = dx * inv * gv.x + bv.x;
    float o1 = dy * inv * gv.y + bv.y;
    float o2 = dz * inv * gv.z + bv.z;
    float o3 = dw * inv * gv.w + bv.w;
    size_t off = (size_t)row * C_ + t * 4;
    *(uint32_t*)(y + off)     = packh2(o0, o1);
    *(uint32_t*)(y + off + 2) = packh2(o2, o3);
}

// ---------------- fused flash attention (q,k,v exact fp16, att out fp16) ----------------
#define FSTAGE 18432   // K 9216 + V 9216
#define FSMEM  (2 * FSTAGE + 9216)  // + Qh
__global__ void __launch_bounds__(128) flash_attn_kernel(
    const __half* __restrict__ qkv, __half* __restrict__ att)
{
    extern __shared__ char fsm[];
    const uint32_t sbase = smem_u32(fsm);
    const uint32_t sQ = sbase + 2 * FSTAGE;
    const int qt = blockIdx.x << 6;
    const int bh = blockIdx.y;
    const int b = bh >> 4, h = bh & 15;
    const int tid = threadIdx.x, lane = tid & 31, wid = tid >> 5;
    const int RS = 3 * C_;
    const int g = lane >> 2, tig = lane & 3;
    const int nk = (qt >> 6) + 1;

    #pragma unroll
    for (int j = 0; j < 4; j++) {
        int c = tid + j * 128;
        int row = c >> 3, q8 = c & 7;
        uint32_t d = (uint32_t)(row * 144 + q8 * 16);
        size_t gq = (size_t)(b * T_ + qt + row) * RS + h * HS_ + q8 * 8;
        CP16(sQ + d, qkv + gq);
    }

    auto stage = [&](int it) {
        const uint32_t s0 = sbase + (uint32_t)(it & 1) * FSTAGE;
        const int kt = it << 6;
        #pragma unroll
        for (int j = 0; j < 4; j++) {
            int c = tid + j * 128;
            int row = c >> 3, q8 = c & 7;
            uint32_t d = (uint32_t)(row * 144 + q8 * 16);
            size_t gk = (size_t)(b * T_ + kt + row) * RS + C_ + h * HS_ + q8 * 8;
            size_t gv = (size_t)(b * T_ + kt + row) * RS + 2 * C_ + h * HS_ + q8 * 8;
            CP16(s0 + d, qkv + gk);
            CP16(s0 + 9216 + d, qkv + gv);
        }
    };

    stage(0); CP_COMMIT();

    const uint32_t aoff = (uint32_t)((wid * 16 + (lane & 15)) * 144 + (lane >> 4) * 16);
    const uint32_t koff = (uint32_t)(((lane & 7) + ((lane >> 4) << 3)) * 144 + ((lane >> 3) & 1) * 16);
    const uint32_t voff = (uint32_t)((lane & 15) * 144 + (lane >> 4) * 16);

    float m0 = -INFINITY, m1 = -INFINITY, l0 = 0.f, l1 = 0.f;
    float accO[8][4];
    #pragma unroll
    for (int n = 0; n < 8; n++)
        #pragma unroll
        for (int c = 0; c < 4; c++) accO[n][c] = 0.f;

    uint32_t qhf[4][4];
    bool qloaded = false;

    for (int i = 0; i < nk; i++) {
        if (i + 1 < nk) { stage(i + 1); CP_COMMIT(); CP_WAIT(1); } else { CP_WAIT(0); }
        __syncthreads();
        if (!qloaded) {
            #pragma unroll
            for (int kc = 0; kc < 4; kc++)
                ldm_x4(qhf[kc], sQ + aoff + kc * 32);
            qloaded = true;
        }
        const uint32_t s0 = sbase + (uint32_t)(i & 1) * FSTAGE;

        float acc[8][4];
        #pragma unroll
        for (int n = 0; n < 8; n++)
            #pragma unroll
            for (int c = 0; c < 4; c++) acc[n][c] = 0.f;
        #pragma unroll
        for (int kc = 0; kc < 4; kc++) {
            uint32_t bb[8][2];
            #pragma unroll
            for (int p = 0; p < 4; p++) {
                uint32_t r[4];
                ldm_x4(r, s0 + koff + (uint32_t)(p * 16 * 144) + kc * 32);
                bb[2 * p][0] = r[0]; bb[2 * p][1] = r[1];
                bb[2 * p + 1][0] = r[2]; bb[2 * p + 1][1] = r[3];
            }
            #pragma unroll
            for (int nf = 0; nf < 8; nf++) mma_f16(acc[nf], qhf[kc], bb[nf]);
        }

        const bool diag = (i == nk - 1);
        const int lr0 = wid * 16 + g, lr1 = lr0 + 8;
        #pragma unroll
        for (int nf = 0; nf < 8; nf++) {
            int c0 = nf * 8 + 2 * tig;
            acc[nf][0] = (diag && (c0     > lr0)) ? -INFINITY : acc[nf][0] * 0.125f;
            acc[nf][1] = (diag && (c0 + 1 > lr0)) ? -INFINITY : acc[nf][1] * 0.125f;
            acc[nf][2] = (diag && (c0     > lr1)) ? -INFINITY : acc[nf][2] * 0.125f;
            acc[nf][3] = (diag && (c0 + 1 > lr1)) ? -INFINITY : acc[nf][3] * 0.125f;
        }

        float mt0 = -INFINITY, mt1 = -INFINITY;
        #pragma unroll
        for (int nf = 0; nf < 8; nf++) {
            mt0 = fmaxf(mt0, fmaxf(acc[nf][0], acc[nf][1]));
            mt1 = fmaxf(mt1, fmaxf(acc[nf][2], acc[nf][3]));
        }
        mt0 = fmaxf(mt0, __shfl_xor_sync(0xffffffff, mt0, 1));
        mt0 = fmaxf(mt0, __shfl_xor_sync(0xffffffff, mt0, 2));
        mt1 = fmaxf(mt1, __shfl_xor_sync(0xffffffff, mt1, 1));
        mt1 = fmaxf(mt1, __shfl_xor_sync(0xffffffff, mt1, 2));
        float mn0 = fmaxf(m0, mt0), mn1 = fmaxf(m1, mt1);
        float al0 = __expf(m0 - mn0), al1 = __expf(m1 - mn1);
        float sum0 = 0.f, sum1 = 0.f;
        #pragma unroll
        for (int nf = 0; nf < 8; nf++) {
            acc[nf][0] = __expf(acc[nf][0] - mn0);
            acc[nf][1] = __expf(acc[nf][1] - mn0);
            acc[nf][2] = __expf(acc[nf][2] - mn1);
            acc[nf][3] = __expf(acc[nf][3] - mn1);
            sum0 += acc[nf][0] + acc[nf][1];
            sum1 += acc[nf][2] + acc[nf][3];
        }
        sum0 += __shfl_xor_sync(0xffffffff, sum0, 1);
        sum0 += __shfl_xor_sync(0xffffffff, sum0, 2);
        sum1 += __shfl_xor_sync(0xffffffff, sum1, 1);
        sum1 += __shfl_xor_sync(0xffffffff, sum1, 2);
        l0 = l0 * al0 + sum0;
        l1 = l1 * al1 + sum1;
        m0 = mn0; m1 = mn1;
        #pragma unroll
        for (int nf = 0; nf < 8; nf++) {
            accO[nf][0] *= al0; accO[nf][1] *= al0;
            accO[nf][2] *= al1; accO[nf][3] *= al1;
        }

        #pragma unroll
        for (int kc = 0; kc < 4; kc++) {
            uint32_t aw[4];
            aw[0] = packh2(acc[2 * kc][0],     acc[2 * kc][1]);
            aw[1] = packh2(acc[2 * kc][2],     acc[2 * kc][3]);
            aw[2] = packh2(acc[2 * kc + 1][0], acc[2 * kc + 1][1]);
            aw[3] = packh2(acc[2 * kc + 1][2], acc[2 * kc + 1][3]);
            #pragma unroll
            for (int db = 0; db < 4; db++) {
                uint32_t rh[4];
                uint32_t vaddr = s0 + 9216 + voff + (uint32_t)(kc * 16 * 144) + db * 32;
                ldm_x4_t(rh, vaddr);
                mma_f16(accO[2 * db],     aw, rh);
                mma_f16(accO[2 * db + 1], aw, rh + 2);
            }
        }
        __syncthreads();
    }

    float il0 = 1.f / l0, il1 = 1.f / l1;
    #pragma unroll
    for (int nf = 0; nf < 8; nf++) {
        int col = h * HS_ + nf * 8 + 2 * tig;
        int row0 = qt + wid * 16 + g;
        size_t off0 = (size_t)(b * T_ + row0) * C_ + col;
        size_t off1 = (size_t)(b * T_ + row0 + 8) * C_ + col;
        *(uint32_t*)(att + off0) = packh2(accO[nf][0] * il0, accO[nf][1] * il0);
        *(uint32_t*)(att + off1) = packh2(accO[nf][2] * il1, accO[nf][3] * il1);
    }
}

// ---------------- loss ----------------
__global__ void zero_acc_kernel(float* acc) { *acc = 0.f; }

__global__ void __launch_bounds__(256) loss_kernel(
    const float* __restrict__ logits, const int* __restrict__ targets, float* __restrict__ acc)
{
    __shared__ float red[256];
    int row = blockIdx.x;
    const float* lr = logits + (size_t)row * V_;
    int t = threadIdx.x;
    float mx = -INFINITY;
    for (int c = t; c < V_; c += 256) mx = fmaxf(mx, lr[c]);
    red[t] = mx; __syncthreads();
    for (int o = 128; o > 0; o >>= 1) { if (t < o) red[t] = fmaxf(red[t], red[t + o]); __syncthreads(); }
    float Mx = red[0]; __syncthreads();
    float s = 0.f;
    for (int c = t; c < V_; c += 256) s += __expf(lr[c] - Mx);
    red[t] = s; __syncthreads();
    for (int o = 128; o > 0; o >>= 1) { if (t < o) red[t] += red[t + o]; __syncthreads(); }
    if (t == 0) {
        float lse = logf(red[0]) + Mx;
        int tgt = targets[row];
        atomicAdd(acc, (lse - lr[tgt]) * (1.f / M_));
    }
}

__global__ void write_loss_kernel(const float* acc, float* out) { out[0] = *acc; }

// ---------------- launch ----------------
extern "C" void kernel_launch(void* const* d_in, const int* in_sizes, int n_in,
                              void* d_out, int out_size)
{
    const int*   idx   = (const int*)d_in[0];
    const int*   tgt   = (const int*)d_in[1];
    const float* tok   = (const float*)d_in[2];
    const float* pos   = (const float*)d_in[3];
    const float* ln1g  = (const float*)d_in[4];
    const float* ln1b  = (const float*)d_in[5];
    const float* Wq    = (const float*)d_in[6];
    const float* Wk    = (const float*)d_in[7];
    const float* Wv    = (const float*)d_in[8];
    const float* Wo    = (const float*)d_in[9];
    const float* bo    = (const float*)d_in[10];
    const float* ln2g  = (const float*)d_in[11];
    const float* ln2b  = (const float*)d_in[12];
    const float* W1    = (const float*)d_in[13];
    const float* b1    = (const float*)d_in[14];
    const float* W2    = (const float*)d_in[15];
    const float* b2    = (const float*)d_in[16];
    const float* lnfg  = (const float*)d_in[17];
    const float* lnfb  = (const float*)d_in[18];
    const float* Wlm   = (const float*)d_in[19];
    const float* blm   = (const float*)d_in[20];

    float *xb, *accp;
    __half *qk, *hb, *ab, *mb, *wt;
    cudaGetSymbolAddress((void**)&xb, g_x);
    cudaGetSymbolAddress((void**)&accp, g_loss_acc);
    cudaGetSymbolAddress((void**)&qk, g_qkv);
    cudaGetSymbolAddress((void**)&hb, g_h);
    cudaGetSymbolAddress((void**)&ab, g_att);
    cudaGetSymbolAddress((void**)&mb, g_mlp);
    cudaGetSymbolAddress((void**)&wt, g_wT);

    cudaFuncSetAttribute(gemm_mma_kernel, cudaFuncAttributeMaxDynamicSharedMemorySize, GSMEM);
    cudaFuncSetAttribute(flash_attn_kernel, cudaFuncAttributeMaxDynamicSharedMemorySize, FSMEM);

    embed_kernel<<<M_, 256>>>(idx, tok, pos, xb);

    dim3 gC(C_ / 128, M_ / 128);
    dim3 gQKV(3 * C_ / 128, M_ / 128);
    dim3 gF(4 * C_ / 128, M_ / 128);
    dim3 gFlash(T_ / 64, B_ * H_);
    dim3 cv3(C_ / 32, C_ / 32, 3);
    dim3 cvC(C_ / 32, C_ / 32);
    dim3 cv1(4 * C_ / 32, C_ / 32);
    dim3 cv2(C_ / 32, 4 * C_ / 32);
    dim3 cvLM(V_ / 32, C_ / 32);

    for (int l = 0; l < L_; l++) {
        ln_kernel<<<M_, 256>>>(xb, ln1g + (size_t)l * C_, ln1b + (size_t)l * C_, hb);

        convw3_kernel<<<cv3, 256>>>(Wq + (size_t)l * C_ * C_, Wk + (size_t)l * C_ * C_,
                                    Wv + (size_t)l * C_ * C_, wt);
        gemm_mma_kernel<<<gQKV, 128, GSMEM>>>(hb, wt, nullptr, nullptr, nullptr, qk, M_, 3 * C_, C_, 0);

        flash_attn_kernel<<<gFlash, 128, FSMEM>>>(qk, ab);

        convw_kernel<<<cvC, 256>>>(Wo + (size_t)l * C_ * C_, wt, C_, C_);
        gemm_mma_kernel<<<gC, 128, GSMEM>>>(ab, wt, bo + (size_t)l * C_, xb, xb, nullptr, M_, C_, C_, 0);

        ln_kernel<<<M_, 256>>>(xb, ln2g + (size_t)l * C_, ln2b + (size_t)l * C_, hb);

        convw_kernel<<<cv1, 256>>>(W1 + (size_t)l * C_ * 4 * C_, wt, C_, 4 * C_);
        gemm_mma_kernel<<<gF, 128, GSMEM>>>(hb, wt, b1 + (size_t)l * 4 * C_, nullptr, nullptr, mb, M_, 4 * C_, C_, 1);
        convw_kernel<<<cv2, 256>>>(W2 + (size_t)l * 4 * C_ * C_, wt, 4 * C_, C_);
        gemm_mma_kernel<<<gC, 128, GSMEM>>>(mb, wt, b2 + (size_t)l * C_, xb, xb, nullptr, M_, C_, 4 * C_, 0);
    }

    ln_kernel<<<M_, 256>>>(xb, lnfg, lnfb, hb);

    float* out = (float*)d_out;
    convw_kernel<<<cvLM, 256>>>(Wlm, wt, C_, V_);
    dim3 gLM(V_ / 128, M_ / 128);
    gemm_mma_kernel<<<gLM, 128, GSMEM>>>(hb, wt, blm, nullptr, out, nullptr, M_, V_, C_, 0);

    if ((size_t)out_size > NLOGITS) {
        zero_acc_kernel<<<1, 1>>>(accp);
        loss_kernel<<<M_, 256>>>(out, tgt, accp);
        write_loss_kernel<<<1, 1>>>(accp, out + NLOGITS);
    }
}